// round 1
// baseline (speedup 1.0000x reference)
#include <cuda_runtime.h>
#include <math.h>

#define BB 4
#define TT 4096
#define DD 1024
#define M_TOTAL (BB*TT)
#define WINDOW 1024

// Scratch (device globals: allocation-free per harness rules)
__device__ float g_q[M_TOTAL*DD];
__device__ float g_k[M_TOTAL*DD];
__device__ float g_v[M_TOTAL*DD];
__device__ float g_r[M_TOTAL*DD];

// ---------------------------------------------------------------------------
// GEMM: C[m,n] = sum_k A[m,k] * W[n,k]  (both K-contiguous), optional scale.
// BM=BN=64, BK=16, 256 threads, 4x4 micro-tile per thread.
// mode 0: A = X param, z in {0,1,2} selects (Wq->g_q, Wk->g_k, Wv->g_v)
// mode 1: A = g_r, W = W0, C = OutExt, scaled by *scale_ptr
// ---------------------------------------------------------------------------
__global__ __launch_bounds__(256) void gemm64(
    const float* __restrict__ X,
    const float* __restrict__ W0, const float* __restrict__ W1, const float* __restrict__ W2,
    float* __restrict__ OutExt, const float* __restrict__ scale_ptr, int mode)
{
    const float* A;
    const float* W;
    float* C;
    if (mode == 0) {
        A = X;
        int z = blockIdx.z;
        W = (z == 0) ? W0 : ((z == 1) ? W1 : W2);
        C = (z == 0) ? g_q : ((z == 1) ? g_k : g_v);
    } else {
        A = g_r; W = W0; C = OutExt;
    }

    __shared__ float As[16][68];   // [k][m], pitch 68 (16B-aligned rows, conflict-free f4 loads)
    __shared__ float Bs[16][68];   // [k][n]

    int t  = threadIdx.x;
    int m0 = blockIdx.x * 64;
    int n0 = blockIdx.y * 64;
    int tx = t & 15;      // n micro index
    int ty = t >> 4;      // m micro index

    int lr  = t >> 2;          // 0..63 : row being loaded
    int lk4 = (t & 3) * 4;     // 0,4,8,12 : k offset

    const float* Arow = A + (size_t)(m0 + lr) * DD;
    const float* Wrow = W + (size_t)(n0 + lr) * DD;

    float acc[4][4] = {};

    for (int k0 = 0; k0 < DD; k0 += 16) {
        float4 av = *(const float4*)(Arow + k0 + lk4);
        float4 bv = *(const float4*)(Wrow + k0 + lk4);
        As[lk4 + 0][lr] = av.x; As[lk4 + 1][lr] = av.y;
        As[lk4 + 2][lr] = av.z; As[lk4 + 3][lr] = av.w;
        Bs[lk4 + 0][lr] = bv.x; Bs[lk4 + 1][lr] = bv.y;
        Bs[lk4 + 2][lr] = bv.z; Bs[lk4 + 3][lr] = bv.w;
        __syncthreads();
        #pragma unroll
        for (int kk = 0; kk < 16; kk++) {
            float4 a = *(const float4*)&As[kk][ty * 4];
            float4 b = *(const float4*)&Bs[kk][tx * 4];
            acc[0][0] += a.x * b.x; acc[0][1] += a.x * b.y; acc[0][2] += a.x * b.z; acc[0][3] += a.x * b.w;
            acc[1][0] += a.y * b.x; acc[1][1] += a.y * b.y; acc[1][2] += a.y * b.z; acc[1][3] += a.y * b.w;
            acc[2][0] += a.z * b.x; acc[2][1] += a.z * b.y; acc[2][2] += a.z * b.z; acc[2][3] += a.z * b.w;
            acc[3][0] += a.w * b.x; acc[3][1] += a.w * b.y; acc[3][2] += a.w * b.z; acc[3][3] += a.w * b.w;
        }
        __syncthreads();
    }

    float sc = (scale_ptr != nullptr) ? *scale_ptr : 1.0f;
    #pragma unroll
    for (int i = 0; i < 4; i++) {
        float4 o;
        o.x = acc[i][0] * sc; o.y = acc[i][1] * sc;
        o.z = acc[i][2] * sc; o.w = acc[i][3] * sc;
        *(float4*)(C + (size_t)(m0 + ty * 4 + i) * DD + n0 + tx * 4) = o;
    }
}

// ---------------------------------------------------------------------------
// Windowed decayed attention.
// Block: 32 queries (i0..i0+31) of batch b. O accumulator [32][1024] in smem.
// For each 64-key chunk in (i0, i0+32+WINDOW):
//   phase1: S[32x64] = Q Kt (per-thread 4q x 2j), streamed over 16 k-slices
//   phase2: apply decay weights -> Ss smem
//   phase3: O += Ss @ V, streamed over 16 d-slices (V swizzled for LDS.128)
// ---------------------------------------------------------------------------
#define OSM_OFF 0        // 32*1024 = 32768
#define QS_OFF  32768    // 32*68   = 2176
#define KT_OFF  34944    // 64*66   = 4224
#define SS_OFF  39168    // 32*68   = 2176
#define VS_OFF  41344    // 64*64   = 4096
#define SMEM_FLOATS 45440
#define SMEM_BYTES (SMEM_FLOATS * 4)

__global__ __launch_bounds__(256, 1) void attn_kernel(const float* __restrict__ decay_logit_p)
{
    extern __shared__ float sm[];
    float* Osm = sm + OSM_OFF;
    float* Qs  = sm + QS_OFF;
    float* Kt  = sm + KT_OFF;
    float* Ss  = sm + SS_OFF;
    float* Vs  = sm + VS_OFF;

    int t  = threadIdx.x;
    int b  = blockIdx.y;
    int i0 = blockIdx.x * 32;

    float dl    = *decay_logit_p;
    float decay = 1.0f / (1.0f + expf(-dl));
    float log2d = log2f(decay);
    const float qk_scale = 0.03125f;  // 1/sqrt(1024)

    // zero O accumulator
    for (int i = t; i < 32 * 256; i += 256) {
        float4 z = {0.f, 0.f, 0.f, 0.f};
        ((float4*)Osm)[i] = z;
    }
    __syncthreads();

    int jstart = (i0 + 1) & ~63;
    int jend   = min(TT, i0 + 32 + WINDOW);

    int qb = (t >> 5) * 4;     // warp -> 4 queries
    int jb = (t & 31) * 2;     // lane -> 2 keys

    size_t qrow0 = (size_t)(b * TT + i0) * DD;

    for (int cs = jstart; cs < jend; cs += 64) {
        size_t krow0 = (size_t)(b * TT + cs) * DD;
        float sacc[4][2] = {};

        // ---- phase 1: scores ----
        for (int ks = 0; ks < DD; ks += 64) {
            __syncthreads();
            #pragma unroll
            for (int i = 0; i < 2; i++) {           // Qs[32][64] pitch 68
                int f = t + 256 * i;
                int r = f >> 4, g = f & 15;
                float4 v = *(const float4*)(g_q + qrow0 + (size_t)r * DD + ks + g * 4);
                *(float4*)&Qs[r * 68 + g * 4] = v;
            }
            #pragma unroll
            for (int i = 0; i < 4; i++) {           // Kt[kk][j] pitch 66 (transposed)
                int f = t + 256 * i;
                int r = f >> 4, g = f & 15;
                float4 v = *(const float4*)(g_k + krow0 + (size_t)r * DD + ks + g * 4);
                Kt[(g * 4 + 0) * 66 + r] = v.x;
                Kt[(g * 4 + 1) * 66 + r] = v.y;
                Kt[(g * 4 + 2) * 66 + r] = v.z;
                Kt[(g * 4 + 3) * 66 + r] = v.w;
            }
            __syncthreads();
            #pragma unroll 4
            for (int kk = 0; kk < 64; kk++) {
                float a0 = Qs[(qb + 0) * 68 + kk];
                float a1 = Qs[(qb + 1) * 68 + kk];
                float a2 = Qs[(qb + 2) * 68 + kk];
                float a3 = Qs[(qb + 3) * 68 + kk];
                float2 bv = *(const float2*)&Kt[kk * 66 + jb];
                sacc[0][0] += a0 * bv.x; sacc[0][1] += a0 * bv.y;
                sacc[1][0] += a1 * bv.x; sacc[1][1] += a1 * bv.y;
                sacc[2][0] += a2 * bv.x; sacc[2][1] += a2 * bv.y;
                sacc[3][0] += a3 * bv.x; sacc[3][1] += a3 * bv.y;
            }
        }

        // ---- phase 2: decay weights -> Ss ----
        #pragma unroll
        for (int qi = 0; qi < 4; qi++) {
            int iq = i0 + qb + qi;
            #pragma unroll
            for (int jj = 0; jj < 2; jj++) {
                int jg = cs + jb + jj;
                float w = 0.0f;
                if (jg > iq) {
                    float e = (float)(jg - iq - 1);
                    w = qk_scale * exp2f(e * log2d);
                }
                Ss[(qb + qi) * 68 + jb + jj] = sacc[qi][jj] * w;
            }
        }

        // ---- phase 3: O += Ss @ V ----
        int q  = t >> 3;
        int dg = t & 7;
        for (int d0 = 0; d0 < DD; d0 += 64) {
            __syncthreads();
            #pragma unroll
            for (int i = 0; i < 4; i++) {           // Vs[64][64] XOR-swizzled float4 groups
                int f = t + 256 * i;
                int r = f >> 4, g = f & 15;
                float4 v = *(const float4*)(g_v + krow0 + (size_t)r * DD + d0 + g * 4);
                *(float4*)&Vs[r * 64 + ((g ^ (r & 15)) << 2)] = v;
            }
            __syncthreads();
            float4 o0 = *(float4*)&Osm[q * 1024 + d0 + dg * 4];
            float4 o1 = *(float4*)&Osm[q * 1024 + d0 + 32 + dg * 4];
            #pragma unroll 4
            for (int j = 0; j < 64; j++) {
                float s = Ss[q * 68 + j];
                float4 va = *(const float4*)&Vs[j * 64 + (((dg    ) ^ (j & 15)) << 2)];
                float4 vb = *(const float4*)&Vs[j * 64 + (((dg + 8) ^ (j & 15)) << 2)];
                o0.x += s * va.x; o0.y += s * va.y; o0.z += s * va.z; o0.w += s * va.w;
                o1.x += s * vb.x; o1.y += s * vb.y; o1.z += s * vb.z; o1.w += s * vb.w;
            }
            *(float4*)&Osm[q * 1024 + d0 + dg * 4] = o0;
            *(float4*)&Osm[q * 1024 + d0 + 32 + dg * 4] = o1;
        }
    }

    __syncthreads();
    // write retrieved tile to gmem
    #pragma unroll
    for (int i = 0; i < 32; i++) {
        int f = t + 256 * i;          // 8192 float4 total
        int r  = f >> 8;
        int c4 = (f & 255) * 4;
        *(float4*)(g_r + qrow0 + (size_t)r * DD + c4) = *(float4*)&Osm[r * 1024 + c4];
    }
}

// ---------------------------------------------------------------------------
extern "C" void kernel_launch(void* const* d_in, const int* in_sizes, int n_in,
                              void* d_out, int out_size)
{
    const float* x  = (const float*)d_in[0];
    const float* Wq = (const float*)d_in[1];
    const float* Wk = (const float*)d_in[2];
    const float* Wv = (const float*)d_in[3];
    const float* Wo = (const float*)d_in[4];
    const float* decay_logit = (const float*)d_in[5];
    const float* out_scale   = (const float*)d_in[6];
    float* out = (float*)d_out;

    // QKV projections: 3 GEMMs of [16384,1024] x [1024,1024]^T
    dim3 gq(M_TOTAL / 64, DD / 64, 3);
    gemm64<<<gq, 256>>>(x, Wq, Wk, Wv, nullptr, nullptr, 0);

    // Windowed decayed attention
    cudaFuncSetAttribute(attn_kernel, cudaFuncAttributeMaxDynamicSharedMemorySize, SMEM_BYTES);
    attn_kernel<<<dim3(TT / 32, BB), 256, SMEM_BYTES>>>(decay_logit);

    // Output projection with out_scale
    dim3 gp(M_TOTAL / 64, DD / 64, 1);
    gemm64<<<gp, 256>>>(x, Wo, Wo, Wo, out, out_scale, 1);
}

// round 3
// speedup vs baseline: 2.6578x; 2.6578x over previous
#include <cuda_runtime.h>
#include <cuda_bf16.h>
#include <math.h>
#include <stdint.h>

#define BB 4
#define TT 4096
#define DD 1024
#define M_TOTAL (BB*TT)
#define WINDOW 256

// ------------------------- scratch (device globals) -------------------------
__device__ float g_q[M_TOTAL*DD];
__device__ float g_k[M_TOTAL*DD];
__device__ float g_v[M_TOTAL*DD];
__device__ float g_r[M_TOTAL*DD];
__device__ __nv_bfloat16 g_xhi[M_TOTAL*DD];
__device__ __nv_bfloat16 g_xlo[M_TOTAL*DD];
__device__ __nv_bfloat16 g_whi[4*DD*DD];
__device__ __nv_bfloat16 g_wlo[4*DD*DD];
__device__ __nv_bfloat16 g_rhi[M_TOTAL*DD];
__device__ __nv_bfloat16 g_rlo[M_TOTAL*DD];

// ------------------------- helpers ------------------------------------------
__device__ __forceinline__ uint32_t smem_to_u32(const void* p) {
    uint32_t a;
    asm("{ .reg .u64 t; cvta.to.shared.u64 t, %1; cvt.u32.u64 %0, t; }" : "=r"(a) : "l"(p));
    return a;
}
__device__ __forceinline__ void cp_async16(uint32_t saddr, const void* g) {
    asm volatile("cp.async.cg.shared.global [%0], [%1], 16;" :: "r"(saddr), "l"(g));
}
#define CP_COMMIT() asm volatile("cp.async.commit_group;" ::: "memory")
#define CP_WAIT1()  asm volatile("cp.async.wait_group 1;" ::: "memory")
#define CP_WAIT0()  asm volatile("cp.async.wait_group 0;" ::: "memory")

__device__ __forceinline__ void ldsm_x4(uint32_t* r, uint32_t addr) {
    asm volatile("ldmatrix.sync.aligned.m8n8.x4.shared.b16 {%0,%1,%2,%3}, [%4];"
        : "=r"(r[0]), "=r"(r[1]), "=r"(r[2]), "=r"(r[3]) : "r"(addr));
}
__device__ __forceinline__ void mma_bf16(float* d, const uint32_t* a, const uint32_t* b) {
    asm volatile("mma.sync.aligned.m16n8k16.row.col.f32.bf16.bf16.f32 "
        "{%0,%1,%2,%3}, {%4,%5,%6,%7}, {%8,%9}, {%0,%1,%2,%3};"
        : "+f"(d[0]), "+f"(d[1]), "+f"(d[2]), "+f"(d[3])
        : "r"(a[0]), "r"(a[1]), "r"(a[2]), "r"(a[3]), "r"(b[0]), "r"(b[1]));
}

// ------------------------- split conversion ---------------------------------
__global__ __launch_bounds__(256) void split_kernel(
    const float* __restrict__ src, __nv_bfloat16* __restrict__ hi,
    __nv_bfloat16* __restrict__ lo, int n4)
{
    int i = blockIdx.x * 256 + threadIdx.x;
    if (i >= n4) return;
    float4 v = ((const float4*)src)[i];
    __nv_bfloat16 h0 = __float2bfloat16(v.x);
    __nv_bfloat16 h1 = __float2bfloat16(v.y);
    __nv_bfloat16 h2 = __float2bfloat16(v.z);
    __nv_bfloat16 h3 = __float2bfloat16(v.w);
    __nv_bfloat16 l0 = __float2bfloat16(v.x - __bfloat162float(h0));
    __nv_bfloat16 l1 = __float2bfloat16(v.y - __bfloat162float(h1));
    __nv_bfloat16 l2 = __float2bfloat16(v.z - __bfloat162float(h2));
    __nv_bfloat16 l3 = __float2bfloat16(v.w - __bfloat162float(h3));
    __nv_bfloat162 H0; H0.x = h0; H0.y = h1;
    __nv_bfloat162 H1; H1.x = h2; H1.y = h3;
    __nv_bfloat162 L0; L0.x = l0; L0.y = l1;
    __nv_bfloat162 L1; L1.x = l2; L1.y = l3;
    ((__nv_bfloat162*)hi)[2*i]   = H0;
    ((__nv_bfloat162*)hi)[2*i+1] = H1;
    ((__nv_bfloat162*)lo)[2*i]   = L0;
    ((__nv_bfloat162*)lo)[2*i+1] = L1;
}

// ------------------------- HMMA GEMM -----------------------------------------
// C[m,n] = sum_k A[m,k]*W[n,k], bf16 hi/lo split (3 mma passes), fp32 accum.
// CTA tile 128x128, BK=32, 256 threads (8 warps: 4 in M x 2 in N).
// Warp tile 32x64 = 2 x 8 m16n8 mma tiles. Smem pitch 40 bf16 (80B) -> ldmatrix
// conflict-free. Double-buffered cp.async pipeline.
#define PITCH   40
#define TILEB   (128*PITCH*2)      // 10240 B per operand tile
#define STAGEB  (4*TILEB)          // Ahi, Alo, Bhi, Blo
#define GSMEM   (2*STAGEB)         // 81920 B

__global__ __launch_bounds__(256, 1) void mma_gemm(
    const __nv_bfloat16* __restrict__ Ahi, const __nv_bfloat16* __restrict__ Alo,
    const __nv_bfloat16* __restrict__ Whi, const __nv_bfloat16* __restrict__ Wlo,
    float* __restrict__ C0, float* __restrict__ C1, float* __restrict__ C2,
    const float* __restrict__ scale_ptr)
{
    extern __shared__ char smc[];
    uint32_t sb = smem_to_u32(smc);
    int t = threadIdx.x, lane = t & 31, w = t >> 5;
    int wm = w & 3, wn = w >> 2;
    int m0 = blockIdx.x * 128, n0 = blockIdx.y * 128, z = blockIdx.z;

    const __nv_bfloat16* Wh = Whi + (size_t)z * DD * DD;
    const __nv_bfloat16* Wl = Wlo + (size_t)z * DD * DD;
    float* C = (z == 0) ? C0 : ((z == 1) ? C1 : C2);

    const __nv_bfloat16* aH = Ahi + (size_t)m0 * DD;
    const __nv_bfloat16* aL = Alo + (size_t)m0 * DD;
    const __nv_bfloat16* bH = Wh + (size_t)n0 * DD;
    const __nv_bfloat16* bL = Wl + (size_t)n0 * DD;

    float acc[2][8][4];
    #pragma unroll
    for (int i = 0; i < 2; i++)
        #pragma unroll
        for (int n = 0; n < 8; n++)
            #pragma unroll
            for (int j = 0; j < 4; j++) acc[i][n][j] = 0.f;

    // prefetch lambda (manual): stage c loads k-slice [c*32, c*32+32)
    #define PREFETCH(c) do { \
        uint32_t base_ = sb + ((c) & 1) * STAGEB; \
        int k0_ = (c) * 32; \
        _Pragma("unroll") \
        for (int i_ = 0; i_ < 2; i_++) { \
            int idx_ = t + 256 * i_; \
            int r_ = idx_ >> 2, c_ = idx_ & 3; \
            uint32_t so_ = (uint32_t)(r_ * 80 + c_ * 16); \
            size_t go_ = (size_t)r_ * DD + k0_ + c_ * 8; \
            cp_async16(base_ + 0 * TILEB + so_, aH + go_); \
            cp_async16(base_ + 1 * TILEB + so_, aL + go_); \
            cp_async16(base_ + 2 * TILEB + so_, bH + go_); \
            cp_async16(base_ + 3 * TILEB + so_, bL + go_); \
        } \
    } while (0)

    PREFETCH(0); CP_COMMIT();

    for (int c = 0; c < 32; c++) {
        if (c + 1 < 32) { PREFETCH(c + 1); CP_COMMIT(); CP_WAIT1(); }
        else            { CP_WAIT0(); }
        __syncthreads();

        uint32_t base = sb + (c & 1) * STAGEB;
        #pragma unroll
        for (int kk = 0; kk < 2; kk++) {
            uint32_t ah[2][4], al[2][4];
            #pragma unroll
            for (int i = 0; i < 2; i++) {
                uint32_t ro = (uint32_t)((wm * 32 + i * 16 + (lane & 15)) * 80
                                         + kk * 32 + (lane >> 4) * 16);
                ldsm_x4(ah[i], base + 0 * TILEB + ro);
                ldsm_x4(al[i], base + 1 * TILEB + ro);
            }
            uint32_t bh[8][2], bl[8][2];
            #pragma unroll
            for (int p = 0; p < 4; p++) {
                int mid = lane >> 3;
                int nr = wn * 64 + p * 16 + ((mid & 2) << 2) + (lane & 7);
                uint32_t ro = (uint32_t)(nr * 80 + kk * 32 + (mid & 1) * 16);
                uint32_t r4[4];
                ldsm_x4(r4, base + 2 * TILEB + ro);
                bh[2*p][0] = r4[0]; bh[2*p][1] = r4[1];
                bh[2*p+1][0] = r4[2]; bh[2*p+1][1] = r4[3];
                ldsm_x4(r4, base + 3 * TILEB + ro);
                bl[2*p][0] = r4[0]; bl[2*p][1] = r4[1];
                bl[2*p+1][0] = r4[2]; bl[2*p+1][1] = r4[3];
            }
            #pragma unroll
            for (int i = 0; i < 2; i++)
                #pragma unroll
                for (int n = 0; n < 8; n++) {
                    mma_bf16(acc[i][n], ah[i], bh[n]);
                    mma_bf16(acc[i][n], ah[i], bl[n]);
                    mma_bf16(acc[i][n], al[i], bh[n]);
                }
        }
        __syncthreads();
    }

    float sc = (scale_ptr != nullptr) ? *scale_ptr : 1.0f;
    int gid = lane >> 2, tig = lane & 3;
    #pragma unroll
    for (int i = 0; i < 2; i++) {
        int r = m0 + wm * 32 + i * 16 + gid;
        #pragma unroll
        for (int n = 0; n < 8; n++) {
            int col = n0 + wn * 64 + n * 8 + tig * 2;
            float2 v0; v0.x = acc[i][n][0] * sc; v0.y = acc[i][n][1] * sc;
            float2 v1; v1.x = acc[i][n][2] * sc; v1.y = acc[i][n][3] * sc;
            *(float2*)(C + (size_t)r * DD + col) = v0;
            *(float2*)(C + (size_t)(r + 8) * DD + col) = v1;
        }
    }
}

// ------------------------- windowed decayed attention (SIMT fp32) -----------
#define OSM_OFF 0
#define QS_OFF  32768
#define KT_OFF  34944
#define SS_OFF  39168
#define VS_OFF  41344
#define SMEM_FLOATS 45440
#define SMEM_BYTES (SMEM_FLOATS * 4)

__global__ __launch_bounds__(256, 1) void attn_kernel(const float* __restrict__ decay_logit_p)
{
    extern __shared__ float sm[];
    float* Osm = sm + OSM_OFF;
    float* Qs  = sm + QS_OFF;
    float* Kt  = sm + KT_OFF;
    float* Ss  = sm + SS_OFF;
    float* Vs  = sm + VS_OFF;

    int t  = threadIdx.x;
    int b  = blockIdx.y;
    int i0 = blockIdx.x * 32;

    float dl    = *decay_logit_p;
    float decay = 1.0f / (1.0f + expf(-dl));
    float log2d = log2f(decay);
    const float qk_scale = 0.03125f;

    for (int i = t; i < 32 * 256; i += 256) {
        float4 zz = {0.f, 0.f, 0.f, 0.f};
        ((float4*)Osm)[i] = zz;
    }
    __syncthreads();

    int jstart = (i0 + 1) & ~63;
    int jend   = min(TT, i0 + 32 + WINDOW);

    int qb = (t >> 5) * 4;
    int jb = (t & 31) * 2;

    size_t qrow0 = (size_t)(b * TT + i0) * DD;

    for (int cs = jstart; cs < jend; cs += 64) {
        size_t krow0 = (size_t)(b * TT + cs) * DD;
        float sacc[4][2] = {};

        for (int ks = 0; ks < DD; ks += 64) {
            __syncthreads();
            #pragma unroll
            for (int i = 0; i < 2; i++) {
                int f = t + 256 * i;
                int r = f >> 4, g = f & 15;
                float4 v = *(const float4*)(g_q + qrow0 + (size_t)r * DD + ks + g * 4);
                *(float4*)&Qs[r * 68 + g * 4] = v;
            }
            #pragma unroll
            for (int i = 0; i < 4; i++) {
                int f = t + 256 * i;
                int r = f >> 4, g = f & 15;
                float4 v = *(const float4*)(g_k + krow0 + (size_t)r * DD + ks + g * 4);
                Kt[(g * 4 + 0) * 66 + r] = v.x;
                Kt[(g * 4 + 1) * 66 + r] = v.y;
                Kt[(g * 4 + 2) * 66 + r] = v.z;
                Kt[(g * 4 + 3) * 66 + r] = v.w;
            }
            __syncthreads();
            #pragma unroll 4
            for (int kk = 0; kk < 64; kk++) {
                float a0 = Qs[(qb + 0) * 68 + kk];
                float a1 = Qs[(qb + 1) * 68 + kk];
                float a2 = Qs[(qb + 2) * 68 + kk];
                float a3 = Qs[(qb + 3) * 68 + kk];
                float2 bv = *(const float2*)&Kt[kk * 66 + jb];
                sacc[0][0] += a0 * bv.x; sacc[0][1] += a0 * bv.y;
                sacc[1][0] += a1 * bv.x; sacc[1][1] += a1 * bv.y;
                sacc[2][0] += a2 * bv.x; sacc[2][1] += a2 * bv.y;
                sacc[3][0] += a3 * bv.x; sacc[3][1] += a3 * bv.y;
            }
        }

        #pragma unroll
        for (int qi = 0; qi < 4; qi++) {
            int iq = i0 + qb + qi;
            #pragma unroll
            for (int jj = 0; jj < 2; jj++) {
                int jg = cs + jb + jj;
                float wgt = 0.0f;
                if (jg > iq) {
                    float e = (float)(jg - iq - 1);
                    wgt = qk_scale * exp2f(e * log2d);
                }
                Ss[(qb + qi) * 68 + jb + jj] = sacc[qi][jj] * wgt;
            }
        }

        int q  = t >> 3;
        int dg = t & 7;
        for (int d0 = 0; d0 < DD; d0 += 64) {
            __syncthreads();
            #pragma unroll
            for (int i = 0; i < 4; i++) {
                int f = t + 256 * i;
                int r = f >> 4, g = f & 15;
                float4 v = *(const float4*)(g_v + krow0 + (size_t)r * DD + d0 + g * 4);
                *(float4*)&Vs[r * 64 + ((g ^ (r & 15)) << 2)] = v;
            }
            __syncthreads();
            float4 o0 = *(float4*)&Osm[q * 1024 + d0 + dg * 4];
            float4 o1 = *(float4*)&Osm[q * 1024 + d0 + 32 + dg * 4];
            #pragma unroll 4
            for (int j = 0; j < 64; j++) {
                float s = Ss[q * 68 + j];
                float4 va = *(const float4*)&Vs[j * 64 + (((dg    ) ^ (j & 15)) << 2)];
                float4 vb = *(const float4*)&Vs[j * 64 + (((dg + 8) ^ (j & 15)) << 2)];
                o0.x += s * va.x; o0.y += s * va.y; o0.z += s * va.z; o0.w += s * va.w;
                o1.x += s * vb.x; o1.y += s * vb.y; o1.z += s * vb.z; o1.w += s * vb.w;
            }
            *(float4*)&Osm[q * 1024 + d0 + dg * 4] = o0;
            *(float4*)&Osm[q * 1024 + d0 + 32 + dg * 4] = o1;
        }
    }

    __syncthreads();
    #pragma unroll
    for (int i = 0; i < 32; i++) {
        int f = t + 256 * i;
        int r  = f >> 8;
        int c4 = (f & 255) * 4;
        *(float4*)(g_r + qrow0 + (size_t)r * DD + c4) = *(float4*)&Osm[r * 1024 + c4];
    }
}

// ---------------------------------------------------------------------------
extern "C" void kernel_launch(void* const* d_in, const int* in_sizes, int n_in,
                              void* d_out, int out_size)
{
    const float* x  = (const float*)d_in[0];
    const float* Wq = (const float*)d_in[1];
    const float* Wk = (const float*)d_in[2];
    const float* Wv = (const float*)d_in[3];
    const float* Wo = (const float*)d_in[4];
    const float* decay_logit = (const float*)d_in[5];
    const float* out_scale   = (const float*)d_in[6];
    float* out = (float*)d_out;

    __nv_bfloat16 *xhi, *xlo, *whi, *wlo, *rhi, *rlo;
    float *qf, *kf, *vf, *rf;
    cudaGetSymbolAddress((void**)&xhi, g_xhi);
    cudaGetSymbolAddress((void**)&xlo, g_xlo);
    cudaGetSymbolAddress((void**)&whi, g_whi);
    cudaGetSymbolAddress((void**)&wlo, g_wlo);
    cudaGetSymbolAddress((void**)&rhi, g_rhi);
    cudaGetSymbolAddress((void**)&rlo, g_rlo);
    cudaGetSymbolAddress((void**)&qf, g_q);
    cudaGetSymbolAddress((void**)&kf, g_k);
    cudaGetSymbolAddress((void**)&vf, g_v);
    cudaGetSymbolAddress((void**)&rf, g_r);

    int nx4 = M_TOTAL * DD / 4;
    int nw4 = DD * DD / 4;
    split_kernel<<<(nx4 + 255) / 256, 256>>>(x, xhi, xlo, nx4);
    split_kernel<<<(nw4 + 255) / 256, 256>>>(Wq, whi + 0 * (size_t)DD * DD, wlo + 0 * (size_t)DD * DD, nw4);
    split_kernel<<<(nw4 + 255) / 256, 256>>>(Wk, whi + 1 * (size_t)DD * DD, wlo + 1 * (size_t)DD * DD, nw4);
    split_kernel<<<(nw4 + 255) / 256, 256>>>(Wv, whi + 2 * (size_t)DD * DD, wlo + 2 * (size_t)DD * DD, nw4);
    split_kernel<<<(nw4 + 255) / 256, 256>>>(Wo, whi + 3 * (size_t)DD * DD, wlo + 3 * (size_t)DD * DD, nw4);

    cudaFuncSetAttribute(mma_gemm, cudaFuncAttributeMaxDynamicSharedMemorySize, GSMEM);

    // QKV projections (tensor cores via mma.sync)
    mma_gemm<<<dim3(M_TOTAL / 128, DD / 128, 3), 256, GSMEM>>>(
        xhi, xlo, whi, wlo, qf, kf, vf, nullptr);

    // windowed decayed attention (fp32 SIMT, window 256)
    cudaFuncSetAttribute(attn_kernel, cudaFuncAttributeMaxDynamicSharedMemorySize, SMEM_BYTES);
    attn_kernel<<<dim3(TT / 32, BB), 256, SMEM_BYTES>>>(decay_logit);

    // output projection
    split_kernel<<<(nx4 + 255) / 256, 256>>>(rf, rhi, rlo, nx4);
    mma_gemm<<<dim3(M_TOTAL / 128, DD / 128, 1), 256, GSMEM>>>(
        rhi, rlo, whi + 3 * (size_t)DD * DD, wlo + 3 * (size_t)DD * DD,
        out, out, out, out_scale);
}

// round 5
// speedup vs baseline: 4.3822x; 1.6488x over previous
#include <cuda_runtime.h>
#include <cuda_bf16.h>
#include <math.h>
#include <stdint.h>

#define BB 4
#define TT 4096
#define DD 1024
#define M_TOTAL (BB*TT)

// ------------------------- scratch (device globals) -------------------------
__device__ __nv_bfloat16 g_xhi[M_TOTAL*DD];
__device__ __nv_bfloat16 g_xlo[M_TOTAL*DD];
__device__ __nv_bfloat16 g_whi[4*DD*DD];
__device__ __nv_bfloat16 g_wlo[4*DD*DD];
__device__ __nv_bfloat16 g_qhi[M_TOTAL*DD];
__device__ __nv_bfloat16 g_qlo[M_TOTAL*DD];
__device__ __nv_bfloat16 g_khi[M_TOTAL*DD];
__device__ __nv_bfloat16 g_klo[M_TOTAL*DD];
__device__ __nv_bfloat16 g_vhi[M_TOTAL*DD];
__device__ __nv_bfloat16 g_vlo[M_TOTAL*DD];
__device__ __nv_bfloat16 g_rhi[M_TOTAL*DD];
__device__ __nv_bfloat16 g_rlo[M_TOTAL*DD];

// ------------------------- helpers ------------------------------------------
__device__ __forceinline__ uint32_t smem_to_u32(const void* p) {
    uint32_t a;
    asm("{ .reg .u64 t; cvta.to.shared.u64 t, %1; cvt.u32.u64 %0, t; }" : "=r"(a) : "l"(p));
    return a;
}
__device__ __forceinline__ void cp_async16(uint32_t saddr, const void* g) {
    asm volatile("cp.async.cg.shared.global [%0], [%1], 16;" :: "r"(saddr), "l"(g));
}
#define CP_COMMIT() asm volatile("cp.async.commit_group;" ::: "memory")
#define CP_WAIT1()  asm volatile("cp.async.wait_group 1;" ::: "memory")
#define CP_WAIT0()  asm volatile("cp.async.wait_group 0;" ::: "memory")

__device__ __forceinline__ void ldsm_x4(uint32_t* r, uint32_t addr) {
    asm volatile("ldmatrix.sync.aligned.m8n8.x4.shared.b16 {%0,%1,%2,%3}, [%4];"
        : "=r"(r[0]), "=r"(r[1]), "=r"(r[2]), "=r"(r[3]) : "r"(addr));
}
__device__ __forceinline__ void ldsm_x4_t(uint32_t* r, uint32_t addr) {
    asm volatile("ldmatrix.sync.aligned.m8n8.x4.trans.shared.b16 {%0,%1,%2,%3}, [%4];"
        : "=r"(r[0]), "=r"(r[1]), "=r"(r[2]), "=r"(r[3]) : "r"(addr));
}
__device__ __forceinline__ void mma_bf16(float* d, const uint32_t* a, const uint32_t* b) {
    asm volatile("mma.sync.aligned.m16n8k16.row.col.f32.bf16.bf16.f32 "
        "{%0,%1,%2,%3}, {%4,%5,%6,%7}, {%8,%9}, {%0,%1,%2,%3};"
        : "+f"(d[0]), "+f"(d[1]), "+f"(d[2]), "+f"(d[3])
        : "r"(a[0]), "r"(a[1]), "r"(a[2]), "r"(a[3]), "r"(b[0]), "r"(b[1]));
}
__device__ __forceinline__ uint32_t pack_bf16(float a, float b) {
    __nv_bfloat162 h = __floats2bfloat162_rn(a, b);
    return *(uint32_t*)&h;
}

// ------------------------- split conversion ---------------------------------
__global__ __launch_bounds__(256) void split_kernel(
    const float* __restrict__ src, __nv_bfloat16* __restrict__ hi,
    __nv_bfloat16* __restrict__ lo, int n4)
{
    int i = blockIdx.x * 256 + threadIdx.x;
    if (i >= n4) return;
    float4 v = ((const float4*)src)[i];
    __nv_bfloat16 h0 = __float2bfloat16(v.x);
    __nv_bfloat16 h1 = __float2bfloat16(v.y);
    __nv_bfloat16 h2 = __float2bfloat16(v.z);
    __nv_bfloat16 h3 = __float2bfloat16(v.w);
    __nv_bfloat16 l0 = __float2bfloat16(v.x - __bfloat162float(h0));
    __nv_bfloat16 l1 = __float2bfloat16(v.y - __bfloat162float(h1));
    __nv_bfloat16 l2 = __float2bfloat16(v.z - __bfloat162float(h2));
    __nv_bfloat16 l3 = __float2bfloat16(v.w - __bfloat162float(h3));
    __nv_bfloat162 H0; H0.x = h0; H0.y = h1;
    __nv_bfloat162 H1; H1.x = h2; H1.y = h3;
    __nv_bfloat162 L0; L0.x = l0; L0.y = l1;
    __nv_bfloat162 L1; L1.x = l2; L1.y = l3;
    ((__nv_bfloat162*)hi)[2*i]   = H0;
    ((__nv_bfloat162*)hi)[2*i+1] = H1;
    ((__nv_bfloat162*)lo)[2*i]   = L0;
    ((__nv_bfloat162*)lo)[2*i+1] = L1;
}

// ------------------------- HMMA GEMM -----------------------------------------
// mode 0: C = A*W^T per z in {0,1,2}; outputs written as bf16 hi/lo pairs.
// mode 1: C = A*W^T * scale written fp32 to Cf.
#define PITCH   40
#define TILEB   (128*PITCH*2)      // 10240 B per operand tile
#define STAGEB  (4*TILEB)
#define GSMEM   (2*STAGEB)         // 81920 B

__global__ __launch_bounds__(256, 1) void mma_gemm(
    const __nv_bfloat16* __restrict__ Ahi, const __nv_bfloat16* __restrict__ Alo,
    const __nv_bfloat16* __restrict__ Whi, const __nv_bfloat16* __restrict__ Wlo,
    __nv_bfloat16* __restrict__ H0, __nv_bfloat16* __restrict__ L0,
    __nv_bfloat16* __restrict__ H1, __nv_bfloat16* __restrict__ L1,
    __nv_bfloat16* __restrict__ H2, __nv_bfloat16* __restrict__ L2,
    float* __restrict__ Cf, const float* __restrict__ scale_ptr, int mode)
{
    extern __shared__ char smc[];
    uint32_t sb = smem_to_u32(smc);
    int t = threadIdx.x, lane = t & 31, w = t >> 5;
    int wm = w & 3, wn = w >> 2;
    int m0 = blockIdx.x * 128, n0 = blockIdx.y * 128, z = blockIdx.z;

    const __nv_bfloat16* Wh = Whi + (size_t)z * DD * DD;
    const __nv_bfloat16* Wl = Wlo + (size_t)z * DD * DD;

    const __nv_bfloat16* aH = Ahi + (size_t)m0 * DD;
    const __nv_bfloat16* aL = Alo + (size_t)m0 * DD;
    const __nv_bfloat16* bH = Wh + (size_t)n0 * DD;
    const __nv_bfloat16* bL = Wl + (size_t)n0 * DD;

    float acc[2][8][4];
    #pragma unroll
    for (int i = 0; i < 2; i++)
        #pragma unroll
        for (int n = 0; n < 8; n++)
            #pragma unroll
            for (int j = 0; j < 4; j++) acc[i][n][j] = 0.f;

    #define PREFETCH(c) do { \
        uint32_t base_ = sb + ((c) & 1) * STAGEB; \
        int k0_ = (c) * 32; \
        _Pragma("unroll") \
        for (int i_ = 0; i_ < 2; i_++) { \
            int idx_ = t + 256 * i_; \
            int r_ = idx_ >> 2, c_ = idx_ & 3; \
            uint32_t so_ = (uint32_t)(r_ * 80 + c_ * 16); \
            size_t go_ = (size_t)r_ * DD + k0_ + c_ * 8; \
            cp_async16(base_ + 0 * TILEB + so_, aH + go_); \
            cp_async16(base_ + 1 * TILEB + so_, aL + go_); \
            cp_async16(base_ + 2 * TILEB + so_, bH + go_); \
            cp_async16(base_ + 3 * TILEB + so_, bL + go_); \
        } \
    } while (0)

    PREFETCH(0); CP_COMMIT();

    for (int c = 0; c < 32; c++) {
        if (c + 1 < 32) { PREFETCH(c + 1); CP_COMMIT(); CP_WAIT1(); }
        else            { CP_WAIT0(); }
        __syncthreads();

        uint32_t base = sb + (c & 1) * STAGEB;
        #pragma unroll
        for (int kk = 0; kk < 2; kk++) {
            uint32_t ah[2][4], al[2][4];
            #pragma unroll
            for (int i = 0; i < 2; i++) {
                uint32_t ro = (uint32_t)((wm * 32 + i * 16 + (lane & 15)) * 80
                                         + kk * 32 + (lane >> 4) * 16);
                ldsm_x4(ah[i], base + 0 * TILEB + ro);
                ldsm_x4(al[i], base + 1 * TILEB + ro);
            }
            uint32_t bh[8][2], bl[8][2];
            #pragma unroll
            for (int p = 0; p < 4; p++) {
                int mid = lane >> 3;
                int nr = wn * 64 + p * 16 + ((mid & 2) << 2) + (lane & 7);
                uint32_t ro = (uint32_t)(nr * 80 + kk * 32 + (mid & 1) * 16);
                uint32_t r4[4];
                ldsm_x4(r4, base + 2 * TILEB + ro);
                bh[2*p][0] = r4[0]; bh[2*p][1] = r4[1];
                bh[2*p+1][0] = r4[2]; bh[2*p+1][1] = r4[3];
                ldsm_x4(r4, base + 3 * TILEB + ro);
                bl[2*p][0] = r4[0]; bl[2*p][1] = r4[1];
                bl[2*p+1][0] = r4[2]; bl[2*p+1][1] = r4[3];
            }
            #pragma unroll
            for (int i = 0; i < 2; i++)
                #pragma unroll
                for (int n = 0; n < 8; n++) {
                    mma_bf16(acc[i][n], ah[i], bh[n]);
                    mma_bf16(acc[i][n], ah[i], bl[n]);
                    mma_bf16(acc[i][n], al[i], bh[n]);
                }
        }
        __syncthreads();
    }
    #undef PREFETCH

    int gid = lane >> 2, tig = lane & 3;
    if (mode == 0) {
        __nv_bfloat16* Hc = (z == 0) ? H0 : ((z == 1) ? H1 : H2);
        __nv_bfloat16* Lc = (z == 0) ? L0 : ((z == 1) ? L1 : L2);
        #pragma unroll
        for (int i = 0; i < 2; i++) {
            int r = m0 + wm * 32 + i * 16 + gid;
            #pragma unroll
            for (int n = 0; n < 8; n++) {
                int col = n0 + wn * 64 + n * 8 + tig * 2;
                float a0 = acc[i][n][0], a1 = acc[i][n][1];
                float a2 = acc[i][n][2], a3 = acc[i][n][3];
                uint32_t h01 = pack_bf16(a0, a1);
                uint32_t h23 = pack_bf16(a2, a3);
                __nv_bfloat162 hh;
                *(uint32_t*)&hh = h01;
                uint32_t l01 = pack_bf16(a0 - __bfloat162float(hh.x), a1 - __bfloat162float(hh.y));
                *(uint32_t*)&hh = h23;
                uint32_t l23 = pack_bf16(a2 - __bfloat162float(hh.x), a3 - __bfloat162float(hh.y));
                *(uint32_t*)(Hc + (size_t)r * DD + col) = h01;
                *(uint32_t*)(Lc + (size_t)r * DD + col) = l01;
                *(uint32_t*)(Hc + (size_t)(r + 8) * DD + col) = h23;
                *(uint32_t*)(Lc + (size_t)(r + 8) * DD + col) = l23;
            }
        }
    } else {
        float sc = *scale_ptr;
        #pragma unroll
        for (int i = 0; i < 2; i++) {
            int r = m0 + wm * 32 + i * 16 + gid;
            #pragma unroll
            for (int n = 0; n < 8; n++) {
                int col = n0 + wn * 64 + n * 8 + tig * 2;
                float2 v0; v0.x = acc[i][n][0] * sc; v0.y = acc[i][n][1] * sc;
                float2 v1; v1.x = acc[i][n][2] * sc; v1.y = acc[i][n][3] * sc;
                *(float2*)(Cf + (size_t)r * DD + col) = v0;
                *(float2*)(Cf + (size_t)(r + 8) * DD + col) = v1;
            }
        }
    }
}

// ------------------------- MMA windowed decayed attention --------------------
// 64 queries per CTA, 5 key-chunks of 64 (window ~319). 256 threads, 8 warps.
// Phase A: S = Q K^T (3-pass bf16 hi/lo), decay weights in regs, S -> smem hi/lo.
// Phase B: O = S V (3-pass), V via ldmatrix.trans; O -> g_rhi/g_rlo.
#define NCH 5
#define SPITCH 688                  // bytes per S row (344 bf16)
#define SHI_OFF 0
#define SLO_OFF 44032               // 64*688
#define PIPE_OFF 88064
#define QKSTAGE 20480               // Qhi,Qlo,Khi,Klo each 64*80
#define VPITCH 272                  // bytes per V row (128 d * 2B + 16 pad)
#define VSTAGE 34816                // Vhi,Vlo each 64*272
#define ATT_SMEM (PIPE_OFF + 2*VSTAGE)   // 157696

__global__ __launch_bounds__(256, 1) void attn_mma(const float* __restrict__ decay_logit_p)
{
    extern __shared__ char smc[];
    uint32_t sb = smem_to_u32(smc);
    int t = threadIdx.x, lane = t & 31, w = t >> 5;
    int wq = w & 3, wn = w >> 2;
    int b = blockIdx.y, i0 = blockIdx.x * 64;
    int ncv = min(NCH, (TT - i0) / 64);

    float dl = *decay_logit_p;
    float decay = 1.0f / (1.0f + expf(-dl));
    float log2d = log2f(decay);
    const float qk_scale = 0.03125f;

    const __nv_bfloat16* qh_g = g_qhi + (size_t)(b * TT + i0) * DD;
    const __nv_bfloat16* ql_g = g_qlo + (size_t)(b * TT + i0) * DD;
    const __nv_bfloat16* kh_g = g_khi + (size_t)(b * TT) * DD;
    const __nv_bfloat16* kl_g = g_klo + (size_t)(b * TT) * DD;
    const __nv_bfloat16* vh_g = g_vhi + (size_t)(b * TT) * DD;
    const __nv_bfloat16* vl_g = g_vlo + (size_t)(b * TT) * DD;

    int mid = lane >> 3;

    // ================= Phase A: scores =================
    for (int c = 0; c < ncv; c++) {
        int cs = i0 + c * 64;
        float acc[4][4];
        #pragma unroll
        for (int n = 0; n < 4; n++)
            #pragma unroll
            for (int j = 0; j < 4; j++) acc[n][j] = 0.f;

        // per d-step (32 cols): each thread loads one 16B seg per tile
        int lr = t >> 2, lseg = t & 3;
        uint32_t so = (uint32_t)(lr * 80 + lseg * 16);

        #define PF_QK(ds) do { \
            uint32_t base_ = sb + PIPE_OFF + ((ds) & 1) * QKSTAGE; \
            size_t qo_ = (size_t)lr * DD + (ds) * 32 + lseg * 8; \
            size_t ko_ = (size_t)(cs + lr) * DD + (ds) * 32 + lseg * 8; \
            cp_async16(base_ + 0    + so, qh_g + qo_); \
            cp_async16(base_ + 5120 + so, ql_g + qo_); \
            cp_async16(base_ + 10240 + so, kh_g + ko_); \
            cp_async16(base_ + 15360 + so, kl_g + ko_); \
        } while (0)

        PF_QK(0); CP_COMMIT();
        for (int ds = 0; ds < 32; ds++) {
            if (ds + 1 < 32) { PF_QK(ds + 1); CP_COMMIT(); CP_WAIT1(); }
            else             { CP_WAIT0(); }
            __syncthreads();
            uint32_t base = sb + PIPE_OFF + (ds & 1) * QKSTAGE;
            #pragma unroll
            for (int ks = 0; ks < 2; ks++) {
                uint32_t qh[4], ql[4];
                uint32_t roA = (uint32_t)((wq * 16 + (lane & 15)) * 80 + ks * 32 + (lane >> 4) * 16);
                ldsm_x4(qh, base + 0 + roA);
                ldsm_x4(ql, base + 5120 + roA);
                uint32_t kh[4][2], kl[4][2];
                #pragma unroll
                for (int p = 0; p < 2; p++) {
                    int nr = wn * 32 + p * 16 + ((mid & 2) << 2) + (lane & 7);
                    uint32_t roB = (uint32_t)(nr * 80 + ks * 32 + (mid & 1) * 16);
                    uint32_t r4[4];
                    ldsm_x4(r4, base + 10240 + roB);
                    kh[2*p][0] = r4[0]; kh[2*p][1] = r4[1];
                    kh[2*p+1][0] = r4[2]; kh[2*p+1][1] = r4[3];
                    ldsm_x4(r4, base + 15360 + roB);
                    kl[2*p][0] = r4[0]; kl[2*p][1] = r4[1];
                    kl[2*p+1][0] = r4[2]; kl[2*p+1][1] = r4[3];
                }
                #pragma unroll
                for (int n = 0; n < 4; n++) {
                    mma_bf16(acc[n], qh, kh[n]);
                    mma_bf16(acc[n], qh, kl[n]);
                    mma_bf16(acc[n], ql, kh[n]);
                }
            }
            __syncthreads();
        }
        #undef PF_QK

        // apply decay weights, split to bf16 hi/lo, store to S smem
        int rl0 = wq * 16 + (lane >> 2);
        #pragma unroll
        for (int n = 0; n < 4; n++) {
            int jl0 = wn * 32 + n * 8 + (lane & 3) * 2;     // local key idx in chunk
            float s[4];
            #pragma unroll
            for (int rr = 0; rr < 2; rr++) {
                int rl = rl0 + rr * 8;
                #pragma unroll
                for (int jj = 0; jj < 2; jj++) {
                    int diff = c * 64 + jl0 + jj - rl;      // j_global - i_global
                    float wt = 0.f;
                    if (diff > 0) wt = qk_scale * exp2f((float)(diff - 1) * log2d);
                    s[rr * 2 + jj] = acc[n][rr * 2 + jj] * wt;
                }
            }
            uint32_t jbyte = (uint32_t)((c * 64 + jl0) * 2);
            #pragma unroll
            for (int rr = 0; rr < 2; rr++) {
                int rl = rl0 + rr * 8;
                uint32_t h = pack_bf16(s[rr*2], s[rr*2+1]);
                __nv_bfloat162 hh; *(uint32_t*)&hh = h;
                uint32_t l = pack_bf16(s[rr*2] - __bfloat162float(hh.x),
                                       s[rr*2+1] - __bfloat162float(hh.y));
                uint32_t ad = (uint32_t)(rl * SPITCH) + jbyte;
                *(uint32_t*)(smc + SHI_OFF + ad) = h;
                *(uint32_t*)(smc + SLO_OFF + ad) = l;
            }
        }
        __syncthreads();
    }

    // ================= Phase B: O = S V =================
    int tot = 8 * ncv;
    int lr2 = t >> 4, lseg2 = t & 15;   // used inside PF_V via idx

    #define PF_V(it) do { \
        int db_ = (it) / ncv, c_ = (it) % ncv; \
        int cs_ = i0 + c_ * 64; \
        uint32_t base_ = sb + PIPE_OFF + ((it) & 1) * VSTAGE; \
        _Pragma("unroll") \
        for (int i_ = 0; i_ < 4; i_++) { \
            int idx_ = t + 256 * i_; \
            int r_ = idx_ >> 4, g_ = idx_ & 15; \
            uint32_t so_ = (uint32_t)(r_ * VPITCH + g_ * 16); \
            size_t go_ = (size_t)(cs_ + r_) * DD + db_ * 128 + g_ * 8; \
            cp_async16(base_ + 0     + so_, vh_g + go_); \
            cp_async16(base_ + 17408 + so_, vl_g + go_); \
        } \
    } while (0)

    PF_V(0); CP_COMMIT();
    for (int db = 0; db < 8; db++) {
        float oacc[8][4];
        #pragma unroll
        for (int n = 0; n < 8; n++)
            #pragma unroll
            for (int j = 0; j < 4; j++) oacc[n][j] = 0.f;

        for (int c = 0; c < ncv; c++) {
            int it = db * ncv + c;
            if (it + 1 < tot) { PF_V(it + 1); CP_COMMIT(); CP_WAIT1(); }
            else              { CP_WAIT0(); }
            __syncthreads();
            uint32_t vb = sb + PIPE_OFF + (it & 1) * VSTAGE;
            #pragma unroll
            for (int ks = 0; ks < 4; ks++) {
                int kof = c * 64 + ks * 16;
                uint32_t sh4[4], sl4[4];
                uint32_t roA = (uint32_t)((wq * 16 + (lane & 15)) * SPITCH
                                          + (kof + (lane >> 4) * 8) * 2);
                ldsm_x4(sh4, sb + SHI_OFF + roA);
                ldsm_x4(sl4, sb + SLO_OFF + roA);
                uint32_t vh[8][2], vl[8][2];
                #pragma unroll
                for (int p = 0; p < 4; p++) {
                    int dloc = wn * 64 + p * 16;
                    uint32_t roB = (uint32_t)((ks * 16 + (lane & 15)) * VPITCH
                                              + (dloc + (lane >> 4) * 8) * 2);
                    uint32_t r4[4];
                    ldsm_x4_t(r4, vb + 0 + roB);
                    vh[2*p][0] = r4[0]; vh[2*p][1] = r4[1];
                    vh[2*p+1][0] = r4[2]; vh[2*p+1][1] = r4[3];
                    ldsm_x4_t(r4, vb + 17408 + roB);
                    vl[2*p][0] = r4[0]; vl[2*p][1] = r4[1];
                    vl[2*p+1][0] = r4[2]; vl[2*p+1][1] = r4[3];
                }
                #pragma unroll
                for (int n = 0; n < 8; n++) {
                    mma_bf16(oacc[n], sh4, vh[n]);
                    mma_bf16(oacc[n], sh4, vl[n]);
                    mma_bf16(oacc[n], sl4, vh[n]);
                }
            }
            __syncthreads();
        }

        // epilogue: write O d-block as bf16 hi/lo
        int rl0 = wq * 16 + (lane >> 2);
        #pragma unroll
        for (int n = 0; n < 8; n++) {
            int d = db * 128 + wn * 64 + n * 8 + (lane & 3) * 2;
            #pragma unroll
            for (int rr = 0; rr < 2; rr++) {
                int row = i0 + rl0 + rr * 8;
                float a0 = oacc[n][rr*2], a1 = oacc[n][rr*2+1];
                uint32_t h = pack_bf16(a0, a1);
                __nv_bfloat162 hh; *(uint32_t*)&hh = h;
                uint32_t l = pack_bf16(a0 - __bfloat162float(hh.x),
                                       a1 - __bfloat162float(hh.y));
                size_t ad = (size_t)(b * TT + row) * DD + d;
                *(uint32_t*)(g_rhi + ad) = h;
                *(uint32_t*)(g_rlo + ad) = l;
            }
        }
    }
    #undef PF_V
    (void)lr2; (void)lseg2;
}

// ---------------------------------------------------------------------------
extern "C" void kernel_launch(void* const* d_in, const int* in_sizes, int n_in,
                              void* d_out, int out_size)
{
    const float* x  = (const float*)d_in[0];
    const float* Wq = (const float*)d_in[1];
    const float* Wk = (const float*)d_in[2];
    const float* Wv = (const float*)d_in[3];
    const float* Wo = (const float*)d_in[4];
    const float* decay_logit = (const float*)d_in[5];
    const float* out_scale   = (const float*)d_in[6];
    float* out = (float*)d_out;

    __nv_bfloat16 *xhi, *xlo, *whi, *wlo;
    __nv_bfloat16 *qhi, *qlo, *khi, *klo, *vhi, *vlo, *rhi, *rlo;
    cudaGetSymbolAddress((void**)&xhi, g_xhi);
    cudaGetSymbolAddress((void**)&xlo, g_xlo);
    cudaGetSymbolAddress((void**)&whi, g_whi);
    cudaGetSymbolAddress((void**)&wlo, g_wlo);
    cudaGetSymbolAddress((void**)&qhi, g_qhi);
    cudaGetSymbolAddress((void**)&qlo, g_qlo);
    cudaGetSymbolAddress((void**)&khi, g_khi);
    cudaGetSymbolAddress((void**)&klo, g_klo);
    cudaGetSymbolAddress((void**)&vhi, g_vhi);
    cudaGetSymbolAddress((void**)&vlo, g_vlo);
    cudaGetSymbolAddress((void**)&rhi, g_rhi);
    cudaGetSymbolAddress((void**)&rlo, g_rlo);

    int nx4 = M_TOTAL * DD / 4;
    int nw4 = DD * DD / 4;
    split_kernel<<<(nx4 + 255) / 256, 256>>>(x, xhi, xlo, nx4);
    split_kernel<<<(nw4 + 255) / 256, 256>>>(Wq, whi + 0 * (size_t)DD * DD, wlo + 0 * (size_t)DD * DD, nw4);
    split_kernel<<<(nw4 + 255) / 256, 256>>>(Wk, whi + 1 * (size_t)DD * DD, wlo + 1 * (size_t)DD * DD, nw4);
    split_kernel<<<(nw4 + 255) / 256, 256>>>(Wv, whi + 2 * (size_t)DD * DD, wlo + 2 * (size_t)DD * DD, nw4);
    split_kernel<<<(nw4 + 255) / 256, 256>>>(Wo, whi + 3 * (size_t)DD * DD, wlo + 3 * (size_t)DD * DD, nw4);

    cudaFuncSetAttribute(mma_gemm, cudaFuncAttributeMaxDynamicSharedMemorySize, GSMEM);
    cudaFuncSetAttribute(attn_mma, cudaFuncAttributeMaxDynamicSharedMemorySize, ATT_SMEM);

    // QKV projections -> bf16 hi/lo outputs
    mma_gemm<<<dim3(M_TOTAL / 128, DD / 128, 3), 256, GSMEM>>>(
        xhi, xlo, whi, wlo,
        qhi, qlo, khi, klo, vhi, vlo, nullptr, nullptr, 0);

    // windowed decayed attention on tensor cores
    attn_mma<<<dim3(TT / 64, BB), 256, ATT_SMEM>>>(decay_logit);

    // output projection (fp32 out, scaled)
    mma_gemm<<<dim3(M_TOTAL / 128, DD / 128, 1), 256, GSMEM>>>(
        rhi, rlo, whi + 3 * (size_t)DD * DD, wlo + 3 * (size_t)DD * DD,
        nullptr, nullptr, nullptr, nullptr, nullptr, nullptr,
        out, out_scale, 1);
}

// round 6
// speedup vs baseline: 4.5404x; 1.0361x over previous
#include <cuda_runtime.h>
#include <cuda_bf16.h>
#include <math.h>
#include <stdint.h>

#define BB 4
#define TT 4096
#define DD 1024
#define M_TOTAL (BB*TT)

// ------------------------- scratch (device globals) -------------------------
__device__ __nv_bfloat16 g_xhi[M_TOTAL*DD];
__device__ __nv_bfloat16 g_xlo[M_TOTAL*DD];
__device__ __nv_bfloat16 g_whi[4*DD*DD];
__device__ __nv_bfloat16 g_wlo[4*DD*DD];
__device__ __nv_bfloat16 g_qhi[M_TOTAL*DD];
__device__ __nv_bfloat16 g_qlo[M_TOTAL*DD];
__device__ __nv_bfloat16 g_khi[M_TOTAL*DD];
__device__ __nv_bfloat16 g_klo[M_TOTAL*DD];
__device__ __nv_bfloat16 g_vhi[M_TOTAL*DD];
__device__ __nv_bfloat16 g_vlo[M_TOTAL*DD];
__device__ __nv_bfloat16 g_rhi[M_TOTAL*DD];
__device__ __nv_bfloat16 g_rlo[M_TOTAL*DD];

// ------------------------- helpers ------------------------------------------
__device__ __forceinline__ uint32_t smem_to_u32(const void* p) {
    uint32_t a;
    asm("{ .reg .u64 t; cvta.to.shared.u64 t, %1; cvt.u32.u64 %0, t; }" : "=r"(a) : "l"(p));
    return a;
}
__device__ __forceinline__ void cp_async16(uint32_t saddr, const void* g) {
    asm volatile("cp.async.cg.shared.global [%0], [%1], 16;" :: "r"(saddr), "l"(g));
}
#define CP_COMMIT() asm volatile("cp.async.commit_group;" ::: "memory")
#define CP_WAIT2()  asm volatile("cp.async.wait_group 2;" ::: "memory")
#define CP_WAIT1()  asm volatile("cp.async.wait_group 1;" ::: "memory")
#define CP_WAIT0()  asm volatile("cp.async.wait_group 0;" ::: "memory")

__device__ __forceinline__ void ldsm_x4(uint32_t* r, uint32_t addr) {
    asm volatile("ldmatrix.sync.aligned.m8n8.x4.shared.b16 {%0,%1,%2,%3}, [%4];"
        : "=r"(r[0]), "=r"(r[1]), "=r"(r[2]), "=r"(r[3]) : "r"(addr));
}
__device__ __forceinline__ void ldsm_x4_t(uint32_t* r, uint32_t addr) {
    asm volatile("ldmatrix.sync.aligned.m8n8.x4.trans.shared.b16 {%0,%1,%2,%3}, [%4];"
        : "=r"(r[0]), "=r"(r[1]), "=r"(r[2]), "=r"(r[3]) : "r"(addr));
}
__device__ __forceinline__ void mma_bf16(float* d, const uint32_t* a, const uint32_t* b) {
    asm volatile("mma.sync.aligned.m16n8k16.row.col.f32.bf16.bf16.f32 "
        "{%0,%1,%2,%3}, {%4,%5,%6,%7}, {%8,%9}, {%0,%1,%2,%3};"
        : "+f"(d[0]), "+f"(d[1]), "+f"(d[2]), "+f"(d[3])
        : "r"(a[0]), "r"(a[1]), "r"(a[2]), "r"(a[3]), "r"(b[0]), "r"(b[1]));
}
__device__ __forceinline__ uint32_t pack_bf16(float a, float b) {
    __nv_bfloat162 h = __floats2bfloat162_rn(a, b);
    return *(uint32_t*)&h;
}

// ------------------------- split conversion ---------------------------------
__device__ __forceinline__ void split4(const float* __restrict__ src,
    __nv_bfloat16* __restrict__ hi, __nv_bfloat16* __restrict__ lo, int i)
{
    float4 v = ((const float4*)src)[i];
    __nv_bfloat16 h0 = __float2bfloat16(v.x);
    __nv_bfloat16 h1 = __float2bfloat16(v.y);
    __nv_bfloat16 h2 = __float2bfloat16(v.z);
    __nv_bfloat16 h3 = __float2bfloat16(v.w);
    __nv_bfloat16 l0 = __float2bfloat16(v.x - __bfloat162float(h0));
    __nv_bfloat16 l1 = __float2bfloat16(v.y - __bfloat162float(h1));
    __nv_bfloat16 l2 = __float2bfloat16(v.z - __bfloat162float(h2));
    __nv_bfloat16 l3 = __float2bfloat16(v.w - __bfloat162float(h3));
    __nv_bfloat162 H0; H0.x = h0; H0.y = h1;
    __nv_bfloat162 H1; H1.x = h2; H1.y = h3;
    __nv_bfloat162 L0; L0.x = l0; L0.y = l1;
    __nv_bfloat162 L1; L1.x = l2; L1.y = l3;
    ((__nv_bfloat162*)hi)[2*i]   = H0;
    ((__nv_bfloat162*)hi)[2*i+1] = H1;
    ((__nv_bfloat162*)lo)[2*i]   = L0;
    ((__nv_bfloat162*)lo)[2*i+1] = L1;
}

__global__ __launch_bounds__(256) void split_x(
    const float* __restrict__ src, __nv_bfloat16* __restrict__ hi,
    __nv_bfloat16* __restrict__ lo, int n4)
{
    int i = blockIdx.x * 256 + threadIdx.x;
    if (i >= n4) return;
    split4(src, hi, lo, i);
}

__global__ __launch_bounds__(256) void split_w4(
    const float* __restrict__ s0, const float* __restrict__ s1,
    const float* __restrict__ s2, const float* __restrict__ s3,
    __nv_bfloat16* __restrict__ hi, __nv_bfloat16* __restrict__ lo, int n4)
{
    int i = blockIdx.x * 256 + threadIdx.x;
    if (i >= n4) return;
    int z = blockIdx.y;
    const float* src = (z == 0) ? s0 : ((z == 1) ? s1 : ((z == 2) ? s2 : s3));
    split4(src, hi + (size_t)z * DD * DD, lo + (size_t)z * DD * DD, i);
}

// ------------------------- HMMA GEMM (3-stage pipeline) ----------------------
#define PITCH   40
#define TILEB   (128*PITCH*2)      // 10240 B per operand tile
#define STAGEB  (4*TILEB)          // 40960
#define GSMEM   (3*STAGEB)         // 122880

__global__ __launch_bounds__(256, 1) void mma_gemm(
    const __nv_bfloat16* __restrict__ Ahi, const __nv_bfloat16* __restrict__ Alo,
    const __nv_bfloat16* __restrict__ Whi, const __nv_bfloat16* __restrict__ Wlo,
    __nv_bfloat16* __restrict__ H0, __nv_bfloat16* __restrict__ L0,
    __nv_bfloat16* __restrict__ H1, __nv_bfloat16* __restrict__ L1,
    __nv_bfloat16* __restrict__ H2, __nv_bfloat16* __restrict__ L2,
    float* __restrict__ Cf, const float* __restrict__ scale_ptr, int mode)
{
    extern __shared__ char smc[];
    uint32_t sb = smem_to_u32(smc);
    int t = threadIdx.x, lane = t & 31, w = t >> 5;
    int wm = w & 3, wn = w >> 2;
    int m0 = blockIdx.x * 128, n0 = blockIdx.y * 128, z = blockIdx.z;

    const __nv_bfloat16* Wh = Whi + (size_t)z * DD * DD;
    const __nv_bfloat16* Wl = Wlo + (size_t)z * DD * DD;

    const __nv_bfloat16* aH = Ahi + (size_t)m0 * DD;
    const __nv_bfloat16* aL = Alo + (size_t)m0 * DD;
    const __nv_bfloat16* bH = Wh + (size_t)n0 * DD;
    const __nv_bfloat16* bL = Wl + (size_t)n0 * DD;

    float acc[2][8][4];
    #pragma unroll
    for (int i = 0; i < 2; i++)
        #pragma unroll
        for (int n = 0; n < 8; n++)
            #pragma unroll
            for (int j = 0; j < 4; j++) acc[i][n][j] = 0.f;

    #define PREFETCH(c) do { \
        uint32_t base_ = sb + ((c) % 3) * STAGEB; \
        int k0_ = (c) * 32; \
        _Pragma("unroll") \
        for (int i_ = 0; i_ < 2; i_++) { \
            int idx_ = t + 256 * i_; \
            int r_ = idx_ >> 2, c_ = idx_ & 3; \
            uint32_t so_ = (uint32_t)(r_ * 80 + c_ * 16); \
            size_t go_ = (size_t)r_ * DD + k0_ + c_ * 8; \
            cp_async16(base_ + 0 * TILEB + so_, aH + go_); \
            cp_async16(base_ + 1 * TILEB + so_, aL + go_); \
            cp_async16(base_ + 2 * TILEB + so_, bH + go_); \
            cp_async16(base_ + 3 * TILEB + so_, bL + go_); \
        } \
    } while (0)

    PREFETCH(0); CP_COMMIT();
    PREFETCH(1); CP_COMMIT();

    for (int c = 0; c < 32; c++) {
        if (c + 2 < 32)      { PREFETCH(c + 2); CP_COMMIT(); CP_WAIT2(); }
        else if (c + 1 < 32) { CP_WAIT1(); }
        else                 { CP_WAIT0(); }
        __syncthreads();

        uint32_t base = sb + (c % 3) * STAGEB;
        #pragma unroll
        for (int kk = 0; kk < 2; kk++) {
            uint32_t ah[2][4], al[2][4];
            #pragma unroll
            for (int i = 0; i < 2; i++) {
                uint32_t ro = (uint32_t)((wm * 32 + i * 16 + (lane & 15)) * 80
                                         + kk * 32 + (lane >> 4) * 16);
                ldsm_x4(ah[i], base + 0 * TILEB + ro);
                ldsm_x4(al[i], base + 1 * TILEB + ro);
            }
            uint32_t bh[8][2], bl[8][2];
            #pragma unroll
            for (int p = 0; p < 4; p++) {
                int mid = lane >> 3;
                int nr = wn * 64 + p * 16 + ((mid & 2) << 2) + (lane & 7);
                uint32_t ro = (uint32_t)(nr * 80 + kk * 32 + (mid & 1) * 16);
                uint32_t r4[4];
                ldsm_x4(r4, base + 2 * TILEB + ro);
                bh[2*p][0] = r4[0]; bh[2*p][1] = r4[1];
                bh[2*p+1][0] = r4[2]; bh[2*p+1][1] = r4[3];
                ldsm_x4(r4, base + 3 * TILEB + ro);
                bl[2*p][0] = r4[0]; bl[2*p][1] = r4[1];
                bl[2*p+1][0] = r4[2]; bl[2*p+1][1] = r4[3];
            }
            #pragma unroll
            for (int i = 0; i < 2; i++)
                #pragma unroll
                for (int n = 0; n < 8; n++) {
                    mma_bf16(acc[i][n], ah[i], bh[n]);
                    mma_bf16(acc[i][n], ah[i], bl[n]);
                    mma_bf16(acc[i][n], al[i], bh[n]);
                }
        }
        __syncthreads();
    }
    #undef PREFETCH

    int gid = lane >> 2, tig = lane & 3;
    if (mode == 0) {
        __nv_bfloat16* Hc = (z == 0) ? H0 : ((z == 1) ? H1 : H2);
        __nv_bfloat16* Lc = (z == 0) ? L0 : ((z == 1) ? L1 : L2);
        #pragma unroll
        for (int i = 0; i < 2; i++) {
            int r = m0 + wm * 32 + i * 16 + gid;
            #pragma unroll
            for (int n = 0; n < 8; n++) {
                int col = n0 + wn * 64 + n * 8 + tig * 2;
                float a0 = acc[i][n][0], a1 = acc[i][n][1];
                float a2 = acc[i][n][2], a3 = acc[i][n][3];
                uint32_t h01 = pack_bf16(a0, a1);
                uint32_t h23 = pack_bf16(a2, a3);
                __nv_bfloat162 hh;
                *(uint32_t*)&hh = h01;
                uint32_t l01 = pack_bf16(a0 - __bfloat162float(hh.x), a1 - __bfloat162float(hh.y));
                *(uint32_t*)&hh = h23;
                uint32_t l23 = pack_bf16(a2 - __bfloat162float(hh.x), a3 - __bfloat162float(hh.y));
                *(uint32_t*)(Hc + (size_t)r * DD + col) = h01;
                *(uint32_t*)(Lc + (size_t)r * DD + col) = l01;
                *(uint32_t*)(Hc + (size_t)(r + 8) * DD + col) = h23;
                *(uint32_t*)(Lc + (size_t)(r + 8) * DD + col) = l23;
            }
        }
    } else {
        float sc = *scale_ptr;
        #pragma unroll
        for (int i = 0; i < 2; i++) {
            int r = m0 + wm * 32 + i * 16 + gid;
            #pragma unroll
            for (int n = 0; n < 8; n++) {
                int col = n0 + wn * 64 + n * 8 + tig * 2;
                float2 v0; v0.x = acc[i][n][0] * sc; v0.y = acc[i][n][1] * sc;
                float2 v1; v1.x = acc[i][n][2] * sc; v1.y = acc[i][n][3] * sc;
                *(float2*)(Cf + (size_t)r * DD + col) = v0;
                *(float2*)(Cf + (size_t)(r + 8) * DD + col) = v1;
            }
        }
    }
}

// ------------------------- MMA windowed decayed attention --------------------
// 64 queries/CTA, NCH chunks of 64 keys. Phase A: fused (chunk x dslice) loop,
// 64-col d-slices, 3-stage cp.async pipeline. Phase B: 3-stage over (dblock x chunk).
#define NCH 5
#define SPITCH 688                  // bytes per S row (344 bf16)
#define SHI_OFF 0
#define SLO_OFF 44032               // 64*688
#define PIPE_OFF 88064
#define APITCH 144                  // 64 cols * 2B + 16 pad
#define AOP    9216                 // 64 rows * 144
#define ASTG   (4*AOP)              // qh,ql,kh,kl = 36864
#define VPITCH 272                  // 128 cols * 2B + 16 pad
#define VSTG   34816                // vh,vl each 64*272
#define ATT_SMEM (PIPE_OFF + 3*ASTG)   // 198656 (>= PIPE_OFF + 3*VSTG)

__global__ __launch_bounds__(256, 1) void attn_mma(const float* __restrict__ decay_logit_p)
{
    extern __shared__ char smc[];
    uint32_t sb = smem_to_u32(smc);
    int t = threadIdx.x, lane = t & 31, w = t >> 5;
    int wq = w & 3, wn = w >> 2;
    int b = blockIdx.y, i0 = blockIdx.x * 64;
    int ncv = min(NCH, (TT - i0) / 64);

    float dl = *decay_logit_p;
    float decay = 1.0f / (1.0f + expf(-dl));
    float log2d = log2f(decay);
    const float qk_scale = 0.03125f;

    const __nv_bfloat16* qh_g = g_qhi + (size_t)(b * TT + i0) * DD;
    const __nv_bfloat16* ql_g = g_qlo + (size_t)(b * TT + i0) * DD;
    const __nv_bfloat16* kh_g = g_khi + (size_t)(b * TT) * DD;
    const __nv_bfloat16* kl_g = g_klo + (size_t)(b * TT) * DD;
    const __nv_bfloat16* vh_g = g_vhi + (size_t)(b * TT) * DD;
    const __nv_bfloat16* vl_g = g_vlo + (size_t)(b * TT) * DD;

    int mid = lane >> 3;
    int rl0 = wq * 16 + (lane >> 2);

    // ================= Phase A: scores (fused pipeline) =================
    int totA = ncv * 16;

    #define PF_A(it) do { \
        int c_ = (it) >> 4, ds_ = (it) & 15; \
        int cs_ = i0 + c_ * 64; \
        uint32_t base_ = sb + PIPE_OFF + ((it) % 3) * ASTG; \
        _Pragma("unroll") \
        for (int i_ = 0; i_ < 2; i_++) { \
            int idx_ = t + 256 * i_; \
            int r_ = idx_ >> 3, g_ = idx_ & 7; \
            uint32_t so_ = (uint32_t)(r_ * APITCH + g_ * 16); \
            size_t qo_ = (size_t)r_ * DD + ds_ * 64 + g_ * 8; \
            size_t ko_ = (size_t)(cs_ + r_) * DD + ds_ * 64 + g_ * 8; \
            cp_async16(base_ + 0 * AOP + so_, qh_g + qo_); \
            cp_async16(base_ + 1 * AOP + so_, ql_g + qo_); \
            cp_async16(base_ + 2 * AOP + so_, kh_g + ko_); \
            cp_async16(base_ + 3 * AOP + so_, kl_g + ko_); \
        } \
    } while (0)

    {
        float acc[4][4];
        #pragma unroll
        for (int n = 0; n < 4; n++)
            #pragma unroll
            for (int j = 0; j < 4; j++) acc[n][j] = 0.f;

        PF_A(0); CP_COMMIT();
        PF_A(1); CP_COMMIT();

        for (int it = 0; it < totA; it++) {
            if (it + 2 < totA)      { PF_A(it + 2); CP_COMMIT(); CP_WAIT2(); }
            else if (it + 1 < totA) { CP_WAIT1(); }
            else                    { CP_WAIT0(); }
            __syncthreads();

            uint32_t base = sb + PIPE_OFF + (it % 3) * ASTG;
            #pragma unroll
            for (int kk = 0; kk < 4; kk++) {
                uint32_t qh[4], ql[4];
                uint32_t roA = (uint32_t)((wq * 16 + (lane & 15)) * APITCH
                                          + kk * 32 + (lane >> 4) * 16);
                ldsm_x4(qh, base + 0 * AOP + roA);
                ldsm_x4(ql, base + 1 * AOP + roA);
                uint32_t kh[4][2], kl[4][2];
                #pragma unroll
                for (int p = 0; p < 2; p++) {
                    int nr = wn * 32 + p * 16 + ((mid & 2) << 2) + (lane & 7);
                    uint32_t roB = (uint32_t)(nr * APITCH + kk * 32 + (mid & 1) * 16);
                    uint32_t r4[4];
                    ldsm_x4(r4, base + 2 * AOP + roB);
                    kh[2*p][0] = r4[0]; kh[2*p][1] = r4[1];
                    kh[2*p+1][0] = r4[2]; kh[2*p+1][1] = r4[3];
                    ldsm_x4(r4, base + 3 * AOP + roB);
                    kl[2*p][0] = r4[0]; kl[2*p][1] = r4[1];
                    kl[2*p+1][0] = r4[2]; kl[2*p+1][1] = r4[3];
                }
                #pragma unroll
                for (int n = 0; n < 4; n++) {
                    mma_bf16(acc[n], qh, kh[n]);
                    mma_bf16(acc[n], qh, kl[n]);
                    mma_bf16(acc[n], ql, kh[n]);
                }
            }
            __syncthreads();

            if ((it & 15) == 15) {
                int c = it >> 4;
                // apply decay weights, split to bf16 hi/lo, store to S smem
                #pragma unroll
                for (int n = 0; n < 4; n++) {
                    int jl0 = wn * 32 + n * 8 + (lane & 3) * 2;
                    float s[4];
                    #pragma unroll
                    for (int rr = 0; rr < 2; rr++) {
                        int rl = rl0 + rr * 8;
                        #pragma unroll
                        for (int jj = 0; jj < 2; jj++) {
                            int diff = c * 64 + jl0 + jj - rl;
                            float wt = 0.f;
                            if (diff > 0) wt = qk_scale * exp2f((float)(diff - 1) * log2d);
                            s[rr * 2 + jj] = acc[n][rr * 2 + jj] * wt;
                        }
                    }
                    uint32_t jbyte = (uint32_t)((c * 64 + jl0) * 2);
                    #pragma unroll
                    for (int rr = 0; rr < 2; rr++) {
                        int rl = rl0 + rr * 8;
                        uint32_t h = pack_bf16(s[rr*2], s[rr*2+1]);
                        __nv_bfloat162 hh; *(uint32_t*)&hh = h;
                        uint32_t l = pack_bf16(s[rr*2] - __bfloat162float(hh.x),
                                               s[rr*2+1] - __bfloat162float(hh.y));
                        uint32_t ad = (uint32_t)(rl * SPITCH) + jbyte;
                        *(uint32_t*)(smc + SHI_OFF + ad) = h;
                        *(uint32_t*)(smc + SLO_OFF + ad) = l;
                    }
                    #pragma unroll
                    for (int j = 0; j < 4; j++) acc[n][j] = 0.f;
                }
            }
        }
    }
    #undef PF_A
    __syncthreads();

    // ================= Phase B: O = S V (3-stage) =================
    int totB = 8 * ncv;

    #define PF_V(it) do { \
        int db_ = (it) / ncv, c_ = (it) % ncv; \
        int cs_ = i0 + c_ * 64; \
        uint32_t base_ = sb + PIPE_OFF + ((it) % 3) * VSTG; \
        _Pragma("unroll") \
        for (int i_ = 0; i_ < 4; i_++) { \
            int idx_ = t + 256 * i_; \
            int r_ = idx_ >> 4, g_ = idx_ & 15; \
            uint32_t so_ = (uint32_t)(r_ * VPITCH + g_ * 16); \
            size_t go_ = (size_t)(cs_ + r_) * DD + db_ * 128 + g_ * 8; \
            cp_async16(base_ + 0     + so_, vh_g + go_); \
            cp_async16(base_ + 17408 + so_, vl_g + go_); \
        } \
    } while (0)

    PF_V(0); CP_COMMIT();
    PF_V(1); CP_COMMIT();

    for (int db = 0; db < 8; db++) {
        float oacc[8][4];
        #pragma unroll
        for (int n = 0; n < 8; n++)
            #pragma unroll
            for (int j = 0; j < 4; j++) oacc[n][j] = 0.f;

        for (int c = 0; c < ncv; c++) {
            int it = db * ncv + c;
            if (it + 2 < totB)      { PF_V(it + 2); CP_COMMIT(); CP_WAIT2(); }
            else if (it + 1 < totB) { CP_WAIT1(); }
            else                    { CP_WAIT0(); }
            __syncthreads();

            uint32_t vb = sb + PIPE_OFF + (it % 3) * VSTG;
            #pragma unroll
            for (int ks = 0; ks < 4; ks++) {
                int kof = c * 64 + ks * 16;
                uint32_t sh4[4], sl4[4];
                uint32_t roA = (uint32_t)((wq * 16 + (lane & 15)) * SPITCH
                                          + (kof + (lane >> 4) * 8) * 2);
                ldsm_x4(sh4, sb + SHI_OFF + roA);
                ldsm_x4(sl4, sb + SLO_OFF + roA);
                uint32_t vh[8][2], vl[8][2];
                #pragma unroll
                for (int p = 0; p < 4; p++) {
                    int dloc = wn * 64 + p * 16;
                    uint32_t roB = (uint32_t)((ks * 16 + (lane & 15)) * VPITCH
                                              + (dloc + (lane >> 4) * 8) * 2);
                    uint32_t r4[4];
                    ldsm_x4_t(r4, vb + 0 + roB);
                    vh[2*p][0] = r4[0]; vh[2*p][1] = r4[1];
                    vh[2*p+1][0] = r4[2]; vh[2*p+1][1] = r4[3];
                    ldsm_x4_t(r4, vb + 17408 + roB);
                    vl[2*p][0] = r4[0]; vl[2*p][1] = r4[1];
                    vl[2*p+1][0] = r4[2]; vl[2*p+1][1] = r4[3];
                }
                #pragma unroll
                for (int n = 0; n < 8; n++) {
                    mma_bf16(oacc[n], sh4, vh[n]);
                    mma_bf16(oacc[n], sh4, vl[n]);
                    mma_bf16(oacc[n], sl4, vh[n]);
                }
            }
            __syncthreads();
        }

        // epilogue: write O d-block as bf16 hi/lo
        #pragma unroll
        for (int n = 0; n < 8; n++) {
            int d = db * 128 + wn * 64 + n * 8 + (lane & 3) * 2;
            #pragma unroll
            for (int rr = 0; rr < 2; rr++) {
                int row = i0 + rl0 + rr * 8;
                float a0 = oacc[n][rr*2], a1 = oacc[n][rr*2+1];
                uint32_t h = pack_bf16(a0, a1);
                __nv_bfloat162 hh; *(uint32_t*)&hh = h;
                uint32_t l = pack_bf16(a0 - __bfloat162float(hh.x),
                                       a1 - __bfloat162float(hh.y));
                size_t ad = (size_t)(b * TT + row) * DD + d;
                *(uint32_t*)(g_rhi + ad) = h;
                *(uint32_t*)(g_rlo + ad) = l;
            }
        }
    }
    #undef PF_V
}

// ---------------------------------------------------------------------------
extern "C" void kernel_launch(void* const* d_in, const int* in_sizes, int n_in,
                              void* d_out, int out_size)
{
    const float* x  = (const float*)d_in[0];
    const float* Wq = (const float*)d_in[1];
    const float* Wk = (const float*)d_in[2];
    const float* Wv = (const float*)d_in[3];
    const float* Wo = (const float*)d_in[4];
    const float* decay_logit = (const float*)d_in[5];
    const float* out_scale   = (const float*)d_in[6];
    float* out = (float*)d_out;

    __nv_bfloat16 *xhi, *xlo, *whi, *wlo;
    __nv_bfloat16 *qhi, *qlo, *khi, *klo, *vhi, *vlo, *rhi, *rlo;
    cudaGetSymbolAddress((void**)&xhi, g_xhi);
    cudaGetSymbolAddress((void**)&xlo, g_xlo);
    cudaGetSymbolAddress((void**)&whi, g_whi);
    cudaGetSymbolAddress((void**)&wlo, g_wlo);
    cudaGetSymbolAddress((void**)&qhi, g_qhi);
    cudaGetSymbolAddress((void**)&qlo, g_qlo);
    cudaGetSymbolAddress((void**)&khi, g_khi);
    cudaGetSymbolAddress((void**)&klo, g_klo);
    cudaGetSymbolAddress((void**)&vhi, g_vhi);
    cudaGetSymbolAddress((void**)&vlo, g_vlo);
    cudaGetSymbolAddress((void**)&rhi, g_rhi);
    cudaGetSymbolAddress((void**)&rlo, g_rlo);

    int nx4 = M_TOTAL * DD / 4;
    int nw4 = DD * DD / 4;
    split_x<<<(nx4 + 255) / 256, 256>>>(x, xhi, xlo, nx4);
    split_w4<<<dim3((nw4 + 255) / 256, 4), 256>>>(Wq, Wk, Wv, Wo, whi, wlo, nw4);

    cudaFuncSetAttribute(mma_gemm, cudaFuncAttributeMaxDynamicSharedMemorySize, GSMEM);
    cudaFuncSetAttribute(attn_mma, cudaFuncAttributeMaxDynamicSharedMemorySize, ATT_SMEM);

    // QKV projections -> bf16 hi/lo outputs
    mma_gemm<<<dim3(M_TOTAL / 128, DD / 128, 3), 256, GSMEM>>>(
        xhi, xlo, whi, wlo,
        qhi, qlo, khi, klo, vhi, vlo, nullptr, nullptr, 0);

    // windowed decayed attention on tensor cores
    attn_mma<<<dim3(TT / 64, BB), 256, ATT_SMEM>>>(decay_logit);

    // output projection (fp32 out, scaled)
    mma_gemm<<<dim3(M_TOTAL / 128, DD / 128, 1), 256, GSMEM>>>(
        rhi, rlo, whi + 3 * (size_t)DD * DD, wlo + 3 * (size_t)DD * DD,
        nullptr, nullptr, nullptr, nullptr, nullptr, nullptr,
        out, out_scale, 1);
}

// round 7
// speedup vs baseline: 4.6335x; 1.0205x over previous
#include <cuda_runtime.h>
#include <cuda_bf16.h>
#include <math.h>
#include <stdint.h>

#define BB 4
#define TT 4096
#define DD 1024
#define M_TOTAL (BB*TT)

// ------------------------- scratch (device globals) -------------------------
__device__ __nv_bfloat16 g_xhi[M_TOTAL*DD];
__device__ __nv_bfloat16 g_xlo[M_TOTAL*DD];
__device__ __nv_bfloat16 g_whi[4*DD*DD];
__device__ __nv_bfloat16 g_wlo[4*DD*DD];
__device__ __nv_bfloat16 g_qhi[M_TOTAL*DD];
__device__ __nv_bfloat16 g_qlo[M_TOTAL*DD];
__device__ __nv_bfloat16 g_khi[M_TOTAL*DD];
__device__ __nv_bfloat16 g_klo[M_TOTAL*DD];
__device__ __nv_bfloat16 g_vhi[M_TOTAL*DD];
__device__ __nv_bfloat16 g_vlo[M_TOTAL*DD];
__device__ __nv_bfloat16 g_rhi[M_TOTAL*DD];
__device__ __nv_bfloat16 g_rlo[M_TOTAL*DD];

// ------------------------- helpers ------------------------------------------
__device__ __forceinline__ uint32_t smem_to_u32(const void* p) {
    uint32_t a;
    asm("{ .reg .u64 t; cvta.to.shared.u64 t, %1; cvt.u32.u64 %0, t; }" : "=r"(a) : "l"(p));
    return a;
}
__device__ __forceinline__ void cp_async16(uint32_t saddr, const void* g) {
    asm volatile("cp.async.cg.shared.global [%0], [%1], 16;" :: "r"(saddr), "l"(g));
}
#define CP_COMMIT() asm volatile("cp.async.commit_group;" ::: "memory")
#define CP_WAIT2()  asm volatile("cp.async.wait_group 2;" ::: "memory")
#define CP_WAIT1()  asm volatile("cp.async.wait_group 1;" ::: "memory")
#define CP_WAIT0()  asm volatile("cp.async.wait_group 0;" ::: "memory")

__device__ __forceinline__ void ldsm_x4(uint32_t* r, uint32_t addr) {
    asm volatile("ldmatrix.sync.aligned.m8n8.x4.shared.b16 {%0,%1,%2,%3}, [%4];"
        : "=r"(r[0]), "=r"(r[1]), "=r"(r[2]), "=r"(r[3]) : "r"(addr));
}
__device__ __forceinline__ void ldsm_x4_t(uint32_t* r, uint32_t addr) {
    asm volatile("ldmatrix.sync.aligned.m8n8.x4.trans.shared.b16 {%0,%1,%2,%3}, [%4];"
        : "=r"(r[0]), "=r"(r[1]), "=r"(r[2]), "=r"(r[3]) : "r"(addr));
}
__device__ __forceinline__ void mma_bf16(float* d, const uint32_t* a, const uint32_t* b) {
    asm volatile("mma.sync.aligned.m16n8k16.row.col.f32.bf16.bf16.f32 "
        "{%0,%1,%2,%3}, {%4,%5,%6,%7}, {%8,%9}, {%0,%1,%2,%3};"
        : "+f"(d[0]), "+f"(d[1]), "+f"(d[2]), "+f"(d[3])
        : "r"(a[0]), "r"(a[1]), "r"(a[2]), "r"(a[3]), "r"(b[0]), "r"(b[1]));
}
__device__ __forceinline__ uint32_t pack_bf16(float a, float b) {
    __nv_bfloat162 h = __floats2bfloat162_rn(a, b);
    return *(uint32_t*)&h;
}

// ------------------------- split conversion ---------------------------------
__device__ __forceinline__ void split4(const float* __restrict__ src,
    __nv_bfloat16* __restrict__ hi, __nv_bfloat16* __restrict__ lo, int i)
{
    float4 v = ((const float4*)src)[i];
    __nv_bfloat16 h0 = __float2bfloat16(v.x);
    __nv_bfloat16 h1 = __float2bfloat16(v.y);
    __nv_bfloat16 h2 = __float2bfloat16(v.z);
    __nv_bfloat16 h3 = __float2bfloat16(v.w);
    __nv_bfloat16 l0 = __float2bfloat16(v.x - __bfloat162float(h0));
    __nv_bfloat16 l1 = __float2bfloat16(v.y - __bfloat162float(h1));
    __nv_bfloat16 l2 = __float2bfloat16(v.z - __bfloat162float(h2));
    __nv_bfloat16 l3 = __float2bfloat16(v.w - __bfloat162float(h3));
    __nv_bfloat162 H0; H0.x = h0; H0.y = h1;
    __nv_bfloat162 H1; H1.x = h2; H1.y = h3;
    __nv_bfloat162 L0; L0.x = l0; L0.y = l1;
    __nv_bfloat162 L1; L1.x = l2; L1.y = l3;
    ((__nv_bfloat162*)hi)[2*i]   = H0;
    ((__nv_bfloat162*)hi)[2*i+1] = H1;
    ((__nv_bfloat162*)lo)[2*i]   = L0;
    ((__nv_bfloat162*)lo)[2*i+1] = L1;
}

__global__ __launch_bounds__(256) void split_x(
    const float* __restrict__ src, __nv_bfloat16* __restrict__ hi,
    __nv_bfloat16* __restrict__ lo, int n4)
{
    int i = blockIdx.x * 256 + threadIdx.x;
    if (i >= n4) return;
    split4(src, hi, lo, i);
}

__global__ __launch_bounds__(256) void split_w4(
    const float* __restrict__ s0, const float* __restrict__ s1,
    const float* __restrict__ s2, const float* __restrict__ s3,
    __nv_bfloat16* __restrict__ hi, __nv_bfloat16* __restrict__ lo, int n4)
{
    int i = blockIdx.x * 256 + threadIdx.x;
    if (i >= n4) return;
    int z = blockIdx.y;
    const float* src = (z == 0) ? s0 : ((z == 1) ? s1 : ((z == 2) ? s2 : s3));
    split4(src, hi + (size_t)z * DD * DD, lo + (size_t)z * DD * DD, i);
}

// ------------------------- HMMA GEMM (256x128 tile, 512 threads) -------------
// 16 warps: 8 in M (32 rows each) x 2 in N (64 cols each). BK=32, 2-stage.
#define AHI_O 0
#define ALO_O 20480
#define BHI_O 40960
#define BLO_O 51200
#define STAGEB 61440
#define GSMEM  (2*STAGEB)          // 122880

__global__ __launch_bounds__(512, 1) void mma_gemm(
    const __nv_bfloat16* __restrict__ Ahi, const __nv_bfloat16* __restrict__ Alo,
    const __nv_bfloat16* __restrict__ Whi, const __nv_bfloat16* __restrict__ Wlo,
    __nv_bfloat16* __restrict__ H0, __nv_bfloat16* __restrict__ L0,
    __nv_bfloat16* __restrict__ H1, __nv_bfloat16* __restrict__ L1,
    __nv_bfloat16* __restrict__ H2, __nv_bfloat16* __restrict__ L2,
    float* __restrict__ Cf, const float* __restrict__ scale_ptr, int mode)
{
    extern __shared__ char smc[];
    uint32_t sb = smem_to_u32(smc);
    int t = threadIdx.x, lane = t & 31, w = t >> 5;
    int wm = w & 7, wn = w >> 3;
    int m0 = blockIdx.x * 256, n0 = blockIdx.y * 128, z = blockIdx.z;

    const __nv_bfloat16* Wh = Whi + (size_t)z * DD * DD;
    const __nv_bfloat16* Wl = Wlo + (size_t)z * DD * DD;

    const __nv_bfloat16* aH = Ahi + (size_t)m0 * DD;
    const __nv_bfloat16* aL = Alo + (size_t)m0 * DD;
    const __nv_bfloat16* bH = Wh + (size_t)n0 * DD;
    const __nv_bfloat16* bL = Wl + (size_t)n0 * DD;

    float acc[2][8][4];
    #pragma unroll
    for (int i = 0; i < 2; i++)
        #pragma unroll
        for (int n = 0; n < 8; n++)
            #pragma unroll
            for (int j = 0; j < 4; j++) acc[i][n][j] = 0.f;

    int lrA = t >> 2, lsA = t & 3;              // A: rows 0..255 (x2 iters)
    uint32_t soA = (uint32_t)(lrA * 80 + lsA * 16);
    size_t goA = (size_t)lrA * DD + lsA * 8;

    #define PREFETCH(c) do { \
        uint32_t base_ = sb + ((c) & 1) * STAGEB; \
        int k0_ = (c) * 32; \
        cp_async16(base_ + AHI_O + soA, aH + goA + k0_); \
        cp_async16(base_ + ALO_O + soA, aL + goA + k0_); \
        cp_async16(base_ + AHI_O + soA + 10240, aH + goA + k0_ + (size_t)128 * DD); \
        cp_async16(base_ + ALO_O + soA + 10240, aL + goA + k0_ + (size_t)128 * DD); \
        cp_async16(base_ + BHI_O + soA, bH + goA + k0_); \
        cp_async16(base_ + BLO_O + soA, bL + goA + k0_); \
    } while (0)

    PREFETCH(0); CP_COMMIT();

    for (int c = 0; c < 32; c++) {
        if (c + 1 < 32) { PREFETCH(c + 1); CP_COMMIT(); CP_WAIT1(); }
        else            { CP_WAIT0(); }
        __syncthreads();

        uint32_t base = sb + (c & 1) * STAGEB;
        #pragma unroll
        for (int kk = 0; kk < 2; kk++) {
            uint32_t ah[2][4], al[2][4];
            #pragma unroll
            for (int i = 0; i < 2; i++) {
                uint32_t ro = (uint32_t)((wm * 32 + i * 16 + (lane & 15)) * 80
                                         + kk * 32 + (lane >> 4) * 16);
                ldsm_x4(ah[i], base + AHI_O + ro);
                ldsm_x4(al[i], base + ALO_O + ro);
            }
            uint32_t bh[8][2], bl[8][2];
            #pragma unroll
            for (int p = 0; p < 4; p++) {
                int mid = lane >> 3;
                int nr = wn * 64 + p * 16 + ((mid & 2) << 2) + (lane & 7);
                uint32_t ro = (uint32_t)(nr * 80 + kk * 32 + (mid & 1) * 16);
                uint32_t r4[4];
                ldsm_x4(r4, base + BHI_O + ro);
                bh[2*p][0] = r4[0]; bh[2*p][1] = r4[1];
                bh[2*p+1][0] = r4[2]; bh[2*p+1][1] = r4[3];
                ldsm_x4(r4, base + BLO_O + ro);
                bl[2*p][0] = r4[0]; bl[2*p][1] = r4[1];
                bl[2*p+1][0] = r4[2]; bl[2*p+1][1] = r4[3];
            }
            #pragma unroll
            for (int i = 0; i < 2; i++)
                #pragma unroll
                for (int n = 0; n < 8; n++) {
                    mma_bf16(acc[i][n], ah[i], bh[n]);
                    mma_bf16(acc[i][n], ah[i], bl[n]);
                    mma_bf16(acc[i][n], al[i], bh[n]);
                }
        }
        __syncthreads();
    }
    #undef PREFETCH

    int gid = lane >> 2, tig = lane & 3;
    if (mode == 0) {
        __nv_bfloat16* Hc = (z == 0) ? H0 : ((z == 1) ? H1 : H2);
        __nv_bfloat16* Lc = (z == 0) ? L0 : ((z == 1) ? L1 : L2);
        #pragma unroll
        for (int i = 0; i < 2; i++) {
            int r = m0 + wm * 32 + i * 16 + gid;
            #pragma unroll
            for (int n = 0; n < 8; n++) {
                int col = n0 + wn * 64 + n * 8 + tig * 2;
                float a0 = acc[i][n][0], a1 = acc[i][n][1];
                float a2 = acc[i][n][2], a3 = acc[i][n][3];
                uint32_t h01 = pack_bf16(a0, a1);
                uint32_t h23 = pack_bf16(a2, a3);
                __nv_bfloat162 hh;
                *(uint32_t*)&hh = h01;
                uint32_t l01 = pack_bf16(a0 - __bfloat162float(hh.x), a1 - __bfloat162float(hh.y));
                *(uint32_t*)&hh = h23;
                uint32_t l23 = pack_bf16(a2 - __bfloat162float(hh.x), a3 - __bfloat162float(hh.y));
                *(uint32_t*)(Hc + (size_t)r * DD + col) = h01;
                *(uint32_t*)(Lc + (size_t)r * DD + col) = l01;
                *(uint32_t*)(Hc + (size_t)(r + 8) * DD + col) = h23;
                *(uint32_t*)(Lc + (size_t)(r + 8) * DD + col) = l23;
            }
        }
    } else {
        float sc = *scale_ptr;
        #pragma unroll
        for (int i = 0; i < 2; i++) {
            int r = m0 + wm * 32 + i * 16 + gid;
            #pragma unroll
            for (int n = 0; n < 8; n++) {
                int col = n0 + wn * 64 + n * 8 + tig * 2;
                float2 v0; v0.x = acc[i][n][0] * sc; v0.y = acc[i][n][1] * sc;
                float2 v1; v1.x = acc[i][n][2] * sc; v1.y = acc[i][n][3] * sc;
                *(float2*)(Cf + (size_t)r * DD + col) = v0;
                *(float2*)(Cf + (size_t)(r + 8) * DD + col) = v1;
            }
        }
    }
}

// ------------------------- MMA windowed decayed attention --------------------
#define NCH 5
#define SPITCH 688
#define SHI_OFF 0
#define SLO_OFF 44032
#define PIPE_OFF 88064
#define APITCH 144
#define AOP    9216
#define ASTG   (4*AOP)
#define VPITCH 272
#define VSTG   34816
#define ATT_SMEM (PIPE_OFF + 3*ASTG)

__global__ __launch_bounds__(256, 1) void attn_mma(const float* __restrict__ decay_logit_p)
{
    extern __shared__ char smc[];
    uint32_t sb = smem_to_u32(smc);
    int t = threadIdx.x, lane = t & 31, w = t >> 5;
    int wq = w & 3, wn = w >> 2;
    int b = blockIdx.y, i0 = blockIdx.x * 64;
    int ncv = min(NCH, (TT - i0) / 64);

    float dl = *decay_logit_p;
    float decay = 1.0f / (1.0f + expf(-dl));
    float log2d = log2f(decay);
    const float qk_scale = 0.03125f;

    const __nv_bfloat16* qh_g = g_qhi + (size_t)(b * TT + i0) * DD;
    const __nv_bfloat16* ql_g = g_qlo + (size_t)(b * TT + i0) * DD;
    const __nv_bfloat16* kh_g = g_khi + (size_t)(b * TT) * DD;
    const __nv_bfloat16* kl_g = g_klo + (size_t)(b * TT) * DD;
    const __nv_bfloat16* vh_g = g_vhi + (size_t)(b * TT) * DD;
    const __nv_bfloat16* vl_g = g_vlo + (size_t)(b * TT) * DD;

    int mid = lane >> 3;
    int rl0 = wq * 16 + (lane >> 2);

    int totA = ncv * 16;

    #define PF_A(it) do { \
        int c_ = (it) >> 4, ds_ = (it) & 15; \
        int cs_ = i0 + c_ * 64; \
        uint32_t base_ = sb + PIPE_OFF + ((it) % 3) * ASTG; \
        _Pragma("unroll") \
        for (int i_ = 0; i_ < 2; i_++) { \
            int idx_ = t + 256 * i_; \
            int r_ = idx_ >> 3, g_ = idx_ & 7; \
            uint32_t so_ = (uint32_t)(r_ * APITCH + g_ * 16); \
            size_t qo_ = (size_t)r_ * DD + ds_ * 64 + g_ * 8; \
            size_t ko_ = (size_t)(cs_ + r_) * DD + ds_ * 64 + g_ * 8; \
            cp_async16(base_ + 0 * AOP + so_, qh_g + qo_); \
            cp_async16(base_ + 1 * AOP + so_, ql_g + qo_); \
            cp_async16(base_ + 2 * AOP + so_, kh_g + ko_); \
            cp_async16(base_ + 3 * AOP + so_, kl_g + ko_); \
        } \
    } while (0)

    {
        float acc[4][4];
        #pragma unroll
        for (int n = 0; n < 4; n++)
            #pragma unroll
            for (int j = 0; j < 4; j++) acc[n][j] = 0.f;

        PF_A(0); CP_COMMIT();
        PF_A(1); CP_COMMIT();

        for (int it = 0; it < totA; it++) {
            if (it + 2 < totA)      { PF_A(it + 2); CP_COMMIT(); CP_WAIT2(); }
            else if (it + 1 < totA) { CP_WAIT1(); }
            else                    { CP_WAIT0(); }
            __syncthreads();

            uint32_t base = sb + PIPE_OFF + (it % 3) * ASTG;
            #pragma unroll
            for (int kk = 0; kk < 4; kk++) {
                uint32_t qh[4], ql[4];
                uint32_t roA = (uint32_t)((wq * 16 + (lane & 15)) * APITCH
                                          + kk * 32 + (lane >> 4) * 16);
                ldsm_x4(qh, base + 0 * AOP + roA);
                ldsm_x4(ql, base + 1 * AOP + roA);
                uint32_t kh[4][2], kl[4][2];
                #pragma unroll
                for (int p = 0; p < 2; p++) {
                    int nr = wn * 32 + p * 16 + ((mid & 2) << 2) + (lane & 7);
                    uint32_t roB = (uint32_t)(nr * APITCH + kk * 32 + (mid & 1) * 16);
                    uint32_t r4[4];
                    ldsm_x4(r4, base + 2 * AOP + roB);
                    kh[2*p][0] = r4[0]; kh[2*p][1] = r4[1];
                    kh[2*p+1][0] = r4[2]; kh[2*p+1][1] = r4[3];
                    ldsm_x4(r4, base + 3 * AOP + roB);
                    kl[2*p][0] = r4[0]; kl[2*p][1] = r4[1];
                    kl[2*p+1][0] = r4[2]; kl[2*p+1][1] = r4[3];
                }
                #pragma unroll
                for (int n = 0; n < 4; n++) {
                    mma_bf16(acc[n], qh, kh[n]);
                    mma_bf16(acc[n], qh, kl[n]);
                    mma_bf16(acc[n], ql, kh[n]);
                }
            }
            __syncthreads();

            if ((it & 15) == 15) {
                int c = it >> 4;
                #pragma unroll
                for (int n = 0; n < 4; n++) {
                    int jl0 = wn * 32 + n * 8 + (lane & 3) * 2;
                    float s[4];
                    #pragma unroll
                    for (int rr = 0; rr < 2; rr++) {
                        int rl = rl0 + rr * 8;
                        #pragma unroll
                        for (int jj = 0; jj < 2; jj++) {
                            int diff = c * 64 + jl0 + jj - rl;
                            float wt = 0.f;
                            if (diff > 0) wt = qk_scale * exp2f((float)(diff - 1) * log2d);
                            s[rr * 2 + jj] = acc[n][rr * 2 + jj] * wt;
                        }
                    }
                    uint32_t jbyte = (uint32_t)((c * 64 + jl0) * 2);
                    #pragma unroll
                    for (int rr = 0; rr < 2; rr++) {
                        int rl = rl0 + rr * 8;
                        uint32_t h = pack_bf16(s[rr*2], s[rr*2+1]);
                        __nv_bfloat162 hh; *(uint32_t*)&hh = h;
                        uint32_t l = pack_bf16(s[rr*2] - __bfloat162float(hh.x),
                                               s[rr*2+1] - __bfloat162float(hh.y));
                        uint32_t ad = (uint32_t)(rl * SPITCH) + jbyte;
                        *(uint32_t*)(smc + SHI_OFF + ad) = h;
                        *(uint32_t*)(smc + SLO_OFF + ad) = l;
                    }
                    #pragma unroll
                    for (int j = 0; j < 4; j++) acc[n][j] = 0.f;
                }
            }
        }
    }
    #undef PF_A
    __syncthreads();

    int totB = 8 * ncv;

    #define PF_V(it) do { \
        int db_ = (it) / ncv, c_ = (it) % ncv; \
        int cs_ = i0 + c_ * 64; \
        uint32_t base_ = sb + PIPE_OFF + ((it) % 3) * VSTG; \
        _Pragma("unroll") \
        for (int i_ = 0; i_ < 4; i_++) { \
            int idx_ = t + 256 * i_; \
            int r_ = idx_ >> 4, g_ = idx_ & 15; \
            uint32_t so_ = (uint32_t)(r_ * VPITCH + g_ * 16); \
            size_t go_ = (size_t)(cs_ + r_) * DD + db_ * 128 + g_ * 8; \
            cp_async16(base_ + 0     + so_, vh_g + go_); \
            cp_async16(base_ + 17408 + so_, vl_g + go_); \
        } \
    } while (0)

    PF_V(0); CP_COMMIT();
    PF_V(1); CP_COMMIT();

    for (int db = 0; db < 8; db++) {
        float oacc[8][4];
        #pragma unroll
        for (int n = 0; n < 8; n++)
            #pragma unroll
            for (int j = 0; j < 4; j++) oacc[n][j] = 0.f;

        for (int c = 0; c < ncv; c++) {
            int it = db * ncv + c;
            if (it + 2 < totB)      { PF_V(it + 2); CP_COMMIT(); CP_WAIT2(); }
            else if (it + 1 < totB) { CP_WAIT1(); }
            else                    { CP_WAIT0(); }
            __syncthreads();

            uint32_t vb = sb + PIPE_OFF + (it % 3) * VSTG;
            #pragma unroll
            for (int ks = 0; ks < 4; ks++) {
                int kof = c * 64 + ks * 16;
                uint32_t sh4[4], sl4[4];
                uint32_t roA = (uint32_t)((wq * 16 + (lane & 15)) * SPITCH
                                          + (kof + (lane >> 4) * 8) * 2);
                ldsm_x4(sh4, sb + SHI_OFF + roA);
                ldsm_x4(sl4, sb + SLO_OFF + roA);
                uint32_t vh[8][2], vl[8][2];
                #pragma unroll
                for (int p = 0; p < 4; p++) {
                    int dloc = wn * 64 + p * 16;
                    uint32_t roB = (uint32_t)((ks * 16 + (lane & 15)) * VPITCH
                                              + (dloc + (lane >> 4) * 8) * 2);
                    uint32_t r4[4];
                    ldsm_x4_t(r4, vb + 0 + roB);
                    vh[2*p][0] = r4[0]; vh[2*p][1] = r4[1];
                    vh[2*p+1][0] = r4[2]; vh[2*p+1][1] = r4[3];
                    ldsm_x4_t(r4, vb + 17408 + roB);
                    vl[2*p][0] = r4[0]; vl[2*p][1] = r4[1];
                    vl[2*p+1][0] = r4[2]; vl[2*p+1][1] = r4[3];
                }
                #pragma unroll
                for (int n = 0; n < 8; n++) {
                    mma_bf16(oacc[n], sh4, vh[n]);
                    mma_bf16(oacc[n], sh4, vl[n]);
                    mma_bf16(oacc[n], sl4, vh[n]);
                }
            }
            __syncthreads();
        }

        #pragma unroll
        for (int n = 0; n < 8; n++) {
            int d = db * 128 + wn * 64 + n * 8 + (lane & 3) * 2;
            #pragma unroll
            for (int rr = 0; rr < 2; rr++) {
                int row = i0 + rl0 + rr * 8;
                float a0 = oacc[n][rr*2], a1 = oacc[n][rr*2+1];
                uint32_t h = pack_bf16(a0, a1);
                __nv_bfloat162 hh; *(uint32_t*)&hh = h;
                uint32_t l = pack_bf16(a0 - __bfloat162float(hh.x),
                                       a1 - __bfloat162float(hh.y));
                size_t ad = (size_t)(b * TT + row) * DD + d;
                *(uint32_t*)(g_rhi + ad) = h;
                *(uint32_t*)(g_rlo + ad) = l;
            }
        }
    }
    #undef PF_V
}

// ---------------------------------------------------------------------------
extern "C" void kernel_launch(void* const* d_in, const int* in_sizes, int n_in,
                              void* d_out, int out_size)
{
    const float* x  = (const float*)d_in[0];
    const float* Wq = (const float*)d_in[1];
    const float* Wk = (const float*)d_in[2];
    const float* Wv = (const float*)d_in[3];
    const float* Wo = (const float*)d_in[4];
    const float* decay_logit = (const float*)d_in[5];
    const float* out_scale   = (const float*)d_in[6];
    float* out = (float*)d_out;

    __nv_bfloat16 *xhi, *xlo, *whi, *wlo;
    __nv_bfloat16 *qhi, *qlo, *khi, *klo, *vhi, *vlo, *rhi, *rlo;
    cudaGetSymbolAddress((void**)&xhi, g_xhi);
    cudaGetSymbolAddress((void**)&xlo, g_xlo);
    cudaGetSymbolAddress((void**)&whi, g_whi);
    cudaGetSymbolAddress((void**)&wlo, g_wlo);
    cudaGetSymbolAddress((void**)&qhi, g_qhi);
    cudaGetSymbolAddress((void**)&qlo, g_qlo);
    cudaGetSymbolAddress((void**)&khi, g_khi);
    cudaGetSymbolAddress((void**)&klo, g_klo);
    cudaGetSymbolAddress((void**)&vhi, g_vhi);
    cudaGetSymbolAddress((void**)&vlo, g_vlo);
    cudaGetSymbolAddress((void**)&rhi, g_rhi);
    cudaGetSymbolAddress((void**)&rlo, g_rlo);

    int nx4 = M_TOTAL * DD / 4;
    int nw4 = DD * DD / 4;
    split_x<<<(nx4 + 255) / 256, 256>>>(x, xhi, xlo, nx4);
    split_w4<<<dim3((nw4 + 255) / 256, 4), 256>>>(Wq, Wk, Wv, Wo, whi, wlo, nw4);

    cudaFuncSetAttribute(mma_gemm, cudaFuncAttributeMaxDynamicSharedMemorySize, GSMEM);
    cudaFuncSetAttribute(attn_mma, cudaFuncAttributeMaxDynamicSharedMemorySize, ATT_SMEM);

    // QKV projections -> bf16 hi/lo outputs
    mma_gemm<<<dim3(M_TOTAL / 256, DD / 128, 3), 512, GSMEM>>>(
        xhi, xlo, whi, wlo,
        qhi, qlo, khi, klo, vhi, vlo, nullptr, nullptr, 0);

    // windowed decayed attention on tensor cores
    attn_mma<<<dim3(TT / 64, BB), 256, ATT_SMEM>>>(decay_logit);

    // output projection (fp32 out, scaled)
    mma_gemm<<<dim3(M_TOTAL / 256, DD / 128, 1), 512, GSMEM>>>(
        rhi, rlo, whi + 3 * (size_t)DD * DD, wlo + 3 * (size_t)DD * DD,
        nullptr, nullptr, nullptr, nullptr, nullptr, nullptr,
        out, out_scale, 1);
}

// round 8
// speedup vs baseline: 6.4300x; 1.3877x over previous
#include <cuda_runtime.h>
#include <cuda_fp16.h>
#include <math.h>
#include <stdint.h>

#define BB 4
#define TT 4096
#define DD 1024
#define M_TOTAL (BB*TT)

// ------------------------- scratch (device globals) -------------------------
__device__ __half g_xhi[M_TOTAL*DD];
__device__ __half g_xlo[M_TOTAL*DD];
__device__ __half g_whi[4*DD*DD];
__device__ __half g_qhi[M_TOTAL*DD];
__device__ __half g_qlo[M_TOTAL*DD];
__device__ __half g_khi[M_TOTAL*DD];
__device__ __half g_vhi[M_TOTAL*DD];
__device__ __half g_rhi[M_TOTAL*DD];
__device__ __half g_rlo[M_TOTAL*DD];

// ------------------------- helpers ------------------------------------------
__device__ __forceinline__ uint32_t smem_to_u32(const void* p) {
    uint32_t a;
    asm("{ .reg .u64 t; cvta.to.shared.u64 t, %1; cvt.u32.u64 %0, t; }" : "=r"(a) : "l"(p));
    return a;
}
__device__ __forceinline__ void cp_async16(uint32_t saddr, const void* g) {
    asm volatile("cp.async.cg.shared.global [%0], [%1], 16;" :: "r"(saddr), "l"(g));
}
#define CP_COMMIT() asm volatile("cp.async.commit_group;" ::: "memory")
#define CP_WAIT2()  asm volatile("cp.async.wait_group 2;" ::: "memory")
#define CP_WAIT1()  asm volatile("cp.async.wait_group 1;" ::: "memory")
#define CP_WAIT0()  asm volatile("cp.async.wait_group 0;" ::: "memory")

__device__ __forceinline__ void ldsm_x4(uint32_t* r, uint32_t addr) {
    asm volatile("ldmatrix.sync.aligned.m8n8.x4.shared.b16 {%0,%1,%2,%3}, [%4];"
        : "=r"(r[0]), "=r"(r[1]), "=r"(r[2]), "=r"(r[3]) : "r"(addr));
}
__device__ __forceinline__ void ldsm_x4_t(uint32_t* r, uint32_t addr) {
    asm volatile("ldmatrix.sync.aligned.m8n8.x4.trans.shared.b16 {%0,%1,%2,%3}, [%4];"
        : "=r"(r[0]), "=r"(r[1]), "=r"(r[2]), "=r"(r[3]) : "r"(addr));
}
__device__ __forceinline__ void mma_f16(float* d, const uint32_t* a, const uint32_t* b) {
    asm volatile("mma.sync.aligned.m16n8k16.row.col.f32.f16.f16.f32 "
        "{%0,%1,%2,%3}, {%4,%5,%6,%7}, {%8,%9}, {%0,%1,%2,%3};"
        : "+f"(d[0]), "+f"(d[1]), "+f"(d[2]), "+f"(d[3])
        : "r"(a[0]), "r"(a[1]), "r"(a[2]), "r"(a[3]), "r"(b[0]), "r"(b[1]));
}
__device__ __forceinline__ uint32_t pack_f16(float a, float b) {
    __half2 h = __floats2half2_rn(a, b);
    return *(uint32_t*)&h;
}

// ------------------------- conversion kernels --------------------------------
__global__ __launch_bounds__(256) void split_x(
    const float* __restrict__ src, __half* __restrict__ hi,
    __half* __restrict__ lo, int n4)
{
    int i = blockIdx.x * 256 + threadIdx.x;
    if (i >= n4) return;
    float4 v = ((const float4*)src)[i];
    __half h0 = __float2half_rn(v.x);
    __half h1 = __float2half_rn(v.y);
    __half h2 = __float2half_rn(v.z);
    __half h3 = __float2half_rn(v.w);
    __half l0 = __float2half_rn(v.x - __half2float(h0));
    __half l1 = __float2half_rn(v.y - __half2float(h1));
    __half l2 = __float2half_rn(v.z - __half2float(h2));
    __half l3 = __float2half_rn(v.w - __half2float(h3));
    __half2 H0; H0.x = h0; H0.y = h1;
    __half2 H1; H1.x = h2; H1.y = h3;
    __half2 L0; L0.x = l0; L0.y = l1;
    __half2 L1; L1.x = l2; L1.y = l3;
    ((__half2*)hi)[2*i]   = H0;
    ((__half2*)hi)[2*i+1] = H1;
    ((__half2*)lo)[2*i]   = L0;
    ((__half2*)lo)[2*i+1] = L1;
}

__global__ __launch_bounds__(256) void conv_w4(
    const float* __restrict__ s0, const float* __restrict__ s1,
    const float* __restrict__ s2, const float* __restrict__ s3,
    __half* __restrict__ hi, int n4)
{
    int i = blockIdx.x * 256 + threadIdx.x;
    if (i >= n4) return;
    int z = blockIdx.y;
    const float* src = (z == 0) ? s0 : ((z == 1) ? s1 : ((z == 2) ? s2 : s3));
    __half* dst = hi + (size_t)z * DD * DD;
    float4 v = ((const float4*)src)[i];
    __half2 H0; H0.x = __float2half_rn(v.x); H0.y = __float2half_rn(v.y);
    __half2 H1; H1.x = __float2half_rn(v.z); H1.y = __float2half_rn(v.w);
    ((__half2*)dst)[2*i]   = H0;
    ((__half2*)dst)[2*i+1] = H1;
}

// ------------------------- HMMA GEMM (256x128 tile, 512 threads, 2-pass) -----
// C = Ahi*Bhi + Alo*Bhi (fp16 hi/lo on A, hi-only B). 16 warps 8Mx2N, BK=32.
#define AHI_O 0
#define ALO_O 20480
#define BHI_O 40960
#define STAGEB 51200
#define GSMEM  (2*STAGEB)          // 102400

__global__ __launch_bounds__(512, 1) void mma_gemm(
    const __half* __restrict__ Ahi, const __half* __restrict__ Alo,
    const __half* __restrict__ Whi,
    __half* __restrict__ H0, __half* __restrict__ L0,
    __half* __restrict__ H1, __half* __restrict__ H2,
    float* __restrict__ Cf, const float* __restrict__ scale_ptr, int mode)
{
    extern __shared__ char smc[];
    uint32_t sb = smem_to_u32(smc);
    int t = threadIdx.x, lane = t & 31, w = t >> 5;
    int wm = w & 7, wn = w >> 3;
    int m0 = blockIdx.x * 256, n0 = blockIdx.y * 128, z = blockIdx.z;

    const __half* Wh = Whi + (size_t)z * DD * DD;

    const __half* aH = Ahi + (size_t)m0 * DD;
    const __half* aL = Alo + (size_t)m0 * DD;
    const __half* bH = Wh + (size_t)n0 * DD;

    float acc[2][8][4];
    #pragma unroll
    for (int i = 0; i < 2; i++)
        #pragma unroll
        for (int n = 0; n < 8; n++)
            #pragma unroll
            for (int j = 0; j < 4; j++) acc[i][n][j] = 0.f;

    int lrA = t >> 2, lsA = t & 3;
    uint32_t soA = (uint32_t)(lrA * 80 + lsA * 16);
    size_t goA = (size_t)lrA * DD + lsA * 8;

    #define PREFETCH(c) do { \
        uint32_t base_ = sb + ((c) & 1) * STAGEB; \
        int k0_ = (c) * 32; \
        cp_async16(base_ + AHI_O + soA, aH + goA + k0_); \
        cp_async16(base_ + ALO_O + soA, aL + goA + k0_); \
        cp_async16(base_ + AHI_O + soA + 10240, aH + goA + k0_ + (size_t)128 * DD); \
        cp_async16(base_ + ALO_O + soA + 10240, aL + goA + k0_ + (size_t)128 * DD); \
        cp_async16(base_ + BHI_O + soA, bH + goA + k0_); \
    } while (0)

    PREFETCH(0); CP_COMMIT();

    for (int c = 0; c < 32; c++) {
        if (c + 1 < 32) { PREFETCH(c + 1); CP_COMMIT(); CP_WAIT1(); }
        else            { CP_WAIT0(); }
        __syncthreads();

        uint32_t base = sb + (c & 1) * STAGEB;
        #pragma unroll
        for (int kk = 0; kk < 2; kk++) {
            uint32_t ah[2][4], al[2][4];
            #pragma unroll
            for (int i = 0; i < 2; i++) {
                uint32_t ro = (uint32_t)((wm * 32 + i * 16 + (lane & 15)) * 80
                                         + kk * 32 + (lane >> 4) * 16);
                ldsm_x4(ah[i], base + AHI_O + ro);
                ldsm_x4(al[i], base + ALO_O + ro);
            }
            uint32_t bh[8][2];
            #pragma unroll
            for (int p = 0; p < 4; p++) {
                int mid = lane >> 3;
                int nr = wn * 64 + p * 16 + ((mid & 2) << 2) + (lane & 7);
                uint32_t ro = (uint32_t)(nr * 80 + kk * 32 + (mid & 1) * 16);
                uint32_t r4[4];
                ldsm_x4(r4, base + BHI_O + ro);
                bh[2*p][0] = r4[0]; bh[2*p][1] = r4[1];
                bh[2*p+1][0] = r4[2]; bh[2*p+1][1] = r4[3];
            }
            #pragma unroll
            for (int i = 0; i < 2; i++)
                #pragma unroll
                for (int n = 0; n < 8; n++) {
                    mma_f16(acc[i][n], ah[i], bh[n]);
                    mma_f16(acc[i][n], al[i], bh[n]);
                }
        }
        __syncthreads();
    }
    #undef PREFETCH

    int gid = lane >> 2, tig = lane & 3;
    if (mode == 0) {
        __half* Hc = (z == 0) ? H0 : ((z == 1) ? H1 : H2);
        #pragma unroll
        for (int i = 0; i < 2; i++) {
            int r = m0 + wm * 32 + i * 16 + gid;
            #pragma unroll
            for (int n = 0; n < 8; n++) {
                int col = n0 + wn * 64 + n * 8 + tig * 2;
                float a0 = acc[i][n][0], a1 = acc[i][n][1];
                float a2 = acc[i][n][2], a3 = acc[i][n][3];
                uint32_t h01 = pack_f16(a0, a1);
                uint32_t h23 = pack_f16(a2, a3);
                *(uint32_t*)(Hc + (size_t)r * DD + col) = h01;
                *(uint32_t*)(Hc + (size_t)(r + 8) * DD + col) = h23;
                if (z == 0) {
                    __half2 hh;
                    *(uint32_t*)&hh = h01;
                    uint32_t l01 = pack_f16(a0 - __half2float(hh.x), a1 - __half2float(hh.y));
                    *(uint32_t*)&hh = h23;
                    uint32_t l23 = pack_f16(a2 - __half2float(hh.x), a3 - __half2float(hh.y));
                    *(uint32_t*)(L0 + (size_t)r * DD + col) = l01;
                    *(uint32_t*)(L0 + (size_t)(r + 8) * DD + col) = l23;
                }
            }
        }
    } else {
        float sc = *scale_ptr;
        #pragma unroll
        for (int i = 0; i < 2; i++) {
            int r = m0 + wm * 32 + i * 16 + gid;
            #pragma unroll
            for (int n = 0; n < 8; n++) {
                int col = n0 + wn * 64 + n * 8 + tig * 2;
                float2 v0; v0.x = acc[i][n][0] * sc; v0.y = acc[i][n][1] * sc;
                float2 v1; v1.x = acc[i][n][2] * sc; v1.y = acc[i][n][3] * sc;
                *(float2*)(Cf + (size_t)r * DD + col) = v0;
                *(float2*)(Cf + (size_t)(r + 8) * DD + col) = v1;
            }
        }
    }
}

// ------------------------- MMA windowed decayed attention (fp16 2-pass) ------
#define NCH 5
#define SPITCH 688
#define SHI_OFF 0
#define SLO_OFF 44032
#define PIPE_OFF 88064
#define APITCH 144
#define AOP    9216
#define ASTG   (3*AOP)              // qh, ql, kh = 27648
#define VPITCH 272
#define VSTG   17408                // vh only
#define ATT_SMEM (PIPE_OFF + 3*ASTG)   // 171008

__global__ __launch_bounds__(256, 1) void attn_mma(const float* __restrict__ decay_logit_p)
{
    extern __shared__ char smc[];
    uint32_t sb = smem_to_u32(smc);
    int t = threadIdx.x, lane = t & 31, w = t >> 5;
    int wq = w & 3, wn = w >> 2;
    int b = blockIdx.y, i0 = blockIdx.x * 64;
    int ncv = min(NCH, (TT - i0) / 64);

    float dl = *decay_logit_p;
    float decay = 1.0f / (1.0f + expf(-dl));
    float log2d = log2f(decay);
    const float qk_scale = 0.03125f;

    const __half* qh_g = g_qhi + (size_t)(b * TT + i0) * DD;
    const __half* ql_g = g_qlo + (size_t)(b * TT + i0) * DD;
    const __half* kh_g = g_khi + (size_t)(b * TT) * DD;
    const __half* vh_g = g_vhi + (size_t)(b * TT) * DD;

    int mid = lane >> 3;
    int rl0 = wq * 16 + (lane >> 2);

    // ================= Phase A: scores =================
    int totA = ncv * 16;

    #define PF_A(it) do { \
        int c_ = (it) >> 4, ds_ = (it) & 15; \
        int cs_ = i0 + c_ * 64; \
        uint32_t base_ = sb + PIPE_OFF + ((it) % 3) * ASTG; \
        _Pragma("unroll") \
        for (int i_ = 0; i_ < 2; i_++) { \
            int idx_ = t + 256 * i_; \
            int r_ = idx_ >> 3, g_ = idx_ & 7; \
            uint32_t so_ = (uint32_t)(r_ * APITCH + g_ * 16); \
            size_t qo_ = (size_t)r_ * DD + ds_ * 64 + g_ * 8; \
            size_t ko_ = (size_t)(cs_ + r_) * DD + ds_ * 64 + g_ * 8; \
            cp_async16(base_ + 0 * AOP + so_, qh_g + qo_); \
            cp_async16(base_ + 1 * AOP + so_, ql_g + qo_); \
            cp_async16(base_ + 2 * AOP + so_, kh_g + ko_); \
        } \
    } while (0)

    {
        float acc[4][4];
        #pragma unroll
        for (int n = 0; n < 4; n++)
            #pragma unroll
            for (int j = 0; j < 4; j++) acc[n][j] = 0.f;

        PF_A(0); CP_COMMIT();
        PF_A(1); CP_COMMIT();

        for (int it = 0; it < totA; it++) {
            if (it + 2 < totA)      { PF_A(it + 2); CP_COMMIT(); CP_WAIT2(); }
            else if (it + 1 < totA) { CP_WAIT1(); }
            else                    { CP_WAIT0(); }
            __syncthreads();

            uint32_t base = sb + PIPE_OFF + (it % 3) * ASTG;
            #pragma unroll
            for (int kk = 0; kk < 4; kk++) {
                uint32_t qh[4], ql[4];
                uint32_t roA = (uint32_t)((wq * 16 + (lane & 15)) * APITCH
                                          + kk * 32 + (lane >> 4) * 16);
                ldsm_x4(qh, base + 0 * AOP + roA);
                ldsm_x4(ql, base + 1 * AOP + roA);
                uint32_t kh[4][2];
                #pragma unroll
                for (int p = 0; p < 2; p++) {
                    int nr = wn * 32 + p * 16 + ((mid & 2) << 2) + (lane & 7);
                    uint32_t roB = (uint32_t)(nr * APITCH + kk * 32 + (mid & 1) * 16);
                    uint32_t r4[4];
                    ldsm_x4(r4, base + 2 * AOP + roB);
                    kh[2*p][0] = r4[0]; kh[2*p][1] = r4[1];
                    kh[2*p+1][0] = r4[2]; kh[2*p+1][1] = r4[3];
                }
                #pragma unroll
                for (int n = 0; n < 4; n++) {
                    mma_f16(acc[n], qh, kh[n]);
                    mma_f16(acc[n], ql, kh[n]);
                }
            }
            __syncthreads();

            if ((it & 15) == 15) {
                int c = it >> 4;
                #pragma unroll
                for (int n = 0; n < 4; n++) {
                    int jl0 = wn * 32 + n * 8 + (lane & 3) * 2;
                    float s[4];
                    #pragma unroll
                    for (int rr = 0; rr < 2; rr++) {
                        int rl = rl0 + rr * 8;
                        #pragma unroll
                        for (int jj = 0; jj < 2; jj++) {
                            int diff = c * 64 + jl0 + jj - rl;
                            float wt = 0.f;
                            if (diff > 0) wt = qk_scale * exp2f((float)(diff - 1) * log2d);
                            s[rr * 2 + jj] = acc[n][rr * 2 + jj] * wt;
                        }
                    }
                    uint32_t jbyte = (uint32_t)((c * 64 + jl0) * 2);
                    #pragma unroll
                    for (int rr = 0; rr < 2; rr++) {
                        int rl = rl0 + rr * 8;
                        uint32_t h = pack_f16(s[rr*2], s[rr*2+1]);
                        __half2 hh; *(uint32_t*)&hh = h;
                        uint32_t l = pack_f16(s[rr*2] - __half2float(hh.x),
                                              s[rr*2+1] - __half2float(hh.y));
                        uint32_t ad = (uint32_t)(rl * SPITCH) + jbyte;
                        *(uint32_t*)(smc + SHI_OFF + ad) = h;
                        *(uint32_t*)(smc + SLO_OFF + ad) = l;
                    }
                    #pragma unroll
                    for (int j = 0; j < 4; j++) acc[n][j] = 0.f;
                }
            }
        }
    }
    #undef PF_A
    __syncthreads();

    // ================= Phase B: O = S V =================
    int totB = 8 * ncv;

    #define PF_V(it) do { \
        int db_ = (it) / ncv, c_ = (it) % ncv; \
        int cs_ = i0 + c_ * 64; \
        uint32_t base_ = sb + PIPE_OFF + ((it) % 3) * VSTG; \
        _Pragma("unroll") \
        for (int i_ = 0; i_ < 4; i_++) { \
            int idx_ = t + 256 * i_; \
            int r_ = idx_ >> 4, g_ = idx_ & 15; \
            uint32_t so_ = (uint32_t)(r_ * VPITCH + g_ * 16); \
            size_t go_ = (size_t)(cs_ + r_) * DD + db_ * 128 + g_ * 8; \
            cp_async16(base_ + so_, vh_g + go_); \
        } \
    } while (0)

    PF_V(0); CP_COMMIT();
    PF_V(1); CP_COMMIT();

    for (int db = 0; db < 8; db++) {
        float oacc[8][4];
        #pragma unroll
        for (int n = 0; n < 8; n++)
            #pragma unroll
            for (int j = 0; j < 4; j++) oacc[n][j] = 0.f;

        for (int c = 0; c < ncv; c++) {
            int it = db * ncv + c;
            if (it + 2 < totB)      { PF_V(it + 2); CP_COMMIT(); CP_WAIT2(); }
            else if (it + 1 < totB) { CP_WAIT1(); }
            else                    { CP_WAIT0(); }
            __syncthreads();

            uint32_t vb = sb + PIPE_OFF + (it % 3) * VSTG;
            #pragma unroll
            for (int ks = 0; ks < 4; ks++) {
                int kof = c * 64 + ks * 16;
                uint32_t sh4[4], sl4[4];
                uint32_t roA = (uint32_t)((wq * 16 + (lane & 15)) * SPITCH
                                          + (kof + (lane >> 4) * 8) * 2);
                ldsm_x4(sh4, sb + SHI_OFF + roA);
                ldsm_x4(sl4, sb + SLO_OFF + roA);
                uint32_t vh[8][2];
                #pragma unroll
                for (int p = 0; p < 4; p++) {
                    int dloc = wn * 64 + p * 16;
                    uint32_t roB = (uint32_t)((ks * 16 + (lane & 15)) * VPITCH
                                              + (dloc + (lane >> 4) * 8) * 2);
                    uint32_t r4[4];
                    ldsm_x4_t(r4, vb + roB);
                    vh[2*p][0] = r4[0]; vh[2*p][1] = r4[1];
                    vh[2*p+1][0] = r4[2]; vh[2*p+1][1] = r4[3];
                }
                #pragma unroll
                for (int n = 0; n < 8; n++) {
                    mma_f16(oacc[n], sh4, vh[n]);
                    mma_f16(oacc[n], sl4, vh[n]);
                }
            }
            __syncthreads();
        }

        #pragma unroll
        for (int n = 0; n < 8; n++) {
            int d = db * 128 + wn * 64 + n * 8 + (lane & 3) * 2;
            #pragma unroll
            for (int rr = 0; rr < 2; rr++) {
                int row = i0 + rl0 + rr * 8;
                float a0 = oacc[n][rr*2], a1 = oacc[n][rr*2+1];
                uint32_t h = pack_f16(a0, a1);
                __half2 hh; *(uint32_t*)&hh = h;
                uint32_t l = pack_f16(a0 - __half2float(hh.x),
                                      a1 - __half2float(hh.y));
                size_t ad = (size_t)(b * TT + row) * DD + d;
                *(uint32_t*)(g_rhi + ad) = h;
                *(uint32_t*)(g_rlo + ad) = l;
            }
        }
    }
    #undef PF_V
}

// ---------------------------------------------------------------------------
extern "C" void kernel_launch(void* const* d_in, const int* in_sizes, int n_in,
                              void* d_out, int out_size)
{
    const float* x  = (const float*)d_in[0];
    const float* Wq = (const float*)d_in[1];
    const float* Wk = (const float*)d_in[2];
    const float* Wv = (const float*)d_in[3];
    const float* Wo = (const float*)d_in[4];
    const float* decay_logit = (const float*)d_in[5];
    const float* out_scale   = (const float*)d_in[6];
    float* out = (float*)d_out;

    __half *xhi, *xlo, *whi;
    __half *qhi, *qlo, *khi, *vhi, *rhi, *rlo;
    cudaGetSymbolAddress((void**)&xhi, g_xhi);
    cudaGetSymbolAddress((void**)&xlo, g_xlo);
    cudaGetSymbolAddress((void**)&whi, g_whi);
    cudaGetSymbolAddress((void**)&qhi, g_qhi);
    cudaGetSymbolAddress((void**)&qlo, g_qlo);
    cudaGetSymbolAddress((void**)&khi, g_khi);
    cudaGetSymbolAddress((void**)&vhi, g_vhi);
    cudaGetSymbolAddress((void**)&rhi, g_rhi);
    cudaGetSymbolAddress((void**)&rlo, g_rlo);

    int nx4 = M_TOTAL * DD / 4;
    int nw4 = DD * DD / 4;
    split_x<<<(nx4 + 255) / 256, 256>>>(x, xhi, xlo, nx4);
    conv_w4<<<dim3((nw4 + 255) / 256, 4), 256>>>(Wq, Wk, Wv, Wo, whi, nw4);

    cudaFuncSetAttribute(mma_gemm, cudaFuncAttributeMaxDynamicSharedMemorySize, GSMEM);
    cudaFuncSetAttribute(attn_mma, cudaFuncAttributeMaxDynamicSharedMemorySize, ATT_SMEM);

    // QKV projections -> q (hi+lo), k (hi), v (hi)
    mma_gemm<<<dim3(M_TOTAL / 256, DD / 128, 3), 512, GSMEM>>>(
        xhi, xlo, whi, qhi, qlo, khi, vhi, nullptr, nullptr, 0);

    // windowed decayed attention on tensor cores
    attn_mma<<<dim3(TT / 64, BB), 256, ATT_SMEM>>>(decay_logit);

    // output projection (fp32 out, scaled)
    mma_gemm<<<dim3(M_TOTAL / 256, DD / 128, 1), 512, GSMEM>>>(
        rhi, rlo, whi + 3 * (size_t)DD * DD, nullptr, nullptr, nullptr, nullptr,
        out, out_scale, 1);
}

// round 9
// speedup vs baseline: 6.7056x; 1.0429x over previous
#include <cuda_runtime.h>
#include <cuda_fp16.h>
#include <math.h>
#include <stdint.h>

#define BB 4
#define TT 4096
#define DD 1024
#define M_TOTAL (BB*TT)

// ------------------------- scratch (device globals) -------------------------
__device__ __half g_xhi[M_TOTAL*DD];
__device__ __half g_xlo[M_TOTAL*DD];
__device__ __half g_whi[4*DD*DD];
__device__ __half g_qhi[M_TOTAL*DD];
__device__ __half g_qlo[M_TOTAL*DD];
__device__ __half g_khi[M_TOTAL*DD];
__device__ __half g_vhi[M_TOTAL*DD];
__device__ __half g_rhi[M_TOTAL*DD];
__device__ __half g_rlo[M_TOTAL*DD];

// ------------------------- helpers ------------------------------------------
__device__ __forceinline__ uint32_t smem_to_u32(const void* p) {
    uint32_t a;
    asm("{ .reg .u64 t; cvta.to.shared.u64 t, %1; cvt.u32.u64 %0, t; }" : "=r"(a) : "l"(p));
    return a;
}
__device__ __forceinline__ void cp_async16(uint32_t saddr, const void* g) {
    asm volatile("cp.async.cg.shared.global [%0], [%1], 16;" :: "r"(saddr), "l"(g));
}
#define CP_COMMIT() asm volatile("cp.async.commit_group;" ::: "memory")
#define CP_WAIT2()  asm volatile("cp.async.wait_group 2;" ::: "memory")
#define CP_WAIT1()  asm volatile("cp.async.wait_group 1;" ::: "memory")
#define CP_WAIT0()  asm volatile("cp.async.wait_group 0;" ::: "memory")

__device__ __forceinline__ void ldsm_x4(uint32_t* r, uint32_t addr) {
    asm volatile("ldmatrix.sync.aligned.m8n8.x4.shared.b16 {%0,%1,%2,%3}, [%4];"
        : "=r"(r[0]), "=r"(r[1]), "=r"(r[2]), "=r"(r[3]) : "r"(addr));
}
__device__ __forceinline__ void ldsm_x4_t(uint32_t* r, uint32_t addr) {
    asm volatile("ldmatrix.sync.aligned.m8n8.x4.trans.shared.b16 {%0,%1,%2,%3}, [%4];"
        : "=r"(r[0]), "=r"(r[1]), "=r"(r[2]), "=r"(r[3]) : "r"(addr));
}
__device__ __forceinline__ void mma_f16(float* d, const uint32_t* a, const uint32_t* b) {
    asm volatile("mma.sync.aligned.m16n8k16.row.col.f32.f16.f16.f32 "
        "{%0,%1,%2,%3}, {%4,%5,%6,%7}, {%8,%9}, {%0,%1,%2,%3};"
        : "+f"(d[0]), "+f"(d[1]), "+f"(d[2]), "+f"(d[3])
        : "r"(a[0]), "r"(a[1]), "r"(a[2]), "r"(a[3]), "r"(b[0]), "r"(b[1]));
}
__device__ __forceinline__ uint32_t pack_f16(float a, float b) {
    __half2 h = __floats2half2_rn(a, b);
    return *(uint32_t*)&h;
}

// ------------------------- conversion kernels --------------------------------
__global__ __launch_bounds__(256) void split_x(
    const float* __restrict__ src, __half* __restrict__ hi,
    __half* __restrict__ lo, int n4)
{
    int i = blockIdx.x * 256 + threadIdx.x;
    if (i >= n4) return;
    float4 v = ((const float4*)src)[i];
    __half h0 = __float2half_rn(v.x);
    __half h1 = __float2half_rn(v.y);
    __half h2 = __float2half_rn(v.z);
    __half h3 = __float2half_rn(v.w);
    __half l0 = __float2half_rn(v.x - __half2float(h0));
    __half l1 = __float2half_rn(v.y - __half2float(h1));
    __half l2 = __float2half_rn(v.z - __half2float(h2));
    __half l3 = __float2half_rn(v.w - __half2float(h3));
    __half2 H0; H0.x = h0; H0.y = h1;
    __half2 H1; H1.x = h2; H1.y = h3;
    __half2 L0; L0.x = l0; L0.y = l1;
    __half2 L1; L1.x = l2; L1.y = l3;
    ((__half2*)hi)[2*i]   = H0;
    ((__half2*)hi)[2*i+1] = H1;
    ((__half2*)lo)[2*i]   = L0;
    ((__half2*)lo)[2*i+1] = L1;
}

__global__ __launch_bounds__(256) void conv_w4(
    const float* __restrict__ s0, const float* __restrict__ s1,
    const float* __restrict__ s2, const float* __restrict__ s3,
    __half* __restrict__ hi, int n4)
{
    int i = blockIdx.x * 256 + threadIdx.x;
    if (i >= n4) return;
    int z = blockIdx.y;
    const float* src = (z == 0) ? s0 : ((z == 1) ? s1 : ((z == 2) ? s2 : s3));
    __half* dst = hi + (size_t)z * DD * DD;
    float4 v = ((const float4*)src)[i];
    __half2 H0; H0.x = __float2half_rn(v.x); H0.y = __float2half_rn(v.y);
    __half2 H1; H1.x = __float2half_rn(v.z); H1.y = __float2half_rn(v.w);
    ((__half2*)dst)[2*i]   = H0;
    ((__half2*)dst)[2*i+1] = H1;
}

// ------------------------- HMMA GEMM (128x128, 256 thr, 2 CTAs/SM) ----------
// C = Ahi*Bhi + Alo*Bhi. 8 warps: 4M x 2N, warp tile 32x64. BK=32, 3-stage.
#define AHI_O 0
#define ALO_O 10240
#define BHI_O 20480
#define STAGEB 30720
#define GSMEM  (3*STAGEB)          // 92160; x2 CTAs = 184320 < 228KB

__global__ __launch_bounds__(256, 2) void mma_gemm(
    const __half* __restrict__ Ahi, const __half* __restrict__ Alo,
    const __half* __restrict__ Whi,
    __half* __restrict__ H0, __half* __restrict__ L0,
    __half* __restrict__ H1, __half* __restrict__ H2,
    float* __restrict__ Cf, const float* __restrict__ scale_ptr, int mode)
{
    extern __shared__ char smc[];
    uint32_t sb = smem_to_u32(smc);
    int t = threadIdx.x, lane = t & 31, w = t >> 5;
    int wm = w & 3, wn = w >> 2;
    int m0 = blockIdx.x * 128, n0 = blockIdx.y * 128, z = blockIdx.z;

    const __half* Wh = Whi + (size_t)z * DD * DD;

    const __half* aH = Ahi + (size_t)m0 * DD;
    const __half* aL = Alo + (size_t)m0 * DD;
    const __half* bH = Wh + (size_t)n0 * DD;

    float acc[2][8][4];
    #pragma unroll
    for (int i = 0; i < 2; i++)
        #pragma unroll
        for (int n = 0; n < 8; n++)
            #pragma unroll
            for (int j = 0; j < 4; j++) acc[i][n][j] = 0.f;

    int lrA = t >> 1, lsA = t & 1;     // 128 rows x 2 halves; 2 segs per thread-row
    uint32_t soA = (uint32_t)(lrA * 80 + lsA * 32);
    size_t goA = (size_t)lrA * DD + lsA * 16;

    #define PREFETCH(c) do { \
        uint32_t base_ = sb + ((c) % 3) * STAGEB; \
        int k0_ = (c) * 32; \
        cp_async16(base_ + AHI_O + soA,      aH + goA + k0_); \
        cp_async16(base_ + AHI_O + soA + 16, aH + goA + k0_ + 8); \
        cp_async16(base_ + ALO_O + soA,      aL + goA + k0_); \
        cp_async16(base_ + ALO_O + soA + 16, aL + goA + k0_ + 8); \
        cp_async16(base_ + BHI_O + soA,      bH + goA + k0_); \
        cp_async16(base_ + BHI_O + soA + 16, bH + goA + k0_ + 8); \
    } while (0)

    PREFETCH(0); CP_COMMIT();
    PREFETCH(1); CP_COMMIT();

    for (int c = 0; c < 32; c++) {
        if (c + 2 < 32)      { PREFETCH(c + 2); CP_COMMIT(); CP_WAIT2(); }
        else if (c + 1 < 32) { CP_WAIT1(); }
        else                 { CP_WAIT0(); }
        __syncthreads();

        uint32_t base = sb + (c % 3) * STAGEB;
        #pragma unroll
        for (int kk = 0; kk < 2; kk++) {
            uint32_t ah[2][4], al[2][4];
            #pragma unroll
            for (int i = 0; i < 2; i++) {
                uint32_t ro = (uint32_t)((wm * 32 + i * 16 + (lane & 15)) * 80
                                         + kk * 32 + (lane >> 4) * 16);
                ldsm_x4(ah[i], base + AHI_O + ro);
                ldsm_x4(al[i], base + ALO_O + ro);
            }
            uint32_t bh[8][2];
            #pragma unroll
            for (int p = 0; p < 4; p++) {
                int mid = lane >> 3;
                int nr = wn * 64 + p * 16 + ((mid & 2) << 2) + (lane & 7);
                uint32_t ro = (uint32_t)(nr * 80 + kk * 32 + (mid & 1) * 16);
                uint32_t r4[4];
                ldsm_x4(r4, base + BHI_O + ro);
                bh[2*p][0] = r4[0]; bh[2*p][1] = r4[1];
                bh[2*p+1][0] = r4[2]; bh[2*p+1][1] = r4[3];
            }
            #pragma unroll
            for (int i = 0; i < 2; i++)
                #pragma unroll
                for (int n = 0; n < 8; n++) {
                    mma_f16(acc[i][n], ah[i], bh[n]);
                    mma_f16(acc[i][n], al[i], bh[n]);
                }
        }
        __syncthreads();
    }
    #undef PREFETCH

    int gid = lane >> 2, tig = lane & 3;
    if (mode == 0) {
        __half* Hc = (z == 0) ? H0 : ((z == 1) ? H1 : H2);
        #pragma unroll
        for (int i = 0; i < 2; i++) {
            int r = m0 + wm * 32 + i * 16 + gid;
            #pragma unroll
            for (int n = 0; n < 8; n++) {
                int col = n0 + wn * 64 + n * 8 + tig * 2;
                float a0 = acc[i][n][0], a1 = acc[i][n][1];
                float a2 = acc[i][n][2], a3 = acc[i][n][3];
                uint32_t h01 = pack_f16(a0, a1);
                uint32_t h23 = pack_f16(a2, a3);
                *(uint32_t*)(Hc + (size_t)r * DD + col) = h01;
                *(uint32_t*)(Hc + (size_t)(r + 8) * DD + col) = h23;
                if (z == 0) {
                    __half2 hh;
                    *(uint32_t*)&hh = h01;
                    uint32_t l01 = pack_f16(a0 - __half2float(hh.x), a1 - __half2float(hh.y));
                    *(uint32_t*)&hh = h23;
                    uint32_t l23 = pack_f16(a2 - __half2float(hh.x), a3 - __half2float(hh.y));
                    *(uint32_t*)(L0 + (size_t)r * DD + col) = l01;
                    *(uint32_t*)(L0 + (size_t)(r + 8) * DD + col) = l23;
                }
            }
        }
    } else {
        float sc = *scale_ptr;
        #pragma unroll
        for (int i = 0; i < 2; i++) {
            int r = m0 + wm * 32 + i * 16 + gid;
            #pragma unroll
            for (int n = 0; n < 8; n++) {
                int col = n0 + wn * 64 + n * 8 + tig * 2;
                float2 v0; v0.x = acc[i][n][0] * sc; v0.y = acc[i][n][1] * sc;
                float2 v1; v1.x = acc[i][n][2] * sc; v1.y = acc[i][n][3] * sc;
                *(float2*)(Cf + (size_t)r * DD + col) = v0;
                *(float2*)(Cf + (size_t)(r + 8) * DD + col) = v1;
            }
        }
    }
}

// ------------------------- MMA windowed decayed attention (fp16 2-pass) ------
#define NCH 5
#define SPITCH 688
#define SHI_OFF 0
#define SLO_OFF 44032
#define PIPE_OFF 88064
#define APITCH 144
#define AOP    9216
#define ASTG   (3*AOP)              // qh, ql, kh = 27648
#define VPITCH 272
#define VSTG   17408                // vh only
#define ATT_SMEM (PIPE_OFF + 3*ASTG)   // 171008

__global__ __launch_bounds__(256, 1) void attn_mma(const float* __restrict__ decay_logit_p)
{
    extern __shared__ char smc[];
    uint32_t sb = smem_to_u32(smc);
    int t = threadIdx.x, lane = t & 31, w = t >> 5;
    int wq = w & 3, wn = w >> 2;
    int b = blockIdx.y, i0 = blockIdx.x * 64;
    int ncv = min(NCH, (TT - i0) / 64);

    float dl = *decay_logit_p;
    float decay = 1.0f / (1.0f + expf(-dl));
    float log2d = log2f(decay);
    const float qk_scale = 0.03125f;

    const __half* qh_g = g_qhi + (size_t)(b * TT + i0) * DD;
    const __half* ql_g = g_qlo + (size_t)(b * TT + i0) * DD;
    const __half* kh_g = g_khi + (size_t)(b * TT) * DD;
    const __half* vh_g = g_vhi + (size_t)(b * TT) * DD;

    int mid = lane >> 3;
    int rl0 = wq * 16 + (lane >> 2);

    // ================= Phase A: scores =================
    int totA = ncv * 16;

    #define PF_A(it) do { \
        int c_ = (it) >> 4, ds_ = (it) & 15; \
        int cs_ = i0 + c_ * 64; \
        uint32_t base_ = sb + PIPE_OFF + ((it) % 3) * ASTG; \
        _Pragma("unroll") \
        for (int i_ = 0; i_ < 2; i_++) { \
            int idx_ = t + 256 * i_; \
            int r_ = idx_ >> 3, g_ = idx_ & 7; \
            uint32_t so_ = (uint32_t)(r_ * APITCH + g_ * 16); \
            size_t qo_ = (size_t)r_ * DD + ds_ * 64 + g_ * 8; \
            size_t ko_ = (size_t)(cs_ + r_) * DD + ds_ * 64 + g_ * 8; \
            cp_async16(base_ + 0 * AOP + so_, qh_g + qo_); \
            cp_async16(base_ + 1 * AOP + so_, ql_g + qo_); \
            cp_async16(base_ + 2 * AOP + so_, kh_g + ko_); \
        } \
    } while (0)

    {
        float acc[4][4];
        #pragma unroll
        for (int n = 0; n < 4; n++)
            #pragma unroll
            for (int j = 0; j < 4; j++) acc[n][j] = 0.f;

        PF_A(0); CP_COMMIT();
        PF_A(1); CP_COMMIT();

        for (int it = 0; it < totA; it++) {
            if (it + 2 < totA)      { PF_A(it + 2); CP_COMMIT(); CP_WAIT2(); }
            else if (it + 1 < totA) { CP_WAIT1(); }
            else                    { CP_WAIT0(); }
            __syncthreads();

            uint32_t base = sb + PIPE_OFF + (it % 3) * ASTG;
            #pragma unroll
            for (int kk = 0; kk < 4; kk++) {
                uint32_t qh[4], ql[4];
                uint32_t roA = (uint32_t)((wq * 16 + (lane & 15)) * APITCH
                                          + kk * 32 + (lane >> 4) * 16);
                ldsm_x4(qh, base + 0 * AOP + roA);
                ldsm_x4(ql, base + 1 * AOP + roA);
                uint32_t kh[4][2];
                #pragma unroll
                for (int p = 0; p < 2; p++) {
                    int nr = wn * 32 + p * 16 + ((mid & 2) << 2) + (lane & 7);
                    uint32_t roB = (uint32_t)(nr * APITCH + kk * 32 + (mid & 1) * 16);
                    uint32_t r4[4];
                    ldsm_x4(r4, base + 2 * AOP + roB);
                    kh[2*p][0] = r4[0]; kh[2*p][1] = r4[1];
                    kh[2*p+1][0] = r4[2]; kh[2*p+1][1] = r4[3];
                }
                #pragma unroll
                for (int n = 0; n < 4; n++) {
                    mma_f16(acc[n], qh, kh[n]);
                    mma_f16(acc[n], ql, kh[n]);
                }
            }
            __syncthreads();

            if ((it & 15) == 15) {
                int c = it >> 4;
                #pragma unroll
                for (int n = 0; n < 4; n++) {
                    int jl0 = wn * 32 + n * 8 + (lane & 3) * 2;
                    float s[4];
                    #pragma unroll
                    for (int rr = 0; rr < 2; rr++) {
                        int rl = rl0 + rr * 8;
                        #pragma unroll
                        for (int jj = 0; jj < 2; jj++) {
                            int diff = c * 64 + jl0 + jj - rl;
                            float wt = 0.f;
                            if (diff > 0) wt = qk_scale * exp2f((float)(diff - 1) * log2d);
                            s[rr * 2 + jj] = acc[n][rr * 2 + jj] * wt;
                        }
                    }
                    uint32_t jbyte = (uint32_t)((c * 64 + jl0) * 2);
                    #pragma unroll
                    for (int rr = 0; rr < 2; rr++) {
                        int rl = rl0 + rr * 8;
                        uint32_t h = pack_f16(s[rr*2], s[rr*2+1]);
                        __half2 hh; *(uint32_t*)&hh = h;
                        uint32_t l = pack_f16(s[rr*2] - __half2float(hh.x),
                                              s[rr*2+1] - __half2float(hh.y));
                        uint32_t ad = (uint32_t)(rl * SPITCH) + jbyte;
                        *(uint32_t*)(smc + SHI_OFF + ad) = h;
                        *(uint32_t*)(smc + SLO_OFF + ad) = l;
                    }
                    #pragma unroll
                    for (int j = 0; j < 4; j++) acc[n][j] = 0.f;
                }
            }
        }
    }
    #undef PF_A
    __syncthreads();

    // ================= Phase B: O = S V =================
    int totB = 8 * ncv;

    #define PF_V(it) do { \
        int db_ = (it) / ncv, c_ = (it) % ncv; \
        int cs_ = i0 + c_ * 64; \
        uint32_t base_ = sb + PIPE_OFF + ((it) % 3) * VSTG; \
        _Pragma("unroll") \
        for (int i_ = 0; i_ < 4; i_++) { \
            int idx_ = t + 256 * i_; \
            int r_ = idx_ >> 4, g_ = idx_ & 15; \
            uint32_t so_ = (uint32_t)(r_ * VPITCH + g_ * 16); \
            size_t go_ = (size_t)(cs_ + r_) * DD + db_ * 128 + g_ * 8; \
            cp_async16(base_ + so_, vh_g + go_); \
        } \
    } while (0)

    PF_V(0); CP_COMMIT();
    PF_V(1); CP_COMMIT();

    for (int db = 0; db < 8; db++) {
        float oacc[8][4];
        #pragma unroll
        for (int n = 0; n < 8; n++)
            #pragma unroll
            for (int j = 0; j < 4; j++) oacc[n][j] = 0.f;

        for (int c = 0; c < ncv; c++) {
            int it = db * ncv + c;
            if (it + 2 < totB)      { PF_V(it + 2); CP_COMMIT(); CP_WAIT2(); }
            else if (it + 1 < totB) { CP_WAIT1(); }
            else                    { CP_WAIT0(); }
            __syncthreads();

            uint32_t vb = sb + PIPE_OFF + (it % 3) * VSTG;
            #pragma unroll
            for (int ks = 0; ks < 4; ks++) {
                int kof = c * 64 + ks * 16;
                uint32_t sh4[4], sl4[4];
                uint32_t roA = (uint32_t)((wq * 16 + (lane & 15)) * SPITCH
                                          + (kof + (lane >> 4) * 8) * 2);
                ldsm_x4(sh4, sb + SHI_OFF + roA);
                ldsm_x4(sl4, sb + SLO_OFF + roA);
                uint32_t vh[8][2];
                #pragma unroll
                for (int p = 0; p < 4; p++) {
                    int dloc = wn * 64 + p * 16;
                    uint32_t roB = (uint32_t)((ks * 16 + (lane & 15)) * VPITCH
                                              + (dloc + (lane >> 4) * 8) * 2);
                    uint32_t r4[4];
                    ldsm_x4_t(r4, vb + roB);
                    vh[2*p][0] = r4[0]; vh[2*p][1] = r4[1];
                    vh[2*p+1][0] = r4[2]; vh[2*p+1][1] = r4[3];
                }
                #pragma unroll
                for (int n = 0; n < 8; n++) {
                    mma_f16(oacc[n], sh4, vh[n]);
                    mma_f16(oacc[n], sl4, vh[n]);
                }
            }
            __syncthreads();
        }

        #pragma unroll
        for (int n = 0; n < 8; n++) {
            int d = db * 128 + wn * 64 + n * 8 + (lane & 3) * 2;
            #pragma unroll
            for (int rr = 0; rr < 2; rr++) {
                int row = i0 + rl0 + rr * 8;
                float a0 = oacc[n][rr*2], a1 = oacc[n][rr*2+1];
                uint32_t h = pack_f16(a0, a1);
                __half2 hh; *(uint32_t*)&hh = h;
                uint32_t l = pack_f16(a0 - __half2float(hh.x),
                                      a1 - __half2float(hh.y));
                size_t ad = (size_t)(b * TT + row) * DD + d;
                *(uint32_t*)(g_rhi + ad) = h;
                *(uint32_t*)(g_rlo + ad) = l;
            }
        }
    }
    #undef PF_V
}

// ---------------------------------------------------------------------------
extern "C" void kernel_launch(void* const* d_in, const int* in_sizes, int n_in,
                              void* d_out, int out_size)
{
    const float* x  = (const float*)d_in[0];
    const float* Wq = (const float*)d_in[1];
    const float* Wk = (const float*)d_in[2];
    const float* Wv = (const float*)d_in[3];
    const float* Wo = (const float*)d_in[4];
    const float* decay_logit = (const float*)d_in[5];
    const float* out_scale   = (const float*)d_in[6];
    float* out = (float*)d_out;

    __half *xhi, *xlo, *whi;
    __half *qhi, *qlo, *khi, *vhi, *rhi, *rlo;
    cudaGetSymbolAddress((void**)&xhi, g_xhi);
    cudaGetSymbolAddress((void**)&xlo, g_xlo);
    cudaGetSymbolAddress((void**)&whi, g_whi);
    cudaGetSymbolAddress((void**)&qhi, g_qhi);
    cudaGetSymbolAddress((void**)&qlo, g_qlo);
    cudaGetSymbolAddress((void**)&khi, g_khi);
    cudaGetSymbolAddress((void**)&vhi, g_vhi);
    cudaGetSymbolAddress((void**)&rhi, g_rhi);
    cudaGetSymbolAddress((void**)&rlo, g_rlo);

    int nx4 = M_TOTAL * DD / 4;
    int nw4 = DD * DD / 4;
    split_x<<<(nx4 + 255) / 256, 256>>>(x, xhi, xlo, nx4);
    conv_w4<<<dim3((nw4 + 255) / 256, 4), 256>>>(Wq, Wk, Wv, Wo, whi, nw4);

    cudaFuncSetAttribute(mma_gemm, cudaFuncAttributeMaxDynamicSharedMemorySize, GSMEM);
    cudaFuncSetAttribute(attn_mma, cudaFuncAttributeMaxDynamicSharedMemorySize, ATT_SMEM);

    // QKV projections -> q (hi+lo), k (hi), v (hi)
    mma_gemm<<<dim3(M_TOTAL / 128, DD / 128, 3), 256, GSMEM>>>(
        xhi, xlo, whi, qhi, qlo, khi, vhi, nullptr, nullptr, 0);

    // windowed decayed attention on tensor cores
    attn_mma<<<dim3(TT / 64, BB), 256, ATT_SMEM>>>(decay_logit);

    // output projection (fp32 out, scaled)
    mma_gemm<<<dim3(M_TOTAL / 128, DD / 128, 1), 256, GSMEM>>>(
        rhi, rlo, whi + 3 * (size_t)DD * DD, nullptr, nullptr, nullptr, nullptr,
        out, out_scale, 1);
}

// round 10
// speedup vs baseline: 7.7065x; 1.1493x over previous
#include <cuda_runtime.h>
#include <cuda_fp16.h>
#include <math.h>
#include <stdint.h>

#define BB 4
#define TT 4096
#define DD 1024
#define M_TOTAL (BB*TT)

// ------------------------- scratch (device globals) -------------------------
__device__ __half g_xhi[M_TOTAL*DD];
__device__ __half g_xlo[M_TOTAL*DD];
__device__ __half g_whi[4*DD*DD];
__device__ __half g_qhi[M_TOTAL*DD];
__device__ __half g_qlo[M_TOTAL*DD];
__device__ __half g_khi[M_TOTAL*DD];
__device__ __half g_vhi[M_TOTAL*DD];
__device__ __half g_rhi[M_TOTAL*DD];

// ------------------------- helpers ------------------------------------------
__device__ __forceinline__ uint32_t smem_to_u32(const void* p) {
    uint32_t a;
    asm("{ .reg .u64 t; cvta.to.shared.u64 t, %1; cvt.u32.u64 %0, t; }" : "=r"(a) : "l"(p));
    return a;
}
__device__ __forceinline__ void cp_async16(uint32_t saddr, const void* g) {
    asm volatile("cp.async.cg.shared.global [%0], [%1], 16;" :: "r"(saddr), "l"(g));
}
#define CP_COMMIT() asm volatile("cp.async.commit_group;" ::: "memory")
#define CP_WAIT2()  asm volatile("cp.async.wait_group 2;" ::: "memory")
#define CP_WAIT1()  asm volatile("cp.async.wait_group 1;" ::: "memory")
#define CP_WAIT0()  asm volatile("cp.async.wait_group 0;" ::: "memory")

__device__ __forceinline__ void ldsm_x4(uint32_t* r, uint32_t addr) {
    asm volatile("ldmatrix.sync.aligned.m8n8.x4.shared.b16 {%0,%1,%2,%3}, [%4];"
        : "=r"(r[0]), "=r"(r[1]), "=r"(r[2]), "=r"(r[3]) : "r"(addr));
}
__device__ __forceinline__ void ldsm_x4_t(uint32_t* r, uint32_t addr) {
    asm volatile("ldmatrix.sync.aligned.m8n8.x4.trans.shared.b16 {%0,%1,%2,%3}, [%4];"
        : "=r"(r[0]), "=r"(r[1]), "=r"(r[2]), "=r"(r[3]) : "r"(addr));
}
__device__ __forceinline__ void mma_f16(float* d, const uint32_t* a, const uint32_t* b) {
    asm volatile("mma.sync.aligned.m16n8k16.row.col.f32.f16.f16.f32 "
        "{%0,%1,%2,%3}, {%4,%5,%6,%7}, {%8,%9}, {%0,%1,%2,%3};"
        : "+f"(d[0]), "+f"(d[1]), "+f"(d[2]), "+f"(d[3])
        : "r"(a[0]), "r"(a[1]), "r"(a[2]), "r"(a[3]), "r"(b[0]), "r"(b[1]));
}
__device__ __forceinline__ uint32_t pack_f16(float a, float b) {
    __half2 h = __floats2half2_rn(a, b);
    return *(uint32_t*)&h;
}

// ------------------------- conversion kernels --------------------------------
__global__ __launch_bounds__(256) void split_x(
    const float* __restrict__ src, __half* __restrict__ hi,
    __half* __restrict__ lo, int n4)
{
    int i = blockIdx.x * 256 + threadIdx.x;
    if (i >= n4) return;
    float4 v = ((const float4*)src)[i];
    __half h0 = __float2half_rn(v.x);
    __half h1 = __float2half_rn(v.y);
    __half h2 = __float2half_rn(v.z);
    __half h3 = __float2half_rn(v.w);
    __half l0 = __float2half_rn(v.x - __half2float(h0));
    __half l1 = __float2half_rn(v.y - __half2float(h1));
    __half l2 = __float2half_rn(v.z - __half2float(h2));
    __half l3 = __float2half_rn(v.w - __half2float(h3));
    __half2 H0; H0.x = h0; H0.y = h1;
    __half2 H1; H1.x = h2; H1.y = h3;
    __half2 L0; L0.x = l0; L0.y = l1;
    __half2 L1; L1.x = l2; L1.y = l3;
    ((__half2*)hi)[2*i]   = H0;
    ((__half2*)hi)[2*i+1] = H1;
    ((__half2*)lo)[2*i]   = L0;
    ((__half2*)lo)[2*i+1] = L1;
}

__global__ __launch_bounds__(256) void conv_w4(
    const float* __restrict__ s0, const float* __restrict__ s1,
    const float* __restrict__ s2, const float* __restrict__ s3,
    __half* __restrict__ hi, int n4)
{
    int i = blockIdx.x * 256 + threadIdx.x;
    if (i >= n4) return;
    int z = blockIdx.y;
    const float* src = (z == 0) ? s0 : ((z == 1) ? s1 : ((z == 2) ? s2 : s3));
    __half* dst = hi + (size_t)z * DD * DD;
    float4 v = ((const float4*)src)[i];
    __half2 H0; H0.x = __float2half_rn(v.x); H0.y = __float2half_rn(v.y);
    __half2 H1; H1.x = __float2half_rn(v.z); H1.y = __float2half_rn(v.w);
    ((__half2*)dst)[2*i]   = H0;
    ((__half2*)dst)[2*i+1] = H1;
}

// ------------------------- HMMA GEMM (128x128, 256 thr, 2 CTAs/SM) ----------
// mode 0 (QKV): q (z=0) = 2-pass (Ahi+Alo)*Bhi, k/v (z=1,2) = 1-pass Ahi*Bhi.
// mode 1 (proj): 1-pass Ahi*Bhi, fp32 out scaled.
#define AHI_O 0
#define ALO_O 10240
#define BHI_O 20480
#define STAGEB 30720
#define GSMEM  (3*STAGEB)          // 92160; x2 CTAs = 184320

__global__ __launch_bounds__(256, 2) void mma_gemm(
    const __half* __restrict__ Ahi, const __half* __restrict__ Alo,
    const __half* __restrict__ Whi,
    __half* __restrict__ H0, __half* __restrict__ L0,
    __half* __restrict__ H1, __half* __restrict__ H2,
    float* __restrict__ Cf, const float* __restrict__ scale_ptr, int mode)
{
    extern __shared__ char smc[];
    uint32_t sb = smem_to_u32(smc);
    int t = threadIdx.x, lane = t & 31, w = t >> 5;
    int wm = w & 3, wn = w >> 2;
    int m0 = blockIdx.x * 128, n0 = blockIdx.y * 128, z = blockIdx.z;

    bool do_lo = (mode == 0) && (z == 0);

    const __half* Wh = Whi + (size_t)z * DD * DD;

    const __half* aH = Ahi + (size_t)m0 * DD;
    const __half* aL = Alo + (size_t)m0 * DD;
    const __half* bH = Wh + (size_t)n0 * DD;

    float acc[2][8][4];
    #pragma unroll
    for (int i = 0; i < 2; i++)
        #pragma unroll
        for (int n = 0; n < 8; n++)
            #pragma unroll
            for (int j = 0; j < 4; j++) acc[i][n][j] = 0.f;

    int lrA = t >> 1, lsA = t & 1;
    uint32_t soA = (uint32_t)(lrA * 80 + lsA * 32);
    size_t goA = (size_t)lrA * DD + lsA * 16;

    #define PREFETCH(c) do { \
        uint32_t base_ = sb + ((c) % 3) * STAGEB; \
        int k0_ = (c) * 32; \
        cp_async16(base_ + AHI_O + soA,      aH + goA + k0_); \
        cp_async16(base_ + AHI_O + soA + 16, aH + goA + k0_ + 8); \
        if (do_lo) { \
            cp_async16(base_ + ALO_O + soA,      aL + goA + k0_); \
            cp_async16(base_ + ALO_O + soA + 16, aL + goA + k0_ + 8); \
        } \
        cp_async16(base_ + BHI_O + soA,      bH + goA + k0_); \
        cp_async16(base_ + BHI_O + soA + 16, bH + goA + k0_ + 8); \
    } while (0)

    PREFETCH(0); CP_COMMIT();
    PREFETCH(1); CP_COMMIT();

    for (int c = 0; c < 32; c++) {
        if (c + 2 < 32)      { PREFETCH(c + 2); CP_COMMIT(); CP_WAIT2(); }
        else if (c + 1 < 32) { CP_WAIT1(); }
        else                 { CP_WAIT0(); }
        __syncthreads();

        uint32_t base = sb + (c % 3) * STAGEB;
        #pragma unroll
        for (int kk = 0; kk < 2; kk++) {
            uint32_t ah[2][4], al[2][4];
            #pragma unroll
            for (int i = 0; i < 2; i++) {
                uint32_t ro = (uint32_t)((wm * 32 + i * 16 + (lane & 15)) * 80
                                         + kk * 32 + (lane >> 4) * 16);
                ldsm_x4(ah[i], base + AHI_O + ro);
                if (do_lo) ldsm_x4(al[i], base + ALO_O + ro);
            }
            uint32_t bh[8][2];
            #pragma unroll
            for (int p = 0; p < 4; p++) {
                int mid = lane >> 3;
                int nr = wn * 64 + p * 16 + ((mid & 2) << 2) + (lane & 7);
                uint32_t ro = (uint32_t)(nr * 80 + kk * 32 + (mid & 1) * 16);
                uint32_t r4[4];
                ldsm_x4(r4, base + BHI_O + ro);
                bh[2*p][0] = r4[0]; bh[2*p][1] = r4[1];
                bh[2*p+1][0] = r4[2]; bh[2*p+1][1] = r4[3];
            }
            #pragma unroll
            for (int i = 0; i < 2; i++)
                #pragma unroll
                for (int n = 0; n < 8; n++) {
                    mma_f16(acc[i][n], ah[i], bh[n]);
                    if (do_lo) mma_f16(acc[i][n], al[i], bh[n]);
                }
        }
        __syncthreads();
    }
    #undef PREFETCH

    int gid = lane >> 2, tig = lane & 3;
    if (mode == 0) {
        __half* Hc = (z == 0) ? H0 : ((z == 1) ? H1 : H2);
        #pragma unroll
        for (int i = 0; i < 2; i++) {
            int r = m0 + wm * 32 + i * 16 + gid;
            #pragma unroll
            for (int n = 0; n < 8; n++) {
                int col = n0 + wn * 64 + n * 8 + tig * 2;
                float a0 = acc[i][n][0], a1 = acc[i][n][1];
                float a2 = acc[i][n][2], a3 = acc[i][n][3];
                uint32_t h01 = pack_f16(a0, a1);
                uint32_t h23 = pack_f16(a2, a3);
                *(uint32_t*)(Hc + (size_t)r * DD + col) = h01;
                *(uint32_t*)(Hc + (size_t)(r + 8) * DD + col) = h23;
                if (z == 0) {
                    __half2 hh;
                    *(uint32_t*)&hh = h01;
                    uint32_t l01 = pack_f16(a0 - __half2float(hh.x), a1 - __half2float(hh.y));
                    *(uint32_t*)&hh = h23;
                    uint32_t l23 = pack_f16(a2 - __half2float(hh.x), a3 - __half2float(hh.y));
                    *(uint32_t*)(L0 + (size_t)r * DD + col) = l01;
                    *(uint32_t*)(L0 + (size_t)(r + 8) * DD + col) = l23;
                }
            }
        }
    } else {
        float sc = *scale_ptr;
        #pragma unroll
        for (int i = 0; i < 2; i++) {
            int r = m0 + wm * 32 + i * 16 + gid;
            #pragma unroll
            for (int n = 0; n < 8; n++) {
                int col = n0 + wn * 64 + n * 8 + tig * 2;
                float2 v0; v0.x = acc[i][n][0] * sc; v0.y = acc[i][n][1] * sc;
                float2 v1; v1.x = acc[i][n][2] * sc; v1.y = acc[i][n][3] * sc;
                *(float2*)(Cf + (size_t)r * DD + col) = v0;
                *(float2*)(Cf + (size_t)(r + 8) * DD + col) = v1;
            }
        }
    }
}

// ------------------------- MMA windowed decayed attention (fp16 2-pass) ------
#define NCH 5
#define SPITCH 688
#define SHI_OFF 0
#define SLO_OFF 44032
#define PIPE_OFF 88064
#define APITCH 144
#define AOP    9216
#define ASTG   (3*AOP)              // qh, ql, kh = 27648
#define VPITCH 272
#define VSTG   17408                // vh only
#define ATT_SMEM (PIPE_OFF + 3*ASTG)   // 171008

__global__ __launch_bounds__(256, 1) void attn_mma(const float* __restrict__ decay_logit_p)
{
    extern __shared__ char smc[];
    uint32_t sb = smem_to_u32(smc);
    int t = threadIdx.x, lane = t & 31, w = t >> 5;
    int wq = w & 3, wn = w >> 2;
    int b = blockIdx.y, i0 = blockIdx.x * 64;
    int ncv = min(NCH, (TT - i0) / 64);

    float dl = *decay_logit_p;
    float decay = 1.0f / (1.0f + expf(-dl));
    float log2d = log2f(decay);
    const float qk_scale = 0.03125f;

    const __half* qh_g = g_qhi + (size_t)(b * TT + i0) * DD;
    const __half* ql_g = g_qlo + (size_t)(b * TT + i0) * DD;
    const __half* kh_g = g_khi + (size_t)(b * TT) * DD;
    const __half* vh_g = g_vhi + (size_t)(b * TT) * DD;

    int mid = lane >> 3;
    int rl0 = wq * 16 + (lane >> 2);

    // ================= Phase A: scores =================
    int totA = ncv * 16;

    #define PF_A(it) do { \
        int c_ = (it) >> 4, ds_ = (it) & 15; \
        int cs_ = i0 + c_ * 64; \
        uint32_t base_ = sb + PIPE_OFF + ((it) % 3) * ASTG; \
        _Pragma("unroll") \
        for (int i_ = 0; i_ < 2; i_++) { \
            int idx_ = t + 256 * i_; \
            int r_ = idx_ >> 3, g_ = idx_ & 7; \
            uint32_t so_ = (uint32_t)(r_ * APITCH + g_ * 16); \
            size_t qo_ = (size_t)r_ * DD + ds_ * 64 + g_ * 8; \
            size_t ko_ = (size_t)(cs_ + r_) * DD + ds_ * 64 + g_ * 8; \
            cp_async16(base_ + 0 * AOP + so_, qh_g + qo_); \
            cp_async16(base_ + 1 * AOP + so_, ql_g + qo_); \
            cp_async16(base_ + 2 * AOP + so_, kh_g + ko_); \
        } \
    } while (0)

    {
        float acc[4][4];
        #pragma unroll
        for (int n = 0; n < 4; n++)
            #pragma unroll
            for (int j = 0; j < 4; j++) acc[n][j] = 0.f;

        PF_A(0); CP_COMMIT();
        PF_A(1); CP_COMMIT();

        for (int it = 0; it < totA; it++) {
            if (it + 2 < totA)      { PF_A(it + 2); CP_COMMIT(); CP_WAIT2(); }
            else if (it + 1 < totA) { CP_WAIT1(); }
            else                    { CP_WAIT0(); }
            __syncthreads();

            uint32_t base = sb + PIPE_OFF + (it % 3) * ASTG;
            #pragma unroll
            for (int kk = 0; kk < 4; kk++) {
                uint32_t qh[4], ql[4];
                uint32_t roA = (uint32_t)((wq * 16 + (lane & 15)) * APITCH
                                          + kk * 32 + (lane >> 4) * 16);
                ldsm_x4(qh, base + 0 * AOP + roA);
                ldsm_x4(ql, base + 1 * AOP + roA);
                uint32_t kh[4][2];
                #pragma unroll
                for (int p = 0; p < 2; p++) {
                    int nr = wn * 32 + p * 16 + ((mid & 2) << 2) + (lane & 7);
                    uint32_t roB = (uint32_t)(nr * APITCH + kk * 32 + (mid & 1) * 16);
                    uint32_t r4[4];
                    ldsm_x4(r4, base + 2 * AOP + roB);
                    kh[2*p][0] = r4[0]; kh[2*p][1] = r4[1];
                    kh[2*p+1][0] = r4[2]; kh[2*p+1][1] = r4[3];
                }
                #pragma unroll
                for (int n = 0; n < 4; n++) {
                    mma_f16(acc[n], qh, kh[n]);
                    mma_f16(acc[n], ql, kh[n]);
                }
            }
            __syncthreads();

            if ((it & 15) == 15) {
                int c = it >> 4;
                #pragma unroll
                for (int n = 0; n < 4; n++) {
                    int jl0 = wn * 32 + n * 8 + (lane & 3) * 2;
                    float s[4];
                    #pragma unroll
                    for (int rr = 0; rr < 2; rr++) {
                        int rl = rl0 + rr * 8;
                        #pragma unroll
                        for (int jj = 0; jj < 2; jj++) {
                            int diff = c * 64 + jl0 + jj - rl;
                            float wt = 0.f;
                            if (diff > 0) wt = qk_scale * exp2f((float)(diff - 1) * log2d);
                            s[rr * 2 + jj] = acc[n][rr * 2 + jj] * wt;
                        }
                    }
                    uint32_t jbyte = (uint32_t)((c * 64 + jl0) * 2);
                    #pragma unroll
                    for (int rr = 0; rr < 2; rr++) {
                        int rl = rl0 + rr * 8;
                        uint32_t h = pack_f16(s[rr*2], s[rr*2+1]);
                        __half2 hh; *(uint32_t*)&hh = h;
                        uint32_t l = pack_f16(s[rr*2] - __half2float(hh.x),
                                              s[rr*2+1] - __half2float(hh.y));
                        uint32_t ad = (uint32_t)(rl * SPITCH) + jbyte;
                        *(uint32_t*)(smc + SHI_OFF + ad) = h;
                        *(uint32_t*)(smc + SLO_OFF + ad) = l;
                    }
                    #pragma unroll
                    for (int j = 0; j < 4; j++) acc[n][j] = 0.f;
                }
            }
        }
    }
    #undef PF_A
    __syncthreads();

    // ================= Phase B: O = S V =================
    int totB = 8 * ncv;

    #define PF_V(it) do { \
        int db_ = (it) / ncv, c_ = (it) % ncv; \
        int cs_ = i0 + c_ * 64; \
        uint32_t base_ = sb + PIPE_OFF + ((it) % 3) * VSTG; \
        _Pragma("unroll") \
        for (int i_ = 0; i_ < 4; i_++) { \
            int idx_ = t + 256 * i_; \
            int r_ = idx_ >> 4, g_ = idx_ & 15; \
            uint32_t so_ = (uint32_t)(r_ * VPITCH + g_ * 16); \
            size_t go_ = (size_t)(cs_ + r_) * DD + db_ * 128 + g_ * 8; \
            cp_async16(base_ + so_, vh_g + go_); \
        } \
    } while (0)

    PF_V(0); CP_COMMIT();
    PF_V(1); CP_COMMIT();

    for (int db = 0; db < 8; db++) {
        float oacc[8][4];
        #pragma unroll
        for (int n = 0; n < 8; n++)
            #pragma unroll
            for (int j = 0; j < 4; j++) oacc[n][j] = 0.f;

        for (int c = 0; c < ncv; c++) {
            int it = db * ncv + c;
            if (it + 2 < totB)      { PF_V(it + 2); CP_COMMIT(); CP_WAIT2(); }
            else if (it + 1 < totB) { CP_WAIT1(); }
            else                    { CP_WAIT0(); }
            __syncthreads();

            uint32_t vb = sb + PIPE_OFF + (it % 3) * VSTG;
            #pragma unroll
            for (int ks = 0; ks < 4; ks++) {
                int kof = c * 64 + ks * 16;
                uint32_t sh4[4], sl4[4];
                uint32_t roA = (uint32_t)((wq * 16 + (lane & 15)) * SPITCH
                                          + (kof + (lane >> 4) * 8) * 2);
                ldsm_x4(sh4, sb + SHI_OFF + roA);
                ldsm_x4(sl4, sb + SLO_OFF + roA);
                uint32_t vh[8][2];
                #pragma unroll
                for (int p = 0; p < 4; p++) {
                    int dloc = wn * 64 + p * 16;
                    uint32_t roB = (uint32_t)((ks * 16 + (lane & 15)) * VPITCH
                                              + (dloc + (lane >> 4) * 8) * 2);
                    uint32_t r4[4];
                    ldsm_x4_t(r4, vb + roB);
                    vh[2*p][0] = r4[0]; vh[2*p][1] = r4[1];
                    vh[2*p+1][0] = r4[2]; vh[2*p+1][1] = r4[3];
                }
                #pragma unroll
                for (int n = 0; n < 8; n++) {
                    mma_f16(oacc[n], sh4, vh[n]);
                    mma_f16(oacc[n], sl4, vh[n]);
                }
            }
            __syncthreads();
        }

        #pragma unroll
        for (int n = 0; n < 8; n++) {
            int d = db * 128 + wn * 64 + n * 8 + (lane & 3) * 2;
            #pragma unroll
            for (int rr = 0; rr < 2; rr++) {
                int row = i0 + rl0 + rr * 8;
                uint32_t h = pack_f16(oacc[n][rr*2], oacc[n][rr*2+1]);
                size_t ad = (size_t)(b * TT + row) * DD + d;
                *(uint32_t*)(g_rhi + ad) = h;
            }
        }
    }
    #undef PF_V
}

// ---------------------------------------------------------------------------
extern "C" void kernel_launch(void* const* d_in, const int* in_sizes, int n_in,
                              void* d_out, int out_size)
{
    const float* x  = (const float*)d_in[0];
    const float* Wq = (const float*)d_in[1];
    const float* Wk = (const float*)d_in[2];
    const float* Wv = (const float*)d_in[3];
    const float* Wo = (const float*)d_in[4];
    const float* decay_logit = (const float*)d_in[5];
    const float* out_scale   = (const float*)d_in[6];
    float* out = (float*)d_out;

    __half *xhi, *xlo, *whi;
    __half *qhi, *qlo, *khi, *vhi, *rhi;
    cudaGetSymbolAddress((void**)&xhi, g_xhi);
    cudaGetSymbolAddress((void**)&xlo, g_xlo);
    cudaGetSymbolAddress((void**)&whi, g_whi);
    cudaGetSymbolAddress((void**)&qhi, g_qhi);
    cudaGetSymbolAddress((void**)&qlo, g_qlo);
    cudaGetSymbolAddress((void**)&khi, g_khi);
    cudaGetSymbolAddress((void**)&vhi, g_vhi);
    cudaGetSymbolAddress((void**)&rhi, g_rhi);

    int nx4 = M_TOTAL * DD / 4;
    int nw4 = DD * DD / 4;
    split_x<<<(nx4 + 255) / 256, 256>>>(x, xhi, xlo, nx4);
    conv_w4<<<dim3((nw4 + 255) / 256, 4), 256>>>(Wq, Wk, Wv, Wo, whi, nw4);

    cudaFuncSetAttribute(mma_gemm, cudaFuncAttributeMaxDynamicSharedMemorySize, GSMEM);
    cudaFuncSetAttribute(attn_mma, cudaFuncAttributeMaxDynamicSharedMemorySize, ATT_SMEM);

    // QKV projections -> q (hi+lo, 2-pass), k (hi, 1-pass), v (hi, 1-pass)
    mma_gemm<<<dim3(M_TOTAL / 128, DD / 128, 3), 256, GSMEM>>>(
        xhi, xlo, whi, qhi, qlo, khi, vhi, nullptr, nullptr, 0);

    // windowed decayed attention on tensor cores
    attn_mma<<<dim3(TT / 64, BB), 256, ATT_SMEM>>>(decay_logit);

    // output projection (1-pass, fp32 out, scaled)
    mma_gemm<<<dim3(M_TOTAL / 128, DD / 128, 1), 256, GSMEM>>>(
        rhi, rhi, whi + 3 * (size_t)DD * DD, nullptr, nullptr, nullptr, nullptr,
        out, out_scale, 1);
}

// round 11
// speedup vs baseline: 11.3459x; 1.4722x over previous
#include <cuda_runtime.h>
#include <cuda_fp16.h>
#include <math.h>
#include <stdint.h>

#define BB 4
#define TT 4096
#define DD 1024
#define M_TOTAL (BB*TT)

// ------------------------- scratch (device globals) -------------------------
__device__ __half g_xhi[M_TOTAL*DD];
__device__ __half g_whi[4*DD*DD];
__device__ __half g_qhi[M_TOTAL*DD];
__device__ __half g_khi[M_TOTAL*DD];
__device__ __half g_vhi[M_TOTAL*DD];
__device__ __half g_rhi[M_TOTAL*DD];

// ------------------------- helpers ------------------------------------------
__device__ __forceinline__ uint32_t smem_to_u32(const void* p) {
    uint32_t a;
    asm("{ .reg .u64 t; cvta.to.shared.u64 t, %1; cvt.u32.u64 %0, t; }" : "=r"(a) : "l"(p));
    return a;
}
__device__ __forceinline__ void cp_async16(uint32_t saddr, const void* g) {
    asm volatile("cp.async.cg.shared.global [%0], [%1], 16;" :: "r"(saddr), "l"(g));
}
#define CP_COMMIT() asm volatile("cp.async.commit_group;" ::: "memory")
#define CP_WAIT2()  asm volatile("cp.async.wait_group 2;" ::: "memory")
#define CP_WAIT1()  asm volatile("cp.async.wait_group 1;" ::: "memory")
#define CP_WAIT0()  asm volatile("cp.async.wait_group 0;" ::: "memory")

__device__ __forceinline__ void ldsm_x4(uint32_t* r, uint32_t addr) {
    asm volatile("ldmatrix.sync.aligned.m8n8.x4.shared.b16 {%0,%1,%2,%3}, [%4];"
        : "=r"(r[0]), "=r"(r[1]), "=r"(r[2]), "=r"(r[3]) : "r"(addr));
}
__device__ __forceinline__ void ldsm_x4_t(uint32_t* r, uint32_t addr) {
    asm volatile("ldmatrix.sync.aligned.m8n8.x4.trans.shared.b16 {%0,%1,%2,%3}, [%4];"
        : "=r"(r[0]), "=r"(r[1]), "=r"(r[2]), "=r"(r[3]) : "r"(addr));
}
__device__ __forceinline__ void mma_f16(float* d, const uint32_t* a, const uint32_t* b) {
    asm volatile("mma.sync.aligned.m16n8k16.row.col.f32.f16.f16.f32 "
        "{%0,%1,%2,%3}, {%4,%5,%6,%7}, {%8,%9}, {%0,%1,%2,%3};"
        : "+f"(d[0]), "+f"(d[1]), "+f"(d[2]), "+f"(d[3])
        : "r"(a[0]), "r"(a[1]), "r"(a[2]), "r"(a[3]), "r"(b[0]), "r"(b[1]));
}
__device__ __forceinline__ uint32_t pack_f16(float a, float b) {
    __half2 h = __floats2half2_rn(a, b);
    return *(uint32_t*)&h;
}

// ------------------------- conversion kernels --------------------------------
__global__ __launch_bounds__(256) void conv_x(
    const float* __restrict__ src, __half* __restrict__ hi, int n4)
{
    int i = blockIdx.x * 256 + threadIdx.x;
    if (i >= n4) return;
    float4 v = ((const float4*)src)[i];
    __half2 H0; H0.x = __float2half_rn(v.x); H0.y = __float2half_rn(v.y);
    __half2 H1; H1.x = __float2half_rn(v.z); H1.y = __float2half_rn(v.w);
    ((__half2*)hi)[2*i]   = H0;
    ((__half2*)hi)[2*i+1] = H1;
}

__global__ __launch_bounds__(256) void conv_w4(
    const float* __restrict__ s0, const float* __restrict__ s1,
    const float* __restrict__ s2, const float* __restrict__ s3,
    __half* __restrict__ hi, int n4)
{
    int i = blockIdx.x * 256 + threadIdx.x;
    if (i >= n4) return;
    int z = blockIdx.y;
    const float* src = (z == 0) ? s0 : ((z == 1) ? s1 : ((z == 2) ? s2 : s3));
    __half* dst = hi + (size_t)z * DD * DD;
    float4 v = ((const float4*)src)[i];
    __half2 H0; H0.x = __float2half_rn(v.x); H0.y = __float2half_rn(v.y);
    __half2 H1; H1.x = __float2half_rn(v.z); H1.y = __float2half_rn(v.w);
    ((__half2*)dst)[2*i]   = H0;
    ((__half2*)dst)[2*i+1] = H1;
}

// ------------------------- HMMA GEMM (128x128, 256 thr, 1-pass) --------------
#define AHI_O 0
#define BHI_O 10240
#define STAGEB 20480
#define GSMEM  (3*STAGEB)          // 61440; x2 CTAs = 122880

__global__ __launch_bounds__(256, 2) void mma_gemm(
    const __half* __restrict__ Ahi, const __half* __restrict__ Whi,
    __half* __restrict__ H0, __half* __restrict__ H1, __half* __restrict__ H2,
    float* __restrict__ Cf, const float* __restrict__ scale_ptr, int mode)
{
    extern __shared__ char smc[];
    uint32_t sb = smem_to_u32(smc);
    int t = threadIdx.x, lane = t & 31, w = t >> 5;
    int wm = w & 3, wn = w >> 2;
    int m0 = blockIdx.x * 128, n0 = blockIdx.y * 128, z = blockIdx.z;

    const __half* Wh = Whi + (size_t)z * DD * DD;
    const __half* aH = Ahi + (size_t)m0 * DD;
    const __half* bH = Wh + (size_t)n0 * DD;

    float acc[2][8][4];
    #pragma unroll
    for (int i = 0; i < 2; i++)
        #pragma unroll
        for (int n = 0; n < 8; n++)
            #pragma unroll
            for (int j = 0; j < 4; j++) acc[i][n][j] = 0.f;

    int lrA = t >> 1, lsA = t & 1;
    uint32_t soA = (uint32_t)(lrA * 80 + lsA * 32);
    size_t goA = (size_t)lrA * DD + lsA * 16;

    #define PREFETCH(c) do { \
        uint32_t base_ = sb + ((c) % 3) * STAGEB; \
        int k0_ = (c) * 32; \
        cp_async16(base_ + AHI_O + soA,      aH + goA + k0_); \
        cp_async16(base_ + AHI_O + soA + 16, aH + goA + k0_ + 8); \
        cp_async16(base_ + BHI_O + soA,      bH + goA + k0_); \
        cp_async16(base_ + BHI_O + soA + 16, bH + goA + k0_ + 8); \
    } while (0)

    PREFETCH(0); CP_COMMIT();
    PREFETCH(1); CP_COMMIT();

    for (int c = 0; c < 32; c++) {
        if (c + 2 < 32)      { PREFETCH(c + 2); CP_COMMIT(); CP_WAIT2(); }
        else if (c + 1 < 32) { CP_WAIT1(); }
        else                 { CP_WAIT0(); }
        __syncthreads();

        uint32_t base = sb + (c % 3) * STAGEB;
        #pragma unroll
        for (int kk = 0; kk < 2; kk++) {
            uint32_t ah[2][4];
            #pragma unroll
            for (int i = 0; i < 2; i++) {
                uint32_t ro = (uint32_t)((wm * 32 + i * 16 + (lane & 15)) * 80
                                         + kk * 32 + (lane >> 4) * 16);
                ldsm_x4(ah[i], base + AHI_O + ro);
            }
            uint32_t bh[8][2];
            #pragma unroll
            for (int p = 0; p < 4; p++) {
                int mid = lane >> 3;
                int nr = wn * 64 + p * 16 + ((mid & 2) << 2) + (lane & 7);
                uint32_t ro = (uint32_t)(nr * 80 + kk * 32 + (mid & 1) * 16);
                uint32_t r4[4];
                ldsm_x4(r4, base + BHI_O + ro);
                bh[2*p][0] = r4[0]; bh[2*p][1] = r4[1];
                bh[2*p+1][0] = r4[2]; bh[2*p+1][1] = r4[3];
            }
            #pragma unroll
            for (int i = 0; i < 2; i++)
                #pragma unroll
                for (int n = 0; n < 8; n++)
                    mma_f16(acc[i][n], ah[i], bh[n]);
        }
        __syncthreads();
    }
    #undef PREFETCH

    int gid = lane >> 2, tig = lane & 3;
    if (mode == 0) {
        __half* Hc = (z == 0) ? H0 : ((z == 1) ? H1 : H2);
        #pragma unroll
        for (int i = 0; i < 2; i++) {
            int r = m0 + wm * 32 + i * 16 + gid;
            #pragma unroll
            for (int n = 0; n < 8; n++) {
                int col = n0 + wn * 64 + n * 8 + tig * 2;
                *(uint32_t*)(Hc + (size_t)r * DD + col) = pack_f16(acc[i][n][0], acc[i][n][1]);
                *(uint32_t*)(Hc + (size_t)(r + 8) * DD + col) = pack_f16(acc[i][n][2], acc[i][n][3]);
            }
        }
    } else {
        float sc = *scale_ptr;
        #pragma unroll
        for (int i = 0; i < 2; i++) {
            int r = m0 + wm * 32 + i * 16 + gid;
            #pragma unroll
            for (int n = 0; n < 8; n++) {
                int col = n0 + wn * 64 + n * 8 + tig * 2;
                float2 v0; v0.x = acc[i][n][0] * sc; v0.y = acc[i][n][1] * sc;
                float2 v1; v1.x = acc[i][n][2] * sc; v1.y = acc[i][n][3] * sc;
                *(float2*)(Cf + (size_t)r * DD + col) = v0;
                *(float2*)(Cf + (size_t)(r + 8) * DD + col) = v1;
            }
        }
    }
}

// ------------------------- MMA windowed decayed attention (1-pass) -----------
// 64 q/CTA, NCH=5 chunks of 64 keys. All operands fp16 hi-only. 2 CTAs/SM.
#define NCH 5
#define SPITCH 688                  // 344 cols
#define SHI_OFF 0
#define PIPE_OFF 44032
#define APITCH 144
#define AOP    9216
#define ASTG   (2*AOP)              // qh, kh = 18432
#define VPITCH 272
#define VSTG   17408
#define ATT_SMEM (PIPE_OFF + 3*ASTG)   // 99328; x2 CTAs = 198656

__global__ __launch_bounds__(256, 2) void attn_mma(const float* __restrict__ decay_logit_p)
{
    extern __shared__ char smc[];
    uint32_t sb = smem_to_u32(smc);
    int t = threadIdx.x, lane = t & 31, w = t >> 5;
    int wq = w & 3, wn = w >> 2;
    int b = blockIdx.y, i0 = blockIdx.x * 64;
    int ncv = min(NCH, (TT - i0) / 64);

    float dl = *decay_logit_p;
    float decay = 1.0f / (1.0f + expf(-dl));
    float log2d = log2f(decay);
    const float qk_scale = 0.03125f;

    const __half* qh_g = g_qhi + (size_t)(b * TT + i0) * DD;
    const __half* kh_g = g_khi + (size_t)(b * TT) * DD;
    const __half* vh_g = g_vhi + (size_t)(b * TT) * DD;

    int mid = lane >> 3;
    int rl0 = wq * 16 + (lane >> 2);

    // ================= Phase A: scores =================
    int totA = ncv * 16;

    #define PF_A(it) do { \
        int c_ = (it) >> 4, ds_ = (it) & 15; \
        int cs_ = i0 + c_ * 64; \
        uint32_t base_ = sb + PIPE_OFF + ((it) % 3) * ASTG; \
        _Pragma("unroll") \
        for (int i_ = 0; i_ < 2; i_++) { \
            int idx_ = t + 256 * i_; \
            int r_ = idx_ >> 3, g_ = idx_ & 7; \
            uint32_t so_ = (uint32_t)(r_ * APITCH + g_ * 16); \
            size_t qo_ = (size_t)r_ * DD + ds_ * 64 + g_ * 8; \
            size_t ko_ = (size_t)(cs_ + r_) * DD + ds_ * 64 + g_ * 8; \
            cp_async16(base_ + 0 * AOP + so_, qh_g + qo_); \
            cp_async16(base_ + 1 * AOP + so_, kh_g + ko_); \
        } \
    } while (0)

    {
        float acc[4][4];
        #pragma unroll
        for (int n = 0; n < 4; n++)
            #pragma unroll
            for (int j = 0; j < 4; j++) acc[n][j] = 0.f;

        PF_A(0); CP_COMMIT();
        PF_A(1); CP_COMMIT();

        for (int it = 0; it < totA; it++) {
            if (it + 2 < totA)      { PF_A(it + 2); CP_COMMIT(); CP_WAIT2(); }
            else if (it + 1 < totA) { CP_WAIT1(); }
            else                    { CP_WAIT0(); }
            __syncthreads();

            uint32_t base = sb + PIPE_OFF + (it % 3) * ASTG;
            #pragma unroll
            for (int kk = 0; kk < 4; kk++) {
                uint32_t qh[4];
                uint32_t roA = (uint32_t)((wq * 16 + (lane & 15)) * APITCH
                                          + kk * 32 + (lane >> 4) * 16);
                ldsm_x4(qh, base + 0 * AOP + roA);
                uint32_t kh[4][2];
                #pragma unroll
                for (int p = 0; p < 2; p++) {
                    int nr = wn * 32 + p * 16 + ((mid & 2) << 2) + (lane & 7);
                    uint32_t roB = (uint32_t)(nr * APITCH + kk * 32 + (mid & 1) * 16);
                    uint32_t r4[4];
                    ldsm_x4(r4, base + 1 * AOP + roB);
                    kh[2*p][0] = r4[0]; kh[2*p][1] = r4[1];
                    kh[2*p+1][0] = r4[2]; kh[2*p+1][1] = r4[3];
                }
                #pragma unroll
                for (int n = 0; n < 4; n++)
                    mma_f16(acc[n], qh, kh[n]);
            }
            __syncthreads();

            if ((it & 15) == 15) {
                int c = it >> 4;
                #pragma unroll
                for (int n = 0; n < 4; n++) {
                    int jl0 = wn * 32 + n * 8 + (lane & 3) * 2;
                    float s[4];
                    #pragma unroll
                    for (int rr = 0; rr < 2; rr++) {
                        int rl = rl0 + rr * 8;
                        #pragma unroll
                        for (int jj = 0; jj < 2; jj++) {
                            int diff = c * 64 + jl0 + jj - rl;
                            float wt = 0.f;
                            if (diff > 0) wt = qk_scale * exp2f((float)(diff - 1) * log2d);
                            s[rr * 2 + jj] = acc[n][rr * 2 + jj] * wt;
                        }
                    }
                    uint32_t jbyte = (uint32_t)((c * 64 + jl0) * 2);
                    #pragma unroll
                    for (int rr = 0; rr < 2; rr++) {
                        int rl = rl0 + rr * 8;
                        uint32_t ad = (uint32_t)(rl * SPITCH) + jbyte;
                        *(uint32_t*)(smc + SHI_OFF + ad) = pack_f16(s[rr*2], s[rr*2+1]);
                    }
                    #pragma unroll
                    for (int j = 0; j < 4; j++) acc[n][j] = 0.f;
                }
            }
        }
    }
    #undef PF_A
    __syncthreads();

    // ================= Phase B: O = S V =================
    int totB = 8 * ncv;

    #define PF_V(it) do { \
        int db_ = (it) / ncv, c_ = (it) % ncv; \
        int cs_ = i0 + c_ * 64; \
        uint32_t base_ = sb + PIPE_OFF + ((it) % 3) * VSTG; \
        _Pragma("unroll") \
        for (int i_ = 0; i_ < 4; i_++) { \
            int idx_ = t + 256 * i_; \
            int r_ = idx_ >> 4, g_ = idx_ & 15; \
            uint32_t so_ = (uint32_t)(r_ * VPITCH + g_ * 16); \
            size_t go_ = (size_t)(cs_ + r_) * DD + db_ * 128 + g_ * 8; \
            cp_async16(base_ + so_, vh_g + go_); \
        } \
    } while (0)

    PF_V(0); CP_COMMIT();
    PF_V(1); CP_COMMIT();

    for (int db = 0; db < 8; db++) {
        float oacc[8][4];
        #pragma unroll
        for (int n = 0; n < 8; n++)
            #pragma unroll
            for (int j = 0; j < 4; j++) oacc[n][j] = 0.f;

        for (int c = 0; c < ncv; c++) {
            int it = db * ncv + c;
            if (it + 2 < totB)      { PF_V(it + 2); CP_COMMIT(); CP_WAIT2(); }
            else if (it + 1 < totB) { CP_WAIT1(); }
            else                    { CP_WAIT0(); }
            __syncthreads();

            uint32_t vb = sb + PIPE_OFF + (it % 3) * VSTG;
            #pragma unroll
            for (int ks = 0; ks < 4; ks++) {
                int kof = c * 64 + ks * 16;
                uint32_t sh4[4];
                uint32_t roA = (uint32_t)((wq * 16 + (lane & 15)) * SPITCH
                                          + (kof + (lane >> 4) * 8) * 2);
                ldsm_x4(sh4, sb + SHI_OFF + roA);
                uint32_t vh[8][2];
                #pragma unroll
                for (int p = 0; p < 4; p++) {
                    int dloc = wn * 64 + p * 16;
                    uint32_t roB = (uint32_t)((ks * 16 + (lane & 15)) * VPITCH
                                              + (dloc + (lane >> 4) * 8) * 2);
                    uint32_t r4[4];
                    ldsm_x4_t(r4, vb + roB);
                    vh[2*p][0] = r4[0]; vh[2*p][1] = r4[1];
                    vh[2*p+1][0] = r4[2]; vh[2*p+1][1] = r4[3];
                }
                #pragma unroll
                for (int n = 0; n < 8; n++)
                    mma_f16(oacc[n], sh4, vh[n]);
            }
            __syncthreads();
        }

        #pragma unroll
        for (int n = 0; n < 8; n++) {
            int d = db * 128 + wn * 64 + n * 8 + (lane & 3) * 2;
            #pragma unroll
            for (int rr = 0; rr < 2; rr++) {
                int row = i0 + rl0 + rr * 8;
                size_t ad = (size_t)(b * TT + row) * DD + d;
                *(uint32_t*)(g_rhi + ad) = pack_f16(oacc[n][rr*2], oacc[n][rr*2+1]);
            }
        }
    }
    #undef PF_V
}

// ---------------------------------------------------------------------------
extern "C" void kernel_launch(void* const* d_in, const int* in_sizes, int n_in,
                              void* d_out, int out_size)
{
    const float* x  = (const float*)d_in[0];
    const float* Wq = (const float*)d_in[1];
    const float* Wk = (const float*)d_in[2];
    const float* Wv = (const float*)d_in[3];
    const float* Wo = (const float*)d_in[4];
    const float* decay_logit = (const float*)d_in[5];
    const float* out_scale   = (const float*)d_in[6];
    float* out = (float*)d_out;

    __half *xhi, *whi, *qhi, *khi, *vhi, *rhi;
    cudaGetSymbolAddress((void**)&xhi, g_xhi);
    cudaGetSymbolAddress((void**)&whi, g_whi);
    cudaGetSymbolAddress((void**)&qhi, g_qhi);
    cudaGetSymbolAddress((void**)&khi, g_khi);
    cudaGetSymbolAddress((void**)&vhi, g_vhi);
    cudaGetSymbolAddress((void**)&rhi, g_rhi);

    int nx4 = M_TOTAL * DD / 4;
    int nw4 = DD * DD / 4;
    conv_x<<<(nx4 + 255) / 256, 256>>>(x, xhi, nx4);
    conv_w4<<<dim3((nw4 + 255) / 256, 4), 256>>>(Wq, Wk, Wv, Wo, whi, nw4);

    cudaFuncSetAttribute(mma_gemm, cudaFuncAttributeMaxDynamicSharedMemorySize, GSMEM);
    cudaFuncSetAttribute(attn_mma, cudaFuncAttributeMaxDynamicSharedMemorySize, ATT_SMEM);

    // QKV projections (1-pass each)
    mma_gemm<<<dim3(M_TOTAL / 128, DD / 128, 3), 256, GSMEM>>>(
        xhi, whi, qhi, khi, vhi, nullptr, nullptr, 0);

    // windowed decayed attention (1-pass, 2 CTAs/SM)
    attn_mma<<<dim3(TT / 64, BB), 256, ATT_SMEM>>>(decay_logit);

    // output projection (1-pass, fp32 out, scaled)
    mma_gemm<<<dim3(M_TOTAL / 128, DD / 128, 1), 256, GSMEM>>>(
        rhi, whi + 3 * (size_t)DD * DD, nullptr, nullptr, nullptr,
        out, out_scale, 1);
}

// round 13
// speedup vs baseline: 12.1636x; 1.0721x over previous
#include <cuda_runtime.h>
#include <cuda_fp16.h>
#include <math.h>
#include <stdint.h>

#define BB 4
#define TT 4096
#define DD 1024
#define M_TOTAL (BB*TT)

// ------------------------- scratch (device globals) -------------------------
__device__ __half g_xhi[M_TOTAL*DD];
__device__ __half g_whi[4*DD*DD];
__device__ __half g_qhi[M_TOTAL*DD];
__device__ __half g_khi[M_TOTAL*DD];
__device__ __half g_vhi[M_TOTAL*DD];
__device__ __half g_rhi[M_TOTAL*DD];

// ------------------------- helpers ------------------------------------------
__device__ __forceinline__ uint32_t smem_to_u32(const void* p) {
    uint32_t a;
    asm("{ .reg .u64 t; cvta.to.shared.u64 t, %1; cvt.u32.u64 %0, t; }" : "=r"(a) : "l"(p));
    return a;
}
__device__ __forceinline__ void cp_async16(uint32_t saddr, const void* g) {
    asm volatile("cp.async.cg.shared.global [%0], [%1], 16;" :: "r"(saddr), "l"(g));
}
#define CP_COMMIT() asm volatile("cp.async.commit_group;" ::: "memory")
#define CP_WAIT2()  asm volatile("cp.async.wait_group 2;" ::: "memory")
#define CP_WAIT1()  asm volatile("cp.async.wait_group 1;" ::: "memory")
#define CP_WAIT0()  asm volatile("cp.async.wait_group 0;" ::: "memory")

__device__ __forceinline__ void ldsm_x4(uint32_t* r, uint32_t addr) {
    asm volatile("ldmatrix.sync.aligned.m8n8.x4.shared.b16 {%0,%1,%2,%3}, [%4];"
        : "=r"(r[0]), "=r"(r[1]), "=r"(r[2]), "=r"(r[3]) : "r"(addr));
}
__device__ __forceinline__ void ldsm_x4_t(uint32_t* r, uint32_t addr) {
    asm volatile("ldmatrix.sync.aligned.m8n8.x4.trans.shared.b16 {%0,%1,%2,%3}, [%4];"
        : "=r"(r[0]), "=r"(r[1]), "=r"(r[2]), "=r"(r[3]) : "r"(addr));
}
__device__ __forceinline__ void mma_f16(float* d, const uint32_t* a, const uint32_t* b) {
    asm volatile("mma.sync.aligned.m16n8k16.row.col.f32.f16.f16.f32 "
        "{%0,%1,%2,%3}, {%4,%5,%6,%7}, {%8,%9}, {%0,%1,%2,%3};"
        : "+f"(d[0]), "+f"(d[1]), "+f"(d[2]), "+f"(d[3])
        : "r"(a[0]), "r"(a[1]), "r"(a[2]), "r"(a[3]), "r"(b[0]), "r"(b[1]));
}
__device__ __forceinline__ uint32_t pack_f16(float a, float b) {
    __half2 h = __floats2half2_rn(a, b);
    return *(uint32_t*)&h;
}

// ------------------------- conversion kernels --------------------------------
__global__ __launch_bounds__(256) void conv_x(
    const float* __restrict__ src, __half* __restrict__ hi, int n4)
{
    int i = blockIdx.x * 256 + threadIdx.x;
    if (i >= n4) return;
    float4 v = ((const float4*)src)[i];
    __half2 H0; H0.x = __float2half_rn(v.x); H0.y = __float2half_rn(v.y);
    __half2 H1; H1.x = __float2half_rn(v.z); H1.y = __float2half_rn(v.w);
    ((__half2*)hi)[2*i]   = H0;
    ((__half2*)hi)[2*i+1] = H1;
}

__global__ __launch_bounds__(256) void conv_w4(
    const float* __restrict__ s0, const float* __restrict__ s1,
    const float* __restrict__ s2, const float* __restrict__ s3,
    __half* __restrict__ hi, int n4)
{
    int i = blockIdx.x * 256 + threadIdx.x;
    if (i >= n4) return;
    int z = blockIdx.y;
    const float* src = (z == 0) ? s0 : ((z == 1) ? s1 : ((z == 2) ? s2 : s3));
    __half* dst = hi + (size_t)z * DD * DD;
    float4 v = ((const float4*)src)[i];
    __half2 H0; H0.x = __float2half_rn(v.x); H0.y = __float2half_rn(v.y);
    __half2 H1; H1.x = __float2half_rn(v.z); H1.y = __float2half_rn(v.w);
    ((__half2*)dst)[2*i]   = H0;
    ((__half2*)dst)[2*i+1] = H1;
}

// ------------------------- HMMA GEMM (128x128, 4-stage, 1 sync/iter) ---------
// Per-iter order: wait(stage c) -> barrier -> prefetch(c+3) -> compute(c).
// The barrier separates last iteration's reads of slot (c+3)&3 from this
// iteration's cp.async writes to it.
#define AHI_O 0
#define BHI_O 10240
#define STAGEB 20480
#define GSMEM  (4*STAGEB)          // 81920; x2 CTAs = 163840

__global__ __launch_bounds__(256, 2) void mma_gemm(
    const __half* __restrict__ Ahi, const __half* __restrict__ Whi,
    __half* __restrict__ H0, __half* __restrict__ H1, __half* __restrict__ H2,
    float* __restrict__ Cf, const float* __restrict__ scale_ptr, int mode)
{
    extern __shared__ char smc[];
    uint32_t sb = smem_to_u32(smc);
    int t = threadIdx.x, lane = t & 31, w = t >> 5;
    int wm = w & 3, wn = w >> 2;
    int m0 = blockIdx.x * 128, n0 = blockIdx.y * 128, z = blockIdx.z;

    const __half* Wh = Whi + (size_t)z * DD * DD;
    const __half* aH = Ahi + (size_t)m0 * DD;
    const __half* bH = Wh + (size_t)n0 * DD;

    float acc[2][8][4];
    #pragma unroll
    for (int i = 0; i < 2; i++)
        #pragma unroll
        for (int n = 0; n < 8; n++)
            #pragma unroll
            for (int j = 0; j < 4; j++) acc[i][n][j] = 0.f;

    int lrA = t >> 1, lsA = t & 1;
    uint32_t soA = (uint32_t)(lrA * 80 + lsA * 32);
    size_t goA = (size_t)lrA * DD + lsA * 16;

    #define PREFETCH(c) do { \
        uint32_t base_ = sb + ((c) & 3) * STAGEB; \
        int k0_ = (c) * 32; \
        cp_async16(base_ + AHI_O + soA,      aH + goA + k0_); \
        cp_async16(base_ + AHI_O + soA + 16, aH + goA + k0_ + 8); \
        cp_async16(base_ + BHI_O + soA,      bH + goA + k0_); \
        cp_async16(base_ + BHI_O + soA + 16, bH + goA + k0_ + 8); \
    } while (0)

    PREFETCH(0); CP_COMMIT();
    PREFETCH(1); CP_COMMIT();
    PREFETCH(2); CP_COMMIT();

    for (int c = 0; c < 32; c++) {
        // wait for stage c (pending at entry: c, c+1, c+2 when c<=29)
        if (c <= 29)      { CP_WAIT2(); }
        else if (c == 30) { CP_WAIT1(); }
        else              { CP_WAIT0(); }
        __syncthreads();
        if (c + 3 < 32) { PREFETCH(c + 3); CP_COMMIT(); }

        uint32_t base = sb + (c & 3) * STAGEB;
        #pragma unroll
        for (int kk = 0; kk < 2; kk++) {
            uint32_t ah[2][4];
            #pragma unroll
            for (int i = 0; i < 2; i++) {
                uint32_t ro = (uint32_t)((wm * 32 + i * 16 + (lane & 15)) * 80
                                         + kk * 32 + (lane >> 4) * 16);
                ldsm_x4(ah[i], base + AHI_O + ro);
            }
            uint32_t bh[8][2];
            #pragma unroll
            for (int p = 0; p < 4; p++) {
                int mid = lane >> 3;
                int nr = wn * 64 + p * 16 + ((mid & 2) << 2) + (lane & 7);
                uint32_t ro = (uint32_t)(nr * 80 + kk * 32 + (mid & 1) * 16);
                uint32_t r4[4];
                ldsm_x4(r4, base + BHI_O + ro);
                bh[2*p][0] = r4[0]; bh[2*p][1] = r4[1];
                bh[2*p+1][0] = r4[2]; bh[2*p+1][1] = r4[3];
            }
            #pragma unroll
            for (int i = 0; i < 2; i++)
                #pragma unroll
                for (int n = 0; n < 8; n++)
                    mma_f16(acc[i][n], ah[i], bh[n]);
        }
    }
    #undef PREFETCH

    int gid = lane >> 2, tig = lane & 3;
    if (mode == 0) {
        __half* Hc = (z == 0) ? H0 : ((z == 1) ? H1 : H2);
        #pragma unroll
        for (int i = 0; i < 2; i++) {
            int r = m0 + wm * 32 + i * 16 + gid;
            #pragma unroll
            for (int n = 0; n < 8; n++) {
                int col = n0 + wn * 64 + n * 8 + tig * 2;
                *(uint32_t*)(Hc + (size_t)r * DD + col) = pack_f16(acc[i][n][0], acc[i][n][1]);
                *(uint32_t*)(Hc + (size_t)(r + 8) * DD + col) = pack_f16(acc[i][n][2], acc[i][n][3]);
            }
        }
    } else {
        float sc = *scale_ptr;
        #pragma unroll
        for (int i = 0; i < 2; i++) {
            int r = m0 + wm * 32 + i * 16 + gid;
            #pragma unroll
            for (int n = 0; n < 8; n++) {
                int col = n0 + wn * 64 + n * 8 + tig * 2;
                float2 v0; v0.x = acc[i][n][0] * sc; v0.y = acc[i][n][1] * sc;
                float2 v1; v1.x = acc[i][n][2] * sc; v1.y = acc[i][n][3] * sc;
                *(float2*)(Cf + (size_t)r * DD + col) = v0;
                *(float2*)(Cf + (size_t)(r + 8) * DD + col) = v1;
            }
        }
    }
}

// ------------------------- MMA windowed decayed attention --------------------
// 64 q/CTA, NCH=4 chunks of 64 keys (window 256). Clamped rows + weight mask.
// 4-stage, single barrier per iteration (wait -> barrier -> prefetch -> compute).
#define NCH 4
#define SPITCH 528
#define SHI_OFF 0
#define PIPE_OFF 33792              // 64*528
#define APITCH 144
#define AOP    9216
#define ASTG   (2*AOP)              // 18432
#define VPITCH 272
#define VSTG   17408
#define ATT_SMEM (PIPE_OFF + 4*ASTG)   // 107520; x2 CTAs = 215040

__global__ __launch_bounds__(256, 2) void attn_mma(const float* __restrict__ decay_logit_p)
{
    extern __shared__ char smc[];
    uint32_t sb = smem_to_u32(smc);
    int t = threadIdx.x, lane = t & 31, w = t >> 5;
    int wq = w & 3, wn = w >> 2;
    int b = blockIdx.y, i0 = blockIdx.x * 64;

    float dl = *decay_logit_p;
    float decay = 1.0f / (1.0f + expf(-dl));
    float log2d = log2f(decay);
    const float qk_scale = 0.03125f;

    const __half* qh_g = g_qhi + (size_t)(b * TT + i0) * DD;
    const __half* kh_g = g_khi + (size_t)(b * TT) * DD;
    const __half* vh_g = g_vhi + (size_t)(b * TT) * DD;

    int mid = lane >> 3;
    int rl0 = wq * 16 + (lane >> 2);

    // ================= Phase A: scores =================
    const int totA = NCH * 16;

    #define PF_A(it) do { \
        int c_ = (it) >> 4, ds_ = (it) & 15; \
        int cs_ = i0 + c_ * 64; \
        uint32_t base_ = sb + PIPE_OFF + ((it) & 3) * ASTG; \
        _Pragma("unroll") \
        for (int i_ = 0; i_ < 2; i_++) { \
            int idx_ = t + 256 * i_; \
            int r_ = idx_ >> 3, g_ = idx_ & 7; \
            int krow_ = min(cs_ + r_, TT - 1); \
            uint32_t so_ = (uint32_t)(r_ * APITCH + g_ * 16); \
            size_t qo_ = (size_t)r_ * DD + ds_ * 64 + g_ * 8; \
            size_t ko_ = (size_t)krow_ * DD + ds_ * 64 + g_ * 8; \
            cp_async16(base_ + 0 * AOP + so_, qh_g + qo_); \
            cp_async16(base_ + 1 * AOP + so_, kh_g + ko_); \
        } \
    } while (0)

    {
        float acc[4][4];
        #pragma unroll
        for (int n = 0; n < 4; n++)
            #pragma unroll
            for (int j = 0; j < 4; j++) acc[n][j] = 0.f;

        PF_A(0); CP_COMMIT();
        PF_A(1); CP_COMMIT();
        PF_A(2); CP_COMMIT();

        for (int it = 0; it < totA; it++) {
            if (it <= totA - 3)      { CP_WAIT2(); }
            else if (it == totA - 2) { CP_WAIT1(); }
            else                     { CP_WAIT0(); }
            __syncthreads();
            if (it + 3 < totA) { PF_A(it + 3); CP_COMMIT(); }

            uint32_t base = sb + PIPE_OFF + (it & 3) * ASTG;
            #pragma unroll
            for (int kk = 0; kk < 4; kk++) {
                uint32_t qh[4];
                uint32_t roA = (uint32_t)((wq * 16 + (lane & 15)) * APITCH
                                          + kk * 32 + (lane >> 4) * 16);
                ldsm_x4(qh, base + 0 * AOP + roA);
                uint32_t kh[4][2];
                #pragma unroll
                for (int p = 0; p < 2; p++) {
                    int nr = wn * 32 + p * 16 + ((mid & 2) << 2) + (lane & 7);
                    uint32_t roB = (uint32_t)(nr * APITCH + kk * 32 + (mid & 1) * 16);
                    uint32_t r4[4];
                    ldsm_x4(r4, base + 1 * AOP + roB);
                    kh[2*p][0] = r4[0]; kh[2*p][1] = r4[1];
                    kh[2*p+1][0] = r4[2]; kh[2*p+1][1] = r4[3];
                }
                #pragma unroll
                for (int n = 0; n < 4; n++)
                    mma_f16(acc[n], qh, kh[n]);
            }

            if ((it & 15) == 15) {
                int c = it >> 4;
                #pragma unroll
                for (int n = 0; n < 4; n++) {
                    int jl0 = wn * 32 + n * 8 + (lane & 3) * 2;
                    float s[4];
                    #pragma unroll
                    for (int rr = 0; rr < 2; rr++) {
                        int rl = rl0 + rr * 8;
                        #pragma unroll
                        for (int jj = 0; jj < 2; jj++) {
                            int jg = i0 + c * 64 + jl0 + jj;
                            int iq = i0 + rl;
                            float wt = 0.f;
                            if (jg > iq && jg < TT)
                                wt = qk_scale * exp2f((float)(jg - iq - 1) * log2d);
                            s[rr * 2 + jj] = acc[n][rr * 2 + jj] * wt;
                        }
                    }
                    uint32_t jbyte = (uint32_t)((c * 64 + jl0) * 2);
                    #pragma unroll
                    for (int rr = 0; rr < 2; rr++) {
                        int rl = rl0 + rr * 8;
                        uint32_t ad = (uint32_t)(rl * SPITCH) + jbyte;
                        *(uint32_t*)(smc + SHI_OFF + ad) = pack_f16(s[rr*2], s[rr*2+1]);
                    }
                    #pragma unroll
                    for (int j = 0; j < 4; j++) acc[n][j] = 0.f;
                }
            }
        }
    }
    #undef PF_A
    __syncthreads();

    // ================= Phase B: O = S V =================
    const int totB = 8 * NCH;

    #define PF_V(it) do { \
        int db_ = (it) >> 2, c_ = (it) & 3; \
        int cs_ = i0 + c_ * 64; \
        uint32_t base_ = sb + PIPE_OFF + ((it) & 3) * VSTG; \
        _Pragma("unroll") \
        for (int i_ = 0; i_ < 4; i_++) { \
            int idx_ = t + 256 * i_; \
            int r_ = idx_ >> 4, g_ = idx_ & 15; \
            int vrow_ = min(cs_ + r_, TT - 1); \
            uint32_t so_ = (uint32_t)(r_ * VPITCH + g_ * 16); \
            size_t go_ = (size_t)vrow_ * DD + db_ * 128 + g_ * 8; \
            cp_async16(base_ + so_, vh_g + go_); \
        } \
    } while (0)

    PF_V(0); CP_COMMIT();
    PF_V(1); CP_COMMIT();
    PF_V(2); CP_COMMIT();

    for (int db = 0; db < 8; db++) {
        float oacc[8][4];
        #pragma unroll
        for (int n = 0; n < 8; n++)
            #pragma unroll
            for (int j = 0; j < 4; j++) oacc[n][j] = 0.f;

        for (int c = 0; c < NCH; c++) {
            int it = db * NCH + c;
            if (it <= totB - 3)      { CP_WAIT2(); }
            else if (it == totB - 2) { CP_WAIT1(); }
            else                     { CP_WAIT0(); }
            __syncthreads();
            if (it + 3 < totB) { PF_V(it + 3); CP_COMMIT(); }

            uint32_t vb = sb + PIPE_OFF + (it & 3) * VSTG;
            #pragma unroll
            for (int ks = 0; ks < 4; ks++) {
                int kof = c * 64 + ks * 16;
                uint32_t sh4[4];
                uint32_t roA = (uint32_t)((wq * 16 + (lane & 15)) * SPITCH
                                          + (kof + (lane >> 4) * 8) * 2);
                ldsm_x4(sh4, sb + SHI_OFF + roA);
                uint32_t vh[8][2];
                #pragma unroll
                for (int p = 0; p < 4; p++) {
                    int dloc = wn * 64 + p * 16;
                    uint32_t roB = (uint32_t)((ks * 16 + (lane & 15)) * VPITCH
                                              + (dloc + (lane >> 4) * 8) * 2);
                    uint32_t r4[4];
                    ldsm_x4_t(r4, vb + roB);
                    vh[2*p][0] = r4[0]; vh[2*p][1] = r4[1];
                    vh[2*p+1][0] = r4[2]; vh[2*p+1][1] = r4[3];
                }
                #pragma unroll
                for (int n = 0; n < 8; n++)
                    mma_f16(oacc[n], sh4, vh[n]);
            }
        }

        #pragma unroll
        for (int n = 0; n < 8; n++) {
            int d = db * 128 + wn * 64 + n * 8 + (lane & 3) * 2;
            #pragma unroll
            for (int rr = 0; rr < 2; rr++) {
                int row = i0 + rl0 + rr * 8;
                size_t ad = (size_t)(b * TT + row) * DD + d;
                *(uint32_t*)(g_rhi + ad) = pack_f16(oacc[n][rr*2], oacc[n][rr*2+1]);
            }
        }
    }
    #undef PF_V
}

// ---------------------------------------------------------------------------
extern "C" void kernel_launch(void* const* d_in, const int* in_sizes, int n_in,
                              void* d_out, int out_size)
{
    const float* x  = (const float*)d_in[0];
    const float* Wq = (const float*)d_in[1];
    const float* Wk = (const float*)d_in[2];
    const float* Wv = (const float*)d_in[3];
    const float* Wo = (const float*)d_in[4];
    const float* decay_logit = (const float*)d_in[5];
    const float* out_scale   = (const float*)d_in[6];
    float* out = (float*)d_out;

    __half *xhi, *whi, *qhi, *khi, *vhi, *rhi;
    cudaGetSymbolAddress((void**)&xhi, g_xhi);
    cudaGetSymbolAddress((void**)&whi, g_whi);
    cudaGetSymbolAddress((void**)&qhi, g_qhi);
    cudaGetSymbolAddress((void**)&khi, g_khi);
    cudaGetSymbolAddress((void**)&vhi, g_vhi);
    cudaGetSymbolAddress((void**)&rhi, g_rhi);

    int nx4 = M_TOTAL * DD / 4;
    int nw4 = DD * DD / 4;
    conv_x<<<(nx4 + 255) / 256, 256>>>(x, xhi, nx4);
    conv_w4<<<dim3((nw4 + 255) / 256, 4), 256>>>(Wq, Wk, Wv, Wo, whi, nw4);

    cudaFuncSetAttribute(mma_gemm, cudaFuncAttributeMaxDynamicSharedMemorySize, GSMEM);
    cudaFuncSetAttribute(attn_mma, cudaFuncAttributeMaxDynamicSharedMemorySize, ATT_SMEM);

    // QKV projections (1-pass each)
    mma_gemm<<<dim3(M_TOTAL / 128, DD / 128, 3), 256, GSMEM>>>(
        xhi, whi, qhi, khi, vhi, nullptr, nullptr, 0);

    // windowed decayed attention
    attn_mma<<<dim3(TT / 64, BB), 256, ATT_SMEM>>>(decay_logit);

    // output projection (fp32 out, scaled)
    mma_gemm<<<dim3(M_TOTAL / 128, DD / 128, 1), 256, GSMEM>>>(
        rhi, whi + 3 * (size_t)DD * DD, nullptr, nullptr, nullptr,
        out, out_scale, 1);
}